// round 2
// baseline (speedup 1.0000x reference)
#include <cuda_runtime.h>
#include <math.h>

#define T_TOK 2048
#define NL    12
#define DM    768
#define FL    2048

#define BM 128
#define BN 128
#define BK 16

// Fallback scratch if the harness output is x_hat-only (acts must live somewhere).
__device__ float g_acts_scratch[(size_t)T_TOK * NL * FL];

// ---------------------------------------------------------------------------
// Packed f32x2 helpers (Blackwell-only; ptxas never auto-fuses into FFMA2)
// ---------------------------------------------------------------------------
__device__ __forceinline__ unsigned long long bcast2(float a) {
    unsigned long long r;
    asm("mov.b64 %0, {%1,%1};" : "=l"(r) : "f"(a));
    return r;
}
__device__ __forceinline__ void ffma2(unsigned long long& c, unsigned long long a,
                                      unsigned long long b) {
    asm("fma.rn.f32x2 %0, %1, %2, %0;" : "+l"(c) : "l"(a), "l"(b));
}
__device__ __forceinline__ float2 unpack2(unsigned long long v) {
    float2 r;
    asm("mov.b64 {%0,%1}, %2;" : "=f"(r.x), "=f"(r.y) : "l"(v));
    return r;
}

// ---------------------------------------------------------------------------
// Encode: for each layer l, H_l[T,F] = X_l[T,D] @ We_l[D,F]; fp32-exact so the
// JumpReLU threshold decisions match the reference. Writes h and acts.
// ---------------------------------------------------------------------------
__global__ __launch_bounds__(256, 2)
void encode_kernel(const float* __restrict__ X,
                   const float* __restrict__ WE,
                   const float* __restrict__ TH,
                   float* __restrict__ H,          // may be null
                   float* __restrict__ A) {
    const int l  = blockIdx.z;
    const int bm = blockIdx.y * BM;   // token tile
    const int bn = blockIdx.x * BN;   // feature tile

    const float* Ag = X + (size_t)l * DM;             // A[t,d], row stride NL*DM
    const float* Bg = WE + (size_t)l * DM * FL;       // B[d,f], row stride FL

    __shared__ float As[2][BK][BM + 4];
    __shared__ float Bs[2][BK][BN];

    const int tid  = threadIdx.x;
    const int arow = tid >> 2;            // 0..63  (rows arow, arow+64)
    const int akq  = (tid & 3) << 2;      // 0,4,8,12
    const int brow = tid >> 5;            // 0..7   (rows brow, brow+8)
    const int bcol = (tid & 31) << 2;

    const int tm = (tid >> 4) << 3;
    const int tn = (tid & 15) << 3;

    unsigned long long acc[8][4];
#pragma unroll
    for (int i = 0; i < 8; i++)
#pragma unroll
        for (int jj = 0; jj < 4; jj++) acc[i][jj] = 0ULL;

    const int NKT = DM / BK;  // 48

    float4 pa0, pa1, pb0, pb1;
    // preload tile 0
    pa0 = *(const float4*)(Ag + (size_t)(bm + arow)      * (NL * DM) + akq);
    pa1 = *(const float4*)(Ag + (size_t)(bm + arow + 64) * (NL * DM) + akq);
    pb0 = *(const float4*)(Bg + (size_t)(brow)     * FL + bn + bcol);
    pb1 = *(const float4*)(Bg + (size_t)(brow + 8) * FL + bn + bcol);
    As[0][akq + 0][arow] = pa0.x; As[0][akq + 1][arow] = pa0.y;
    As[0][akq + 2][arow] = pa0.z; As[0][akq + 3][arow] = pa0.w;
    As[0][akq + 0][arow + 64] = pa1.x; As[0][akq + 1][arow + 64] = pa1.y;
    As[0][akq + 2][arow + 64] = pa1.z; As[0][akq + 3][arow + 64] = pa1.w;
    *(float4*)&Bs[0][brow][bcol]     = pb0;
    *(float4*)&Bs[0][brow + 8][bcol] = pb1;
    __syncthreads();

    int buf = 0;
    for (int kt = 0; kt < NKT; kt++) {
        if (kt + 1 < NKT) {
            const int k0 = (kt + 1) * BK;
            pa0 = *(const float4*)(Ag + (size_t)(bm + arow)      * (NL * DM) + k0 + akq);
            pa1 = *(const float4*)(Ag + (size_t)(bm + arow + 64) * (NL * DM) + k0 + akq);
            pb0 = *(const float4*)(Bg + (size_t)(k0 + brow)     * FL + bn + bcol);
            pb1 = *(const float4*)(Bg + (size_t)(k0 + brow + 8) * FL + bn + bcol);
        }
#pragma unroll
        for (int k = 0; k < BK; k++) {
            unsigned long long bv[4];
#pragma unroll
            for (int jj = 0; jj < 4; jj++)
                bv[jj] = *(const unsigned long long*)&Bs[buf][k][tn + jj * 2];
#pragma unroll
            for (int i = 0; i < 8; i++) {
                unsigned long long av = bcast2(As[buf][k][tm + i]);
#pragma unroll
                for (int jj = 0; jj < 4; jj++) ffma2(acc[i][jj], av, bv[jj]);
            }
        }
        if (kt + 1 < NKT) {
            const int nb = buf ^ 1;
            As[nb][akq + 0][arow] = pa0.x; As[nb][akq + 1][arow] = pa0.y;
            As[nb][akq + 2][arow] = pa0.z; As[nb][akq + 3][arow] = pa0.w;
            As[nb][akq + 0][arow + 64] = pa1.x; As[nb][akq + 1][arow + 64] = pa1.y;
            As[nb][akq + 2][arow + 64] = pa1.z; As[nb][akq + 3][arow + 64] = pa1.w;
            *(float4*)&Bs[nb][brow][bcol]     = pb0;
            *(float4*)&Bs[nb][brow + 8][bcol] = pb1;
        }
        __syncthreads();
        buf ^= 1;
    }

    // Epilogue: JumpReLU with exact thresholds
    float thr[8];
#pragma unroll
    for (int jj = 0; jj < 8; jj++)
        thr[jj] = expf(TH[l * FL + bn + tn + jj]);

#pragma unroll
    for (int i = 0; i < 8; i++) {
        const int trow = bm + tm + i;
        const size_t base = (size_t)trow * (NL * FL) + (size_t)l * FL + bn + tn;
        float v[8];
#pragma unroll
        for (int jj = 0; jj < 4; jj++) {
            float2 c = unpack2(acc[i][jj]);
            v[jj * 2] = c.x; v[jj * 2 + 1] = c.y;
        }
        if (H) {
            *(float4*)(H + base)     = make_float4(v[0], v[1], v[2], v[3]);
            *(float4*)(H + base + 4) = make_float4(v[4], v[5], v[6], v[7]);
        }
        float a[8];
#pragma unroll
        for (int jj = 0; jj < 8; jj++) a[jj] = (v[jj] > thr[jj]) ? v[jj] : 0.0f;
        *(float4*)(A + base)     = make_float4(a[0], a[1], a[2], a[3]);
        *(float4*)(A + base + 4) = make_float4(a[4], a[5], a[6], a[7]);
    }
}

// ---------------------------------------------------------------------------
// Decode: x_hat[:, j, :] = sum_{i<=j} acts[:, i, :] @ w_d[i, j]
// K flattened over (i, f); acts columns are contiguous in k = i*FL + f.
// j mapped descending over blockIdx.z so the largest K-loops launch first.
// ---------------------------------------------------------------------------
__global__ __launch_bounds__(256, 2)
void decode_kernel(const float* __restrict__ ACT,
                   const float* __restrict__ WD,
                   float* __restrict__ XH) {
    const int j  = (NL - 1) - blockIdx.z;
    const int bm = blockIdx.y * BM;   // token tile
    const int bn = blockIdx.x * BN;   // d tile (6 tiles of 128)

    const size_t bstride_i = (size_t)NL * FL * DM;        // w_d i-stride
    const float* Bg = WD + (size_t)j * FL * DM;           // + i*bstride_i + f*DM

    __shared__ float As[2][BK][BM + 4];
    __shared__ float Bs[2][BK][BN];

    const int tid  = threadIdx.x;
    const int arow = tid >> 2;
    const int akq  = (tid & 3) << 2;
    const int brow = tid >> 5;
    const int bcol = (tid & 31) << 2;

    const int tm = (tid >> 4) << 3;
    const int tn = (tid & 15) << 3;

    unsigned long long acc[8][4];
#pragma unroll
    for (int i = 0; i < 8; i++)
#pragma unroll
        for (int jj = 0; jj < 4; jj++) acc[i][jj] = 0ULL;

    const int NKT = (j + 1) * (FL / BK);   // (j+1)*128 k-tiles

    float4 pa0, pa1, pb0, pb1;
    // preload k-tile 0 (i=0, f0=0)
    pa0 = *(const float4*)(ACT + (size_t)(bm + arow)      * (NL * FL) + akq);
    pa1 = *(const float4*)(ACT + (size_t)(bm + arow + 64) * (NL * FL) + akq);
    pb0 = *(const float4*)(Bg + (size_t)(brow)     * DM + bn + bcol);
    pb1 = *(const float4*)(Bg + (size_t)(brow + 8) * DM + bn + bcol);
    As[0][akq + 0][arow] = pa0.x; As[0][akq + 1][arow] = pa0.y;
    As[0][akq + 2][arow] = pa0.z; As[0][akq + 3][arow] = pa0.w;
    As[0][akq + 0][arow + 64] = pa1.x; As[0][akq + 1][arow + 64] = pa1.y;
    As[0][akq + 2][arow + 64] = pa1.z; As[0][akq + 3][arow + 64] = pa1.w;
    *(float4*)&Bs[0][brow][bcol]     = pb0;
    *(float4*)&Bs[0][brow + 8][bcol] = pb1;
    __syncthreads();

    int buf = 0;
    for (int kt = 0; kt < NKT; kt++) {
        if (kt + 1 < NKT) {
            const int ktn = kt + 1;
            const int k0  = ktn * BK;                 // acts column base
            const int ii  = ktn >> 7;                 // decoder layer i
            const int f0  = (ktn & 127) << 4;         // feature row base
            const float* bb = Bg + (size_t)ii * bstride_i + (size_t)f0 * DM;
            pa0 = *(const float4*)(ACT + (size_t)(bm + arow)      * (NL * FL) + k0 + akq);
            pa1 = *(const float4*)(ACT + (size_t)(bm + arow + 64) * (NL * FL) + k0 + akq);
            pb0 = *(const float4*)(bb + (size_t)(brow)     * DM + bn + bcol);
            pb1 = *(const float4*)(bb + (size_t)(brow + 8) * DM + bn + bcol);
        }
#pragma unroll
        for (int k = 0; k < BK; k++) {
            unsigned long long bv[4];
#pragma unroll
            for (int jj = 0; jj < 4; jj++)
                bv[jj] = *(const unsigned long long*)&Bs[buf][k][tn + jj * 2];
#pragma unroll
            for (int i = 0; i < 8; i++) {
                unsigned long long av = bcast2(As[buf][k][tm + i]);
#pragma unroll
                for (int jj = 0; jj < 4; jj++) ffma2(acc[i][jj], av, bv[jj]);
            }
        }
        if (kt + 1 < NKT) {
            const int nb = buf ^ 1;
            As[nb][akq + 0][arow] = pa0.x; As[nb][akq + 1][arow] = pa0.y;
            As[nb][akq + 2][arow] = pa0.z; As[nb][akq + 3][arow] = pa0.w;
            As[nb][akq + 0][arow + 64] = pa1.x; As[nb][akq + 1][arow + 64] = pa1.y;
            As[nb][akq + 2][arow + 64] = pa1.z; As[nb][akq + 3][arow + 64] = pa1.w;
            *(float4*)&Bs[nb][brow][bcol]     = pb0;
            *(float4*)&Bs[nb][brow + 8][bcol] = pb1;
        }
        __syncthreads();
        buf ^= 1;
    }

#pragma unroll
    for (int i = 0; i < 8; i++) {
        const int trow = bm + tm + i;
        const size_t base = (size_t)trow * (NL * DM) + (size_t)j * DM + bn + tn;
        float v[8];
#pragma unroll
        for (int jj = 0; jj < 4; jj++) {
            float2 c = unpack2(acc[i][jj]);
            v[jj * 2] = c.x; v[jj * 2 + 1] = c.y;
        }
        *(float4*)(XH + base)     = make_float4(v[0], v[1], v[2], v[3]);
        *(float4*)(XH + base + 4) = make_float4(v[4], v[5], v[6], v[7]);
    }
}

// ---------------------------------------------------------------------------
extern "C" void kernel_launch(void* const* d_in, const int* in_sizes, int n_in,
                              void* d_out, int out_size) {
    const float* x  = (const float*)d_in[0];   // [T, L, D]
    const float* we = (const float*)d_in[1];   // [L, D, F]
    const float* wd = (const float*)d_in[2];   // [L, L, F, D]
    const float* th = (const float*)d_in[3];   // [L, F]
    float* out = (float*)d_out;

    const long long HE = (long long)T_TOK * NL * FL;   // 50,331,648
    const long long XE = (long long)T_TOK * NL * DM;   // 18,874,368

    float *hp, *ap, *xp;
    if ((long long)out_size >= 2 * HE + XE) {
        // Standard layout: concat(h, acts, x_hat)
        hp = out;
        ap = out + HE;
        xp = out + 2 * HE;
    } else {
        // Fallback: x_hat only; acts goes to device scratch
        hp = nullptr;
        float* sp = nullptr;
        cudaGetSymbolAddress((void**)&sp, g_acts_scratch);
        ap = sp;
        xp = out;
    }

    dim3 blk(256);
    encode_kernel<<<dim3(FL / BN, T_TOK / BM, NL), blk>>>(x, we, th, hp, ap);
    decode_kernel<<<dim3(DM / BN, T_TOK / BM, NL), blk>>>(ap, wd, xp);
}

// round 4
// speedup vs baseline: 1.9709x; 1.9709x over previous
#include <cuda_runtime.h>
#include <math.h>
#include <stdint.h>

#define T_TOK 2048
#define NL    12
#define DM    768
#define FL    2048

// encode tile
#define BM 128
#define BN 128
#define BK 16

// decode tile
#define DBM 256
#define DBN 128
#define DBK 16

__device__ float g_wd32[(size_t)NL * NL * FL * DM];     // tf32-RN-rounded w_d
__device__ float g_acts32[(size_t)T_TOK * NL * FL];     // tf32-RN-rounded acts
__device__ float g_acts_scratch[(size_t)T_TOK * NL * FL];

// ---------------- helpers ----------------
__device__ __forceinline__ unsigned long long bcast2(float a) {
    unsigned long long r; asm("mov.b64 %0, {%1,%1};" : "=l"(r) : "f"(a)); return r;
}
__device__ __forceinline__ void ffma2(unsigned long long& c, unsigned long long a,
                                      unsigned long long b) {
    asm("fma.rn.f32x2 %0, %1, %2, %0;" : "+l"(c) : "l"(a), "l"(b));
}
__device__ __forceinline__ float2 unpack2(unsigned long long v) {
    float2 r; asm("mov.b64 {%0,%1}, %2;" : "=f"(r.x), "=f"(r.y) : "l"(v)); return r;
}
__device__ __forceinline__ float tf32rn(float v) {
    uint32_t u; asm("cvt.rn.tf32.f32 %0, %1;" : "=r"(u) : "f"(v));
    return __uint_as_float(u);
}
__device__ __forceinline__ uint32_t smem_u32(const void* p) {
    return (uint32_t)__cvta_generic_to_shared(p);
}
__device__ __forceinline__ void cp16(uint32_t d, const void* s) {
    asm volatile("cp.async.cg.shared.global [%0], [%1], 16;" :: "r"(d), "l"(s));
}
__device__ __forceinline__ void cp_commit() {
    asm volatile("cp.async.commit_group;");
}
__device__ __forceinline__ void mma_tf32(float* d, const uint32_t* a, const uint32_t* b) {
    asm volatile(
        "mma.sync.aligned.m16n8k8.row.col.f32.tf32.tf32.f32 "
        "{%0,%1,%2,%3}, {%4,%5,%6,%7}, {%8,%9}, {%0,%1,%2,%3};"
        : "+f"(d[0]), "+f"(d[1]), "+f"(d[2]), "+f"(d[3])
        : "r"(a[0]), "r"(a[1]), "r"(a[2]), "r"(a[3]), "r"(b[0]), "r"(b[1]));
}

// ---------------- encode (fp32 FFMA2, exact JumpReLU) ----------------
__global__ __launch_bounds__(256, 2)
void encode_kernel(const float* __restrict__ X, const float* __restrict__ WE,
                   const float* __restrict__ TH, float* __restrict__ H,
                   float* __restrict__ A, float* __restrict__ A32) {
    const int l = blockIdx.z, bm = blockIdx.y * BM, bn = blockIdx.x * BN;
    const float* Ag = X + (size_t)l * DM;
    const float* Bg = WE + (size_t)l * DM * FL;

    __shared__ float As[2][BK][BM + 4];
    __shared__ float Bs[2][BK][BN];

    const int tid = threadIdx.x;
    const int arow = tid >> 2, akq = (tid & 3) << 2;
    const int brow = tid >> 5, bcol = (tid & 31) << 2;
    const int tm = (tid >> 4) << 3, tn = (tid & 15) << 3;

    unsigned long long acc[8][4];
#pragma unroll
    for (int i = 0; i < 8; i++)
#pragma unroll
        for (int jj = 0; jj < 4; jj++) acc[i][jj] = 0ULL;

    const int NKT = DM / BK;
    float4 pa0, pa1, pb0, pb1;
    pa0 = *(const float4*)(Ag + (size_t)(bm + arow)      * (NL * DM) + akq);
    pa1 = *(const float4*)(Ag + (size_t)(bm + arow + 64) * (NL * DM) + akq);
    pb0 = *(const float4*)(Bg + (size_t)(brow)     * FL + bn + bcol);
    pb1 = *(const float4*)(Bg + (size_t)(brow + 8) * FL + bn + bcol);
    As[0][akq + 0][arow] = pa0.x; As[0][akq + 1][arow] = pa0.y;
    As[0][akq + 2][arow] = pa0.z; As[0][akq + 3][arow] = pa0.w;
    As[0][akq + 0][arow + 64] = pa1.x; As[0][akq + 1][arow + 64] = pa1.y;
    As[0][akq + 2][arow + 64] = pa1.z; As[0][akq + 3][arow + 64] = pa1.w;
    *(float4*)&Bs[0][brow][bcol] = pb0;
    *(float4*)&Bs[0][brow + 8][bcol] = pb1;
    __syncthreads();

    int buf = 0;
    for (int kt = 0; kt < NKT; kt++) {
        if (kt + 1 < NKT) {
            const int k0 = (kt + 1) * BK;
            pa0 = *(const float4*)(Ag + (size_t)(bm + arow)      * (NL * DM) + k0 + akq);
            pa1 = *(const float4*)(Ag + (size_t)(bm + arow + 64) * (NL * DM) + k0 + akq);
            pb0 = *(const float4*)(Bg + (size_t)(k0 + brow)     * FL + bn + bcol);
            pb1 = *(const float4*)(Bg + (size_t)(k0 + brow + 8) * FL + bn + bcol);
        }
#pragma unroll
        for (int k = 0; k < BK; k++) {
            unsigned long long bv[4];
#pragma unroll
            for (int jj = 0; jj < 4; jj++)
                bv[jj] = *(const unsigned long long*)&Bs[buf][k][tn + jj * 2];
#pragma unroll
            for (int i = 0; i < 8; i++) {
                unsigned long long av = bcast2(As[buf][k][tm + i]);
#pragma unroll
                for (int jj = 0; jj < 4; jj++) ffma2(acc[i][jj], av, bv[jj]);
            }
        }
        if (kt + 1 < NKT) {
            const int nb = buf ^ 1;
            As[nb][akq + 0][arow] = pa0.x; As[nb][akq + 1][arow] = pa0.y;
            As[nb][akq + 2][arow] = pa0.z; As[nb][akq + 3][arow] = pa0.w;
            As[nb][akq + 0][arow + 64] = pa1.x; As[nb][akq + 1][arow + 64] = pa1.y;
            As[nb][akq + 2][arow + 64] = pa1.z; As[nb][akq + 3][arow + 64] = pa1.w;
            *(float4*)&Bs[nb][brow][bcol] = pb0;
            *(float4*)&Bs[nb][brow + 8][bcol] = pb1;
        }
        __syncthreads();
        buf ^= 1;
    }

    float thr[8];
#pragma unroll
    for (int jj = 0; jj < 8; jj++) thr[jj] = expf(TH[l * FL + bn + tn + jj]);
#pragma unroll
    for (int i = 0; i < 8; i++) {
        const size_t base = (size_t)(bm + tm + i) * (NL * FL) + (size_t)l * FL + bn + tn;
        float v[8];
#pragma unroll
        for (int jj = 0; jj < 4; jj++) {
            float2 cc = unpack2(acc[i][jj]); v[jj * 2] = cc.x; v[jj * 2 + 1] = cc.y;
        }
        if (H) {
            *(float4*)(H + base)     = make_float4(v[0], v[1], v[2], v[3]);
            *(float4*)(H + base + 4) = make_float4(v[4], v[5], v[6], v[7]);
        }
        float a[8];
#pragma unroll
        for (int jj = 0; jj < 8; jj++) a[jj] = (v[jj] > thr[jj]) ? v[jj] : 0.0f;
        *(float4*)(A + base)     = make_float4(a[0], a[1], a[2], a[3]);
        *(float4*)(A + base + 4) = make_float4(a[4], a[5], a[6], a[7]);
        // tf32-rounded copy for the tensor-core decode
        *(float4*)(A32 + base)     = make_float4(tf32rn(a[0]), tf32rn(a[1]),
                                                 tf32rn(a[2]), tf32rn(a[3]));
        *(float4*)(A32 + base + 4) = make_float4(tf32rn(a[4]), tf32rn(a[5]),
                                                 tf32rn(a[6]), tf32rn(a[7]));
    }
}

// ---------------- round w_d to tf32 (triangle only) ----------------
__global__ __launch_bounds__(256)
void round_wd(const float* __restrict__ wd, float* __restrict__ o) {
    const int z = blockIdx.z;
    if ((z / NL) > (z % NL)) return;
    const size_t idx = (size_t)z * FL * DM +
                       ((size_t)blockIdx.x * 256 + threadIdx.x) * 4;
    float4 v = *(const float4*)(wd + idx);
    v.x = tf32rn(v.x); v.y = tf32rn(v.y); v.z = tf32rn(v.z); v.w = tf32rn(v.w);
    *(float4*)(o + idx) = v;
}

// ---------------- decode via mma.sync tf32 ----------------
// CTA 256x128x16, 8 warps (4 m x 2 n), warp tile 64x64.
#define AS_STRIDE 20
#define BS_STRIDE 136
#define AS_BYTES (2 * DBM * AS_STRIDE * 4)    // 40960
#define SMEM_DEC (AS_BYTES + 2 * DBK * BS_STRIDE * 4)  // 58368

__global__ __launch_bounds__(256, 1)
void decode_mma(const float* __restrict__ ACT,   // tf32-rounded acts [T][NL*FL]
                const float* __restrict__ WD,    // tf32-rounded w_d  [i][j][f][d]
                float* __restrict__ XH) {
    extern __shared__ float smem[];
    float* Asm = smem;                                  // [2][DBM][20]
    float* Bsm = smem + 2 * DBM * AS_STRIDE;            // [2][DBK][136]

    const int j  = (NL - 1) - blockIdx.z;
    const int bm = blockIdx.y * DBM;
    const int bn = blockIdx.x * DBN;
    const int KT = (j + 1) * (FL / DBK);

    const int tid  = threadIdx.x;
    const int lane = tid & 31, wid = tid >> 5;
    const int wm = wid & 3, wn = wid >> 2;
    const int r = lane >> 2, c = lane & 3;

    const float* arow_g = ACT + (size_t)(bm + tid) * (NL * FL);
    const uint32_t a_dst0 = smem_u32(&Asm[tid * AS_STRIDE]);
    const uint32_t a_dst1 = smem_u32(&Asm[(DBM + tid) * AS_STRIDE]);
    const int br = tid >> 4, bq = (tid & 15) * 8;
    const uint32_t b_dst0 = smem_u32(&Bsm[br * BS_STRIDE + bq]);
    const uint32_t b_dst1 = smem_u32(&Bsm[(DBK + br) * BS_STRIDE + bq]);
    const float* wbase = WD + (size_t)j * FL * DM + (size_t)br * DM + bn + bq;
    const size_t wd_istride = (size_t)NL * FL * DM;

    float acc[4][8][4];
#pragma unroll
    for (int mt = 0; mt < 4; mt++)
#pragma unroll
        for (int nt = 0; nt < 8; nt++)
#pragma unroll
            for (int q = 0; q < 4; q++) acc[mt][nt][q] = 0.0f;

    // stage k-tile 0 into buf 0
    {
        const float* sa = arow_g;
        cp16(a_dst0, sa); cp16(a_dst0 + 16, sa + 4);
        cp16(a_dst0 + 32, sa + 8); cp16(a_dst0 + 48, sa + 12);
        const float* sb = wbase;
        cp16(b_dst0, sb); cp16(b_dst0 + 16, sb + 4);
        cp_commit();
    }

    int buf = 0;
    for (int kt = 0; kt < KT; kt++) {
        if (kt + 1 < KT) {
            const int kn = kt + 1;
            const float* sa = arow_g + kn * DBK;
            const uint32_t ad = buf ? a_dst0 : a_dst1;
            cp16(ad, sa); cp16(ad + 16, sa + 4);
            cp16(ad + 32, sa + 8); cp16(ad + 48, sa + 12);
            const int ii = kn >> 7, f0 = (kn & 127) * DBK;
            const float* sb = wbase + (size_t)ii * wd_istride + (size_t)f0 * DM;
            const uint32_t bd = buf ? b_dst0 : b_dst1;
            cp16(bd, sb); cp16(bd + 16, sb + 4);
            cp_commit();
            asm volatile("cp.async.wait_group 1;");
        } else {
            asm volatile("cp.async.wait_group 0;");
        }
        __syncthreads();

        const uint32_t* Ab = (const uint32_t*)(Asm + buf * DBM * AS_STRIDE);
        const uint32_t* Bb = (const uint32_t*)(Bsm + buf * DBK * BS_STRIDE);
#pragma unroll
        for (int s = 0; s < 2; s++) {
            uint32_t a[4][4], b[8][2];
#pragma unroll
            for (int mt = 0; mt < 4; mt++) {
                const int m = wm * 64 + mt * 16 + r;
                const int k = s * 8 + c;
                a[mt][0] = Ab[m * AS_STRIDE + k];
                a[mt][1] = Ab[(m + 8) * AS_STRIDE + k];
                a[mt][2] = Ab[m * AS_STRIDE + k + 4];
                a[mt][3] = Ab[(m + 8) * AS_STRIDE + k + 4];
            }
#pragma unroll
            for (int nt = 0; nt < 8; nt++) {
                const int n = wn * 64 + nt * 8 + r;
                b[nt][0] = Bb[(s * 8 + c) * BS_STRIDE + n];
                b[nt][1] = Bb[(s * 8 + c + 4) * BS_STRIDE + n];
            }
#pragma unroll
            for (int mt = 0; mt < 4; mt++)
#pragma unroll
                for (int nt = 0; nt < 8; nt++)
                    mma_tf32(acc[mt][nt], a[mt], b[nt]);
        }
        __syncthreads();
        buf ^= 1;
    }

#pragma unroll
    for (int mt = 0; mt < 4; mt++) {
        const int row = bm + wm * 64 + mt * 16 + r;
#pragma unroll
        for (int nt = 0; nt < 8; nt++) {
            const int col = bn + wn * 64 + nt * 8 + 2 * c;
            float* p = XH + (size_t)row * (NL * DM) + (size_t)j * DM + col;
            *(float2*)p = make_float2(acc[mt][nt][0], acc[mt][nt][1]);
            *(float2*)(p + (size_t)8 * (NL * DM)) =
                make_float2(acc[mt][nt][2], acc[mt][nt][3]);
        }
    }
}

// ---------------- host ----------------
extern "C" void kernel_launch(void* const* d_in, const int* in_sizes, int n_in,
                              void* d_out, int out_size) {
    const float* x  = (const float*)d_in[0];
    const float* we = (const float*)d_in[1];
    const float* wd = (const float*)d_in[2];
    const float* th = (const float*)d_in[3];
    float* out = (float*)d_out;

    const long long HE = (long long)T_TOK * NL * FL;
    const long long XE = (long long)T_TOK * NL * DM;

    float *hp, *ap, *xp;
    if ((long long)out_size >= 2 * HE + XE) {
        hp = out; ap = out + HE; xp = out + 2 * HE;
    } else {
        hp = nullptr;
        float* sp = nullptr;
        cudaGetSymbolAddress((void**)&sp, g_acts_scratch);
        ap = sp; xp = out;
    }

    float *wd32 = nullptr, *a32 = nullptr;
    cudaGetSymbolAddress((void**)&wd32, g_wd32);
    cudaGetSymbolAddress((void**)&a32, g_acts32);

    cudaFuncSetAttribute(decode_mma, cudaFuncAttributeMaxDynamicSharedMemorySize, SMEM_DEC);

    round_wd<<<dim3(FL * DM / 1024, 1, NL * NL), 256>>>(wd, wd32);
    encode_kernel<<<dim3(FL / BN, T_TOK / BM, NL), 256>>>(x, we, th, hp, ap, a32);
    decode_mma<<<dim3(DM / DBN, T_TOK / DBM, NL), 256, SMEM_DEC>>>(a32, wd32, xp);
}

// round 5
// speedup vs baseline: 2.1738x; 1.1029x over previous
#include <cuda_runtime.h>
#include <cuda_fp16.h>
#include <math.h>
#include <stdint.h>

#define T_TOK 2048
#define NL    12
#define DM    768
#define FL    2048

// encode tile
#define BM 128
#define BN 128
#define BK 16

// decode tile
#define DBM 256
#define DBN 128
#define DBK 32
#define ASTR 40     // A smem stride in halves
#define BSTR 136    // B smem stride in halves
// smem half-offsets
#define AH_OFF 0
#define AL_OFF 20480
#define B_OFF  40960
#define SMEM_DEC_BYTES ((B_OFF + 2 * DBK * BSTR) * 2)   // 99328

__device__ __half g_wd16[(size_t)NL * NL * FL * DM];
__device__ __half g_ah[(size_t)T_TOK * NL * FL];
__device__ __half g_al[(size_t)T_TOK * NL * FL];
__device__ float  g_acts_scratch[(size_t)T_TOK * NL * FL];

// ---------------- helpers ----------------
__device__ __forceinline__ unsigned long long bcast2(float a) {
    unsigned long long r; asm("mov.b64 %0, {%1,%1};" : "=l"(r) : "f"(a)); return r;
}
__device__ __forceinline__ void ffma2(unsigned long long& c, unsigned long long a,
                                      unsigned long long b) {
    asm("fma.rn.f32x2 %0, %1, %2, %0;" : "+l"(c) : "l"(a), "l"(b));
}
__device__ __forceinline__ float2 unpack2(unsigned long long v) {
    float2 r; asm("mov.b64 {%0,%1}, %2;" : "=f"(r.x), "=f"(r.y) : "l"(v)); return r;
}
__device__ __forceinline__ uint32_t smem_u32(const void* p) {
    return (uint32_t)__cvta_generic_to_shared(p);
}
__device__ __forceinline__ void cp16(uint32_t d, const void* s) {
    asm volatile("cp.async.cg.shared.global [%0], [%1], 16;" :: "r"(d), "l"(s));
}
__device__ __forceinline__ void ldsm_x4(uint32_t* r, uint32_t a) {
    asm volatile("ldmatrix.sync.aligned.m8n8.x4.shared.b16 {%0,%1,%2,%3}, [%4];"
                 : "=r"(r[0]), "=r"(r[1]), "=r"(r[2]), "=r"(r[3]) : "r"(a));
}
__device__ __forceinline__ void ldsm_x4t(uint32_t* r, uint32_t a) {
    asm volatile("ldmatrix.sync.aligned.m8n8.x4.trans.shared.b16 {%0,%1,%2,%3}, [%4];"
                 : "=r"(r[0]), "=r"(r[1]), "=r"(r[2]), "=r"(r[3]) : "r"(a));
}
__device__ __forceinline__ void mma_f16(float* d, const uint32_t* a, const uint32_t* b) {
    asm volatile(
        "mma.sync.aligned.m16n8k16.row.col.f32.f16.f16.f32 "
        "{%0,%1,%2,%3}, {%4,%5,%6,%7}, {%8,%9}, {%0,%1,%2,%3};"
        : "+f"(d[0]), "+f"(d[1]), "+f"(d[2]), "+f"(d[3])
        : "r"(a[0]), "r"(a[1]), "r"(a[2]), "r"(a[3]), "r"(b[0]), "r"(b[1]));
}

// ---------------- encode (fp32 FFMA2, exact JumpReLU) ----------------
struct alignas(16) H8 { __half v[8]; };

__global__ __launch_bounds__(256, 2)
void encode_kernel(const float* __restrict__ X, const float* __restrict__ WE,
                   const float* __restrict__ TH, float* __restrict__ H,
                   float* __restrict__ A, __half* __restrict__ AH,
                   __half* __restrict__ AL) {
    const int l = blockIdx.z, bm = blockIdx.y * BM, bn = blockIdx.x * BN;
    const float* Ag = X + (size_t)l * DM;
    const float* Bg = WE + (size_t)l * DM * FL;

    __shared__ float As[2][BK][BM + 4];
    __shared__ float Bs[2][BK][BN];

    const int tid = threadIdx.x;
    const int arow = tid >> 2, akq = (tid & 3) << 2;
    const int brow = tid >> 5, bcol = (tid & 31) << 2;
    const int tm = (tid >> 4) << 3, tn = (tid & 15) << 3;

    unsigned long long acc[8][4];
#pragma unroll
    for (int i = 0; i < 8; i++)
#pragma unroll
        for (int jj = 0; jj < 4; jj++) acc[i][jj] = 0ULL;

    const int NKT = DM / BK;
    float4 pa0, pa1, pb0, pb1;
    pa0 = *(const float4*)(Ag + (size_t)(bm + arow)      * (NL * DM) + akq);
    pa1 = *(const float4*)(Ag + (size_t)(bm + arow + 64) * (NL * DM) + akq);
    pb0 = *(const float4*)(Bg + (size_t)(brow)     * FL + bn + bcol);
    pb1 = *(const float4*)(Bg + (size_t)(brow + 8) * FL + bn + bcol);
    As[0][akq + 0][arow] = pa0.x; As[0][akq + 1][arow] = pa0.y;
    As[0][akq + 2][arow] = pa0.z; As[0][akq + 3][arow] = pa0.w;
    As[0][akq + 0][arow + 64] = pa1.x; As[0][akq + 1][arow + 64] = pa1.y;
    As[0][akq + 2][arow + 64] = pa1.z; As[0][akq + 3][arow + 64] = pa1.w;
    *(float4*)&Bs[0][brow][bcol] = pb0;
    *(float4*)&Bs[0][brow + 8][bcol] = pb1;
    __syncthreads();

    int buf = 0;
    for (int kt = 0; kt < NKT; kt++) {
        if (kt + 1 < NKT) {
            const int k0 = (kt + 1) * BK;
            pa0 = *(const float4*)(Ag + (size_t)(bm + arow)      * (NL * DM) + k0 + akq);
            pa1 = *(const float4*)(Ag + (size_t)(bm + arow + 64) * (NL * DM) + k0 + akq);
            pb0 = *(const float4*)(Bg + (size_t)(k0 + brow)     * FL + bn + bcol);
            pb1 = *(const float4*)(Bg + (size_t)(k0 + brow + 8) * FL + bn + bcol);
        }
#pragma unroll
        for (int k = 0; k < BK; k++) {
            unsigned long long bv[4];
#pragma unroll
            for (int jj = 0; jj < 4; jj++)
                bv[jj] = *(const unsigned long long*)&Bs[buf][k][tn + jj * 2];
#pragma unroll
            for (int i = 0; i < 8; i++) {
                unsigned long long av = bcast2(As[buf][k][tm + i]);
#pragma unroll
                for (int jj = 0; jj < 4; jj++) ffma2(acc[i][jj], av, bv[jj]);
            }
        }
        if (kt + 1 < NKT) {
            const int nb = buf ^ 1;
            As[nb][akq + 0][arow] = pa0.x; As[nb][akq + 1][arow] = pa0.y;
            As[nb][akq + 2][arow] = pa0.z; As[nb][akq + 3][arow] = pa0.w;
            As[nb][akq + 0][arow + 64] = pa1.x; As[nb][akq + 1][arow + 64] = pa1.y;
            As[nb][akq + 2][arow + 64] = pa1.z; As[nb][akq + 3][arow + 64] = pa1.w;
            *(float4*)&Bs[nb][brow][bcol] = pb0;
            *(float4*)&Bs[nb][brow + 8][bcol] = pb1;
        }
        __syncthreads();
        buf ^= 1;
    }

    float thr[8];
#pragma unroll
    for (int jj = 0; jj < 8; jj++) thr[jj] = expf(TH[l * FL + bn + tn + jj]);
#pragma unroll
    for (int i = 0; i < 8; i++) {
        const size_t base = (size_t)(bm + tm + i) * (NL * FL) + (size_t)l * FL + bn + tn;
        float v[8];
#pragma unroll
        for (int jj = 0; jj < 4; jj++) {
            float2 cc = unpack2(acc[i][jj]); v[jj * 2] = cc.x; v[jj * 2 + 1] = cc.y;
        }
        if (H) {
            *(float4*)(H + base)     = make_float4(v[0], v[1], v[2], v[3]);
            *(float4*)(H + base + 4) = make_float4(v[4], v[5], v[6], v[7]);
        }
        float a[8];
#pragma unroll
        for (int jj = 0; jj < 8; jj++) a[jj] = (v[jj] > thr[jj]) ? v[jj] : 0.0f;
        *(float4*)(A + base)     = make_float4(a[0], a[1], a[2], a[3]);
        *(float4*)(A + base + 4) = make_float4(a[4], a[5], a[6], a[7]);
        H8 hh, hl;
#pragma unroll
        for (int jj = 0; jj < 8; jj++) {
            hh.v[jj] = __float2half_rn(a[jj]);
            hl.v[jj] = __float2half_rn(a[jj] - __half2float(hh.v[jj]));
        }
        *(H8*)(AH + base) = hh;
        *(H8*)(AL + base) = hl;
    }
}

// ---------------- round w_d to fp16 (triangle only) ----------------
__global__ __launch_bounds__(256)
void round_wd16(const float* __restrict__ wd, __half* __restrict__ o) {
    const int z = blockIdx.z;
    if ((z / NL) > (z % NL)) return;
    const size_t idx = (size_t)z * FL * DM +
                       ((size_t)blockIdx.x * 256 + threadIdx.x) * 4;
    float4 v = *(const float4*)(wd + idx);
    H8 h4;  // use first 4
    h4.v[0] = __float2half_rn(v.x); h4.v[1] = __float2half_rn(v.y);
    h4.v[2] = __float2half_rn(v.z); h4.v[3] = __float2half_rn(v.w);
    *(uint2*)(o + idx) = *(uint2*)&h4.v[0];
}

// ---------------- decode via mma.sync fp16, 2-product split ----------------
// CTA 256x128x32, 8 warps (4m x 2n), warp tile 64x64.
__global__ __launch_bounds__(256, 1)
void decode_fp16(const __half* __restrict__ AH, const __half* __restrict__ AL,
                 const __half* __restrict__ WD, float* __restrict__ XH) {
    extern __shared__ __half sm[];
    const uint32_t sb = smem_u32(sm);

    const int j  = (NL - 1) - blockIdx.z;
    const int bm = blockIdx.y * DBM;
    const int bn = blockIdx.x * DBN;
    const int KT = (j + 1) * (FL / DBK);   // (j+1)*64

    const int tid  = threadIdx.x;
    const int lane = tid & 31, wid = tid >> 5;
    const int wm = wid & 3, wn = wid >> 2;
    const int r = lane >> 2, c = lane & 3;
    const int lr = lane & 15, lc = lane >> 4;

    const __half* gah = AH + (size_t)(bm + tid) * (NL * FL);
    const __half* gal = AL + (size_t)(bm + tid) * (NL * FL);
    const __half* wj  = WD + (size_t)j * FL * DM;   // + ii*NL*FL*DM + f*DM
    const size_t wd_istride = (size_t)NL * FL * DM;

    // cp.async destination bases (half offsets)
    const uint32_t a_row_off = (uint32_t)tid * ASTR;
    const int brow = tid >> 3, bq = (tid & 7) * 16;
    const uint32_t b_row_off = (uint32_t)brow * BSTR + bq;

    float acc[4][8][4];
#pragma unroll
    for (int mt = 0; mt < 4; mt++)
#pragma unroll
        for (int nt = 0; nt < 8; nt++)
#pragma unroll
            for (int q = 0; q < 4; q++) acc[mt][nt][q] = 0.0f;

    // prefetch ktile 0 into stage 0
    {
        const __half* sa = gah;
        const __half* sl = gal;
#pragma unroll
        for (int q = 0; q < 4; q++) {
            cp16(sb + 2 * (AH_OFF + a_row_off + q * 8), sa + q * 8);
            cp16(sb + 2 * (AL_OFF + a_row_off + q * 8), sl + q * 8);
        }
        const __half* sbp = wj + (size_t)brow * DM + bn + bq;
        cp16(sb + 2 * (B_OFF + b_row_off),     sbp);
        cp16(sb + 2 * (B_OFF + b_row_off + 8), sbp + 8);
        asm volatile("cp.async.commit_group;");
    }

    int buf = 0;
    for (int kt = 0; kt < KT; kt++) {
        if (kt + 1 < KT) {
            const int kn = kt + 1;
            const int st = buf ^ 1;
            const __half* sa = gah + kn * DBK;
            const __half* sl = gal + kn * DBK;
            const uint32_t ao = a_row_off + (uint32_t)st * (DBM * ASTR);
#pragma unroll
            for (int q = 0; q < 4; q++) {
                cp16(sb + 2 * (AH_OFF + ao + q * 8), sa + q * 8);
                cp16(sb + 2 * (AL_OFF + ao + q * 8), sl + q * 8);
            }
            const int ii = kn >> 6, f0 = (kn & 63) * DBK;
            const __half* sbp = wj + (size_t)ii * wd_istride +
                                (size_t)(f0 + brow) * DM + bn + bq;
            const uint32_t bo = B_OFF + b_row_off + (uint32_t)st * (DBK * BSTR);
            cp16(sb + 2 * bo, sbp);
            cp16(sb + 2 * (bo + 8), sbp + 8);
            asm volatile("cp.async.commit_group;");
            asm volatile("cp.async.wait_group 1;");
        } else {
            asm volatile("cp.async.wait_group 0;");
        }
        __syncthreads();

        const uint32_t ah_b = sb + 2 * (AH_OFF + (uint32_t)buf * (DBM * ASTR));
        const uint32_t al_b = sb + 2 * (AL_OFF + (uint32_t)buf * (DBM * ASTR));
        const uint32_t b_b  = sb + 2 * (B_OFF  + (uint32_t)buf * (DBK * BSTR));

#pragma unroll
        for (int s = 0; s < 2; s++) {
            uint32_t ah[4][4], al[4][4], bb[4][4];
#pragma unroll
            for (int mt = 0; mt < 4; mt++) {
                const uint32_t ao =
                    2 * ((uint32_t)(wm * 64 + mt * 16 + lr) * ASTR + s * 16 + 8 * lc);
                ldsm_x4(ah[mt], ah_b + ao);
                ldsm_x4(al[mt], al_b + ao);
            }
#pragma unroll
            for (int g = 0; g < 4; g++) {
                const uint32_t bo =
                    2 * ((uint32_t)(s * 16 + lr) * BSTR + wn * 64 + g * 16 + 8 * lc);
                ldsm_x4t(bb[g], b_b + bo);
            }
#pragma unroll
            for (int mt = 0; mt < 4; mt++)
#pragma unroll
                for (int g = 0; g < 4; g++) {
                    mma_f16(acc[mt][2 * g],     ah[mt], &bb[g][0]);
                    mma_f16(acc[mt][2 * g + 1], ah[mt], &bb[g][2]);
                    mma_f16(acc[mt][2 * g],     al[mt], &bb[g][0]);
                    mma_f16(acc[mt][2 * g + 1], al[mt], &bb[g][2]);
                }
        }
        __syncthreads();
        buf ^= 1;
    }

#pragma unroll
    for (int mt = 0; mt < 4; mt++) {
        const int row = bm + wm * 64 + mt * 16 + r;
#pragma unroll
        for (int nt = 0; nt < 8; nt++) {
            const int col = bn + wn * 64 + nt * 8 + 2 * c;
            float* p = XH + (size_t)row * (NL * DM) + (size_t)j * DM + col;
            *(float2*)p = make_float2(acc[mt][nt][0], acc[mt][nt][1]);
            *(float2*)(p + (size_t)8 * (NL * DM)) =
                make_float2(acc[mt][nt][2], acc[mt][nt][3]);
        }
    }
}

// ---------------- host ----------------
extern "C" void kernel_launch(void* const* d_in, const int* in_sizes, int n_in,
                              void* d_out, int out_size) {
    const float* x  = (const float*)d_in[0];
    const float* we = (const float*)d_in[1];
    const float* wd = (const float*)d_in[2];
    const float* th = (const float*)d_in[3];
    float* out = (float*)d_out;

    const long long HE = (long long)T_TOK * NL * FL;
    const long long XE = (long long)T_TOK * NL * DM;

    float *hp, *ap, *xp;
    if ((long long)out_size >= 2 * HE + XE) {
        hp = out; ap = out + HE; xp = out + 2 * HE;
    } else {
        hp = nullptr;
        float* sp = nullptr;
        cudaGetSymbolAddress((void**)&sp, g_acts_scratch);
        ap = sp; xp = out;
    }

    __half *wd16 = nullptr, *ah = nullptr, *al = nullptr;
    cudaGetSymbolAddress((void**)&wd16, g_wd16);
    cudaGetSymbolAddress((void**)&ah, g_ah);
    cudaGetSymbolAddress((void**)&al, g_al);

    cudaFuncSetAttribute(decode_fp16, cudaFuncAttributeMaxDynamicSharedMemorySize,
                         SMEM_DEC_BYTES);

    round_wd16<<<dim3(FL * DM / 1024, 1, NL * NL), 256>>>(wd, wd16);
    encode_kernel<<<dim3(FL / BN, T_TOK / BM, NL), 256>>>(x, we, th, hp, ap, ah, al);
    decode_fp16<<<dim3(DM / DBN, T_TOK / DBM, NL), 256, SMEM_DEC_BYTES>>>(ah, al, wd16, xp);
}

// round 6
// speedup vs baseline: 3.1574x; 1.4525x over previous
#include <cuda_runtime.h>
#include <cuda_fp16.h>
#include <math.h>
#include <stdint.h>

#define T_TOK 2048
#define NL    12
#define DM    768
#define FL    2048

// encode tile
#define BM 128
#define BN 128
#define BK 16

// decode tile
#define DBM 256
#define DBN 128
#define DBK 32
#define ASTR 40     // A smem stride in halves
#define BSTR 136    // B smem stride in halves
#define A_OFF 0
#define B_OFF 20480                                   // 2*DBM*ASTR halves
#define SMEM_DEC_BYTES ((B_OFF + 2 * DBK * BSTR) * 2) // 58368

__device__ __half g_wd16[(size_t)NL * NL * FL * DM];
__device__ __half g_ah[(size_t)T_TOK * NL * FL];
__device__ float  g_acts_scratch[(size_t)T_TOK * NL * FL];

__constant__ unsigned char c_tri_i[78];
__constant__ unsigned char c_tri_j[78];

// ---------------- helpers ----------------
__device__ __forceinline__ unsigned long long bcast2(float a) {
    unsigned long long r; asm("mov.b64 %0, {%1,%1};" : "=l"(r) : "f"(a)); return r;
}
__device__ __forceinline__ void ffma2(unsigned long long& c, unsigned long long a,
                                      unsigned long long b) {
    asm("fma.rn.f32x2 %0, %1, %2, %0;" : "+l"(c) : "l"(a), "l"(b));
}
__device__ __forceinline__ float2 unpack2(unsigned long long v) {
    float2 r; asm("mov.b64 {%0,%1}, %2;" : "=f"(r.x), "=f"(r.y) : "l"(v)); return r;
}
__device__ __forceinline__ uint32_t smem_u32(const void* p) {
    return (uint32_t)__cvta_generic_to_shared(p);
}
__device__ __forceinline__ void cp16(uint32_t d, const void* s) {
    asm volatile("cp.async.cg.shared.global [%0], [%1], 16;" :: "r"(d), "l"(s));
}
__device__ __forceinline__ void ldsm_x4(uint32_t* r, uint32_t a) {
    asm volatile("ldmatrix.sync.aligned.m8n8.x4.shared.b16 {%0,%1,%2,%3}, [%4];"
                 : "=r"(r[0]), "=r"(r[1]), "=r"(r[2]), "=r"(r[3]) : "r"(a));
}
__device__ __forceinline__ void ldsm_x4t(uint32_t* r, uint32_t a) {
    asm volatile("ldmatrix.sync.aligned.m8n8.x4.trans.shared.b16 {%0,%1,%2,%3}, [%4];"
                 : "=r"(r[0]), "=r"(r[1]), "=r"(r[2]), "=r"(r[3]) : "r"(a));
}
__device__ __forceinline__ void mma_f16(float* d, const uint32_t* a, const uint32_t* b) {
    asm volatile(
        "mma.sync.aligned.m16n8k16.row.col.f32.f16.f16.f32 "
        "{%0,%1,%2,%3}, {%4,%5,%6,%7}, {%8,%9}, {%0,%1,%2,%3};"
        : "+f"(d[0]), "+f"(d[1]), "+f"(d[2]), "+f"(d[3])
        : "r"(a[0]), "r"(a[1]), "r"(a[2]), "r"(a[3]), "r"(b[0]), "r"(b[1]));
}

struct alignas(16) H8 { __half v[8]; };

// ---------------- encode (fp32 FFMA2, exact JumpReLU) ----------------
__global__ __launch_bounds__(256, 2)
void encode_kernel(const float* __restrict__ X, const float* __restrict__ WE,
                   const float* __restrict__ TH, float* __restrict__ H,
                   float* __restrict__ A, __half* __restrict__ AH) {
    const int l = blockIdx.z, bm = blockIdx.y * BM, bn = blockIdx.x * BN;
    const float* Ag = X + (size_t)l * DM;
    const float* Bg = WE + (size_t)l * DM * FL;

    __shared__ float As[2][BK][BM + 4];
    __shared__ float Bs[2][BK][BN];

    const int tid = threadIdx.x;
    const int arow = tid >> 2, akq = (tid & 3) << 2;
    const int brow = tid >> 5, bcol = (tid & 31) << 2;
    const int tm = (tid >> 4) << 3, tn = (tid & 15) << 3;

    unsigned long long acc[8][4];
#pragma unroll
    for (int i = 0; i < 8; i++)
#pragma unroll
        for (int jj = 0; jj < 4; jj++) acc[i][jj] = 0ULL;

    const int NKT = DM / BK;
    float4 pa0, pa1, pb0, pb1;
    pa0 = *(const float4*)(Ag + (size_t)(bm + arow)      * (NL * DM) + akq);
    pa1 = *(const float4*)(Ag + (size_t)(bm + arow + 64) * (NL * DM) + akq);
    pb0 = *(const float4*)(Bg + (size_t)(brow)     * FL + bn + bcol);
    pb1 = *(const float4*)(Bg + (size_t)(brow + 8) * FL + bn + bcol);
    As[0][akq + 0][arow] = pa0.x; As[0][akq + 1][arow] = pa0.y;
    As[0][akq + 2][arow] = pa0.z; As[0][akq + 3][arow] = pa0.w;
    As[0][akq + 0][arow + 64] = pa1.x; As[0][akq + 1][arow + 64] = pa1.y;
    As[0][akq + 2][arow + 64] = pa1.z; As[0][akq + 3][arow + 64] = pa1.w;
    *(float4*)&Bs[0][brow][bcol] = pb0;
    *(float4*)&Bs[0][brow + 8][bcol] = pb1;
    __syncthreads();

    int buf = 0;
    for (int kt = 0; kt < NKT; kt++) {
        if (kt + 1 < NKT) {
            const int k0 = (kt + 1) * BK;
            pa0 = *(const float4*)(Ag + (size_t)(bm + arow)      * (NL * DM) + k0 + akq);
            pa1 = *(const float4*)(Ag + (size_t)(bm + arow + 64) * (NL * DM) + k0 + akq);
            pb0 = *(const float4*)(Bg + (size_t)(k0 + brow)     * FL + bn + bcol);
            pb1 = *(const float4*)(Bg + (size_t)(k0 + brow + 8) * FL + bn + bcol);
        }
#pragma unroll
        for (int k = 0; k < BK; k++) {
            unsigned long long bv[4];
#pragma unroll
            for (int jj = 0; jj < 4; jj++)
                bv[jj] = *(const unsigned long long*)&Bs[buf][k][tn + jj * 2];
#pragma unroll
            for (int i = 0; i < 8; i++) {
                unsigned long long av = bcast2(As[buf][k][tm + i]);
#pragma unroll
                for (int jj = 0; jj < 4; jj++) ffma2(acc[i][jj], av, bv[jj]);
            }
        }
        if (kt + 1 < NKT) {
            const int nb = buf ^ 1;
            As[nb][akq + 0][arow] = pa0.x; As[nb][akq + 1][arow] = pa0.y;
            As[nb][akq + 2][arow] = pa0.z; As[nb][akq + 3][arow] = pa0.w;
            As[nb][akq + 0][arow + 64] = pa1.x; As[nb][akq + 1][arow + 64] = pa1.y;
            As[nb][akq + 2][arow + 64] = pa1.z; As[nb][akq + 3][arow + 64] = pa1.w;
            *(float4*)&Bs[nb][brow][bcol] = pb0;
            *(float4*)&Bs[nb][brow + 8][bcol] = pb1;
        }
        __syncthreads();
        buf ^= 1;
    }

    float thr[8];
#pragma unroll
    for (int jj = 0; jj < 8; jj++) thr[jj] = expf(TH[l * FL + bn + tn + jj]);
#pragma unroll
    for (int i = 0; i < 8; i++) {
        const size_t base = (size_t)(bm + tm + i) * (NL * FL) + (size_t)l * FL + bn + tn;
        float v[8];
#pragma unroll
        for (int jj = 0; jj < 4; jj++) {
            float2 cc = unpack2(acc[i][jj]); v[jj * 2] = cc.x; v[jj * 2 + 1] = cc.y;
        }
        if (H) {
            *(float4*)(H + base)     = make_float4(v[0], v[1], v[2], v[3]);
            *(float4*)(H + base + 4) = make_float4(v[4], v[5], v[6], v[7]);
        }
        float a[8];
#pragma unroll
        for (int jj = 0; jj < 8; jj++) a[jj] = (v[jj] > thr[jj]) ? v[jj] : 0.0f;
        *(float4*)(A + base)     = make_float4(a[0], a[1], a[2], a[3]);
        *(float4*)(A + base + 4) = make_float4(a[4], a[5], a[6], a[7]);
        H8 hh;
#pragma unroll
        for (int jj = 0; jj < 8; jj++) hh.v[jj] = __float2half_rn(a[jj]);
        *(H8*)(AH + base) = hh;
    }
}

// ---------------- round w_d to fp16 (triangle pairs only) ----------------
__global__ __launch_bounds__(256)
void round_wd16(const float* __restrict__ wd, __half* __restrict__ o) {
    const int z = c_tri_i[blockIdx.z] * NL + c_tri_j[blockIdx.z];
    const size_t idx = (size_t)z * FL * DM +
                       ((size_t)blockIdx.x * 256 + threadIdx.x) * 4;
    float4 v = *(const float4*)(wd + idx);
    H8 h4;
    h4.v[0] = __float2half_rn(v.x); h4.v[1] = __float2half_rn(v.y);
    h4.v[2] = __float2half_rn(v.z); h4.v[3] = __float2half_rn(v.w);
    *(uint2*)(o + idx) = *(uint2*)&h4.v[0];
}

// ---------------- decode via mma.sync fp16 (single product) ----------------
// CTA 256x128x32, 8 warps (4m x 2n), warp tile 64x64.
__global__ __launch_bounds__(256, 1)
void decode_fp16(const __half* __restrict__ AH, const __half* __restrict__ WD,
                 float* __restrict__ XH) {
    extern __shared__ __half sm[];
    const uint32_t sb = smem_u32(sm);

    const int j  = (NL - 1) - blockIdx.z;
    const int bm = blockIdx.y * DBM;
    const int bn = blockIdx.x * DBN;
    const int KT = (j + 1) * (FL / DBK);

    const int tid  = threadIdx.x;
    const int lane = tid & 31, wid = tid >> 5;
    const int wm = wid & 3, wn = wid >> 2;
    const int r = lane >> 2, c = lane & 3;
    const int lr = lane & 15, lc = lane >> 4;

    const __half* gah = AH + (size_t)(bm + tid) * (NL * FL);
    const __half* wj  = WD + (size_t)j * FL * DM;
    const size_t wd_istride = (size_t)NL * FL * DM;

    const uint32_t a_row_off = (uint32_t)tid * ASTR;
    const int brow = tid >> 3, bq = (tid & 7) * 16;
    const uint32_t b_row_off = (uint32_t)brow * BSTR + bq;

    float acc[4][8][4];
#pragma unroll
    for (int mt = 0; mt < 4; mt++)
#pragma unroll
        for (int nt = 0; nt < 8; nt++)
#pragma unroll
            for (int q = 0; q < 4; q++) acc[mt][nt][q] = 0.0f;

    {   // prefetch ktile 0 -> stage 0
        const __half* sa = gah;
#pragma unroll
        for (int q = 0; q < 4; q++)
            cp16(sb + 2 * (A_OFF + a_row_off + q * 8), sa + q * 8);
        const __half* sbp = wj + (size_t)brow * DM + bn + bq;
        cp16(sb + 2 * (B_OFF + b_row_off),     sbp);
        cp16(sb + 2 * (B_OFF + b_row_off + 8), sbp + 8);
        asm volatile("cp.async.commit_group;");
    }

    int buf = 0;
    for (int kt = 0; kt < KT; kt++) {
        if (kt + 1 < KT) {
            const int kn = kt + 1;
            const int st = buf ^ 1;
            const __half* sa = gah + kn * DBK;
            const uint32_t ao = a_row_off + (uint32_t)st * (DBM * ASTR);
#pragma unroll
            for (int q = 0; q < 4; q++)
                cp16(sb + 2 * (A_OFF + ao + q * 8), sa + q * 8);
            const int ii = kn >> 6, f0 = (kn & 63) * DBK;
            const __half* sbp = wj + (size_t)ii * wd_istride +
                                (size_t)(f0 + brow) * DM + bn + bq;
            const uint32_t bo = B_OFF + b_row_off + (uint32_t)st * (DBK * BSTR);
            cp16(sb + 2 * bo, sbp);
            cp16(sb + 2 * (bo + 8), sbp + 8);
            asm volatile("cp.async.commit_group;");
            asm volatile("cp.async.wait_group 1;");
        } else {
            asm volatile("cp.async.wait_group 0;");
        }
        __syncthreads();

        const uint32_t a_b = sb + 2 * (A_OFF + (uint32_t)buf * (DBM * ASTR));
        const uint32_t b_b = sb + 2 * (B_OFF + (uint32_t)buf * (DBK * BSTR));

#pragma unroll
        for (int s = 0; s < 2; s++) {
            uint32_t a[4][4], bb[4][4];
#pragma unroll
            for (int mt = 0; mt < 4; mt++) {
                const uint32_t ao =
                    2 * ((uint32_t)(wm * 64 + mt * 16 + lr) * ASTR + s * 16 + 8 * lc);
                ldsm_x4(a[mt], a_b + ao);
            }
#pragma unroll
            for (int g = 0; g < 4; g++) {
                const uint32_t bo =
                    2 * ((uint32_t)(s * 16 + lr) * BSTR + wn * 64 + g * 16 + 8 * lc);
                ldsm_x4t(bb[g], b_b + bo);
            }
#pragma unroll
            for (int mt = 0; mt < 4; mt++)
#pragma unroll
                for (int g = 0; g < 4; g++) {
                    mma_f16(acc[mt][2 * g],     a[mt], &bb[g][0]);
                    mma_f16(acc[mt][2 * g + 1], a[mt], &bb[g][2]);
                }
        }
        __syncthreads();
        buf ^= 1;
    }

#pragma unroll
    for (int mt = 0; mt < 4; mt++) {
        const int row = bm + wm * 64 + mt * 16 + r;
#pragma unroll
        for (int nt = 0; nt < 8; nt++) {
            const int col = bn + wn * 64 + nt * 8 + 2 * c;
            float* p = XH + (size_t)row * (NL * DM) + (size_t)j * DM + col;
            *(float2*)p = make_float2(acc[mt][nt][0], acc[mt][nt][1]);
            *(float2*)(p + (size_t)8 * (NL * DM)) =
                make_float2(acc[mt][nt][2], acc[mt][nt][3]);
        }
    }
}

// ---------------- host ----------------
extern "C" void kernel_launch(void* const* d_in, const int* in_sizes, int n_in,
                              void* d_out, int out_size) {
    const float* x  = (const float*)d_in[0];
    const float* we = (const float*)d_in[1];
    const float* wd = (const float*)d_in[2];
    const float* th = (const float*)d_in[3];
    float* out = (float*)d_out;

    const long long HE = (long long)T_TOK * NL * FL;
    const long long XE = (long long)T_TOK * NL * DM;

    float *hp, *ap, *xp;
    if ((long long)out_size >= 2 * HE + XE) {
        hp = out; ap = out + HE; xp = out + 2 * HE;
    } else {
        hp = nullptr;
        float* sp = nullptr;
        cudaGetSymbolAddress((void**)&sp, g_acts_scratch);
        ap = sp; xp = out;
    }

    __half *wd16 = nullptr, *ah = nullptr;
    cudaGetSymbolAddress((void**)&wd16, g_wd16);
    cudaGetSymbolAddress((void**)&ah, g_ah);

    // triangle pair tables (host-side const; cheap per-call, capture-safe)
    static bool tri_done = false;
    if (!tri_done) {
        unsigned char ti[78], tj[78];
        int n = 0;
        for (int i = 0; i < NL; i++)
            for (int j = i; j < NL; j++) { ti[n] = (unsigned char)i; tj[n] = (unsigned char)j; n++; }
        cudaMemcpyToSymbol(c_tri_i, ti, 78);
        cudaMemcpyToSymbol(c_tri_j, tj, 78);
        tri_done = true;
    }

    cudaFuncSetAttribute(decode_fp16, cudaFuncAttributeMaxDynamicSharedMemorySize,
                         SMEM_DEC_BYTES);

    round_wd16<<<dim3(FL * DM / 1024, 1, 78), 256>>>(wd, wd16);
    encode_kernel<<<dim3(FL / BN, T_TOK / BM, NL), 256>>>(x, we, th, hp, ap, ah);
    decode_fp16<<<dim3(DM / DBN, T_TOK / DBM, NL), 256, SMEM_DEC_BYTES>>>(ah, wd16, xp);
}

// round 7
// speedup vs baseline: 3.6783x; 1.1650x over previous
#include <cuda_runtime.h>
#include <cuda_fp16.h>
#include <math.h>
#include <stdint.h>

#define T_TOK 2048
#define NL    12
#define DM    768
#define FL    2048

// shared tile geometry (both mma kernels): CTA 256x128x32, 8 warps, warp 64x64
#define DBM 256
#define DBN 128
#define DBK 32
#define ASTR 40
#define BSTR 136

// decode smem (halves)
#define A_OFF 0
#define B_OFF 20480
#define SMEM_DEC_BYTES ((B_OFF + 2 * DBK * BSTR) * 2)   // 58368

// encode smem (halves)
#define EAH_OFF 0
#define EAL_OFF 20480
#define EBH_OFF 40960
#define EBL_OFF 49664
#define SMEM_ENC_BYTES ((EBL_OFF + 2 * DBK * BSTR) * 2) // 116736

__device__ __half g_wd16[(size_t)NL * NL * FL * DM];
__device__ __half g_ah[(size_t)T_TOK * NL * FL];
__device__ __half g_xh[(size_t)T_TOK * NL * DM];
__device__ __half g_xl[(size_t)T_TOK * NL * DM];
__device__ __half g_weh[(size_t)NL * DM * FL];
__device__ __half g_wel[(size_t)NL * DM * FL];
__device__ float  g_acts_scratch[(size_t)T_TOK * NL * FL];

__constant__ unsigned char c_tri_i[78];
__constant__ unsigned char c_tri_j[78];

// ---------------- helpers ----------------
__device__ __forceinline__ uint32_t smem_u32(const void* p) {
    return (uint32_t)__cvta_generic_to_shared(p);
}
__device__ __forceinline__ void cp16(uint32_t d, const void* s) {
    asm volatile("cp.async.cg.shared.global [%0], [%1], 16;" :: "r"(d), "l"(s));
}
__device__ __forceinline__ void ldsm_x4(uint32_t* r, uint32_t a) {
    asm volatile("ldmatrix.sync.aligned.m8n8.x4.shared.b16 {%0,%1,%2,%3}, [%4];"
                 : "=r"(r[0]), "=r"(r[1]), "=r"(r[2]), "=r"(r[3]) : "r"(a));
}
__device__ __forceinline__ void ldsm_x4t(uint32_t* r, uint32_t a) {
    asm volatile("ldmatrix.sync.aligned.m8n8.x4.trans.shared.b16 {%0,%1,%2,%3}, [%4];"
                 : "=r"(r[0]), "=r"(r[1]), "=r"(r[2]), "=r"(r[3]) : "r"(a));
}
__device__ __forceinline__ void mma_f16(float* d, const uint32_t* a, const uint32_t* b) {
    asm volatile(
        "mma.sync.aligned.m16n8k16.row.col.f32.f16.f16.f32 "
        "{%0,%1,%2,%3}, {%4,%5,%6,%7}, {%8,%9}, {%0,%1,%2,%3};"
        : "+f"(d[0]), "+f"(d[1]), "+f"(d[2]), "+f"(d[3])
        : "r"(a[0]), "r"(a[1]), "r"(a[2]), "r"(a[3]), "r"(b[0]), "r"(b[1]));
}

struct alignas(16) H8 { __half v[8]; };

// ---------------- prep: split x and w_e into fp16 hi/lo ----------------
__global__ __launch_bounds__(256)
void split_f32(const float* __restrict__ src, __half* __restrict__ hi,
               __half* __restrict__ lo) {
    const size_t idx = ((size_t)blockIdx.x * 256 + threadIdx.x) * 4;
    float4 v = *(const float4*)(src + idx);
    __half h0 = __float2half_rn(v.x), h1 = __float2half_rn(v.y);
    __half h2 = __float2half_rn(v.z), h3 = __float2half_rn(v.w);
    __half l0 = __float2half_rn(v.x - __half2float(h0));
    __half l1 = __float2half_rn(v.y - __half2float(h1));
    __half l2 = __float2half_rn(v.z - __half2float(h2));
    __half l3 = __float2half_rn(v.w - __half2float(h3));
    __half hh[4] = {h0, h1, h2, h3};
    __half ll[4] = {l0, l1, l2, l3};
    *(uint2*)(hi + idx) = *(uint2*)hh;
    *(uint2*)(lo + idx) = *(uint2*)ll;
}

// ---------------- round w_d to fp16 (triangle pairs only) ----------------
__global__ __launch_bounds__(256)
void round_wd16(const float* __restrict__ wd, __half* __restrict__ o) {
    const int z = c_tri_i[blockIdx.z] * NL + c_tri_j[blockIdx.z];
    const size_t idx = (size_t)z * FL * DM +
                       ((size_t)blockIdx.x * 256 + threadIdx.x) * 4;
    float4 v = *(const float4*)(wd + idx);
    __half h4[4] = {__float2half_rn(v.x), __float2half_rn(v.y),
                    __float2half_rn(v.z), __float2half_rn(v.w)};
    *(uint2*)(o + idx) = *(uint2*)h4;
}

// ---------------- encode via mma.sync fp16, 3-product split ----------------
__global__ __launch_bounds__(256, 1)
void encode_mma(const __half* __restrict__ XHp, const __half* __restrict__ XLp,
                const __half* __restrict__ WHp, const __half* __restrict__ WLp,
                const float* __restrict__ TH, float* __restrict__ H,
                float* __restrict__ A, __half* __restrict__ AH16) {
    extern __shared__ __half sm[];
    const uint32_t sb = smem_u32(sm);

    const int l  = blockIdx.z;
    const int bm = blockIdx.y * DBM;
    const int bn = blockIdx.x * DBN;
    const int KT = DM / DBK;   // 24

    const int tid  = threadIdx.x;
    const int lane = tid & 31, wid = tid >> 5;
    const int wm = wid & 3, wn = wid >> 2;
    const int r = lane >> 2, c = lane & 3;
    const int lr = lane & 15, lc = lane >> 4;

    const __half* gxh = XHp + ((size_t)(bm + tid) * NL + l) * DM;
    const __half* gxl = XLp + ((size_t)(bm + tid) * NL + l) * DM;
    const __half* gwh = WHp + (size_t)l * DM * FL;
    const __half* gwl = WLp + (size_t)l * DM * FL;

    const uint32_t a_row_off = (uint32_t)tid * ASTR;
    const int brow = tid >> 3, bq = (tid & 7) * 16;
    const uint32_t b_row_off = (uint32_t)brow * BSTR + bq;

    float acc[4][8][4];
#pragma unroll
    for (int mt = 0; mt < 4; mt++)
#pragma unroll
        for (int nt = 0; nt < 8; nt++)
#pragma unroll
            for (int q = 0; q < 4; q++) acc[mt][nt][q] = 0.0f;

    {   // prefetch ktile 0 -> stage 0
#pragma unroll
        for (int q = 0; q < 4; q++) {
            cp16(sb + 2 * (EAH_OFF + a_row_off + q * 8), gxh + q * 8);
            cp16(sb + 2 * (EAL_OFF + a_row_off + q * 8), gxl + q * 8);
        }
        const __half* wb = gwh + (size_t)brow * FL + bn + bq;
        const __half* wc = gwl + (size_t)brow * FL + bn + bq;
        cp16(sb + 2 * (EBH_OFF + b_row_off),     wb);
        cp16(sb + 2 * (EBH_OFF + b_row_off + 8), wb + 8);
        cp16(sb + 2 * (EBL_OFF + b_row_off),     wc);
        cp16(sb + 2 * (EBL_OFF + b_row_off + 8), wc + 8);
        asm volatile("cp.async.commit_group;");
    }

    int buf = 0;
    for (int kt = 0; kt < KT; kt++) {
        if (kt + 1 < KT) {
            const int kn = kt + 1;
            const int st = buf ^ 1;
            const uint32_t ao = a_row_off + (uint32_t)st * (DBM * ASTR);
#pragma unroll
            for (int q = 0; q < 4; q++) {
                cp16(sb + 2 * (EAH_OFF + ao + q * 8), gxh + kn * DBK + q * 8);
                cp16(sb + 2 * (EAL_OFF + ao + q * 8), gxl + kn * DBK + q * 8);
            }
            const __half* wb = gwh + (size_t)(kn * DBK + brow) * FL + bn + bq;
            const __half* wc = gwl + (size_t)(kn * DBK + brow) * FL + bn + bq;
            const uint32_t bo = b_row_off + (uint32_t)st * (DBK * BSTR);
            cp16(sb + 2 * (EBH_OFF + bo),     wb);
            cp16(sb + 2 * (EBH_OFF + bo + 8), wb + 8);
            cp16(sb + 2 * (EBL_OFF + bo),     wc);
            cp16(sb + 2 * (EBL_OFF + bo + 8), wc + 8);
            asm volatile("cp.async.commit_group;");
            asm volatile("cp.async.wait_group 1;");
        } else {
            asm volatile("cp.async.wait_group 0;");
        }
        __syncthreads();

        const uint32_t ah_b = sb + 2 * (EAH_OFF + (uint32_t)buf * (DBM * ASTR));
        const uint32_t al_b = sb + 2 * (EAL_OFF + (uint32_t)buf * (DBM * ASTR));
        const uint32_t bh_b = sb + 2 * (EBH_OFF + (uint32_t)buf * (DBK * BSTR));
        const uint32_t bl_b = sb + 2 * (EBL_OFF + (uint32_t)buf * (DBK * BSTR));

#pragma unroll
        for (int s = 0; s < 2; s++) {
            uint32_t ah[4][4], fb[4][4];
            const uint32_t aoff = 2 * (uint32_t)((wm * 64 + lr) * ASTR + s * 16 + 8 * lc);
            const uint32_t boff = 2 * (uint32_t)((s * 16 + lr) * BSTR + wn * 64 + 8 * lc);
#pragma unroll
            for (int mt = 0; mt < 4; mt++)
                ldsm_x4(ah[mt], ah_b + aoff + 2 * (uint32_t)(mt * 16 * ASTR));
#pragma unroll
            for (int g = 0; g < 4; g++)
                ldsm_x4t(fb[g], bh_b + boff + 2 * (uint32_t)(g * 16));
            // xh * wh
#pragma unroll
            for (int mt = 0; mt < 4; mt++)
#pragma unroll
                for (int g = 0; g < 4; g++) {
                    mma_f16(acc[mt][2 * g],     ah[mt], &fb[g][0]);
                    mma_f16(acc[mt][2 * g + 1], ah[mt], &fb[g][2]);
                }
            // xl * wh (reuse fb)
            {
                uint32_t al[4][4];
#pragma unroll
                for (int mt = 0; mt < 4; mt++)
                    ldsm_x4(al[mt], al_b + aoff + 2 * (uint32_t)(mt * 16 * ASTR));
#pragma unroll
                for (int mt = 0; mt < 4; mt++)
#pragma unroll
                    for (int g = 0; g < 4; g++) {
                        mma_f16(acc[mt][2 * g],     al[mt], &fb[g][0]);
                        mma_f16(acc[mt][2 * g + 1], al[mt], &fb[g][2]);
                    }
            }
            // xh * wl (reuse ah, reload fb)
#pragma unroll
            for (int g = 0; g < 4; g++)
                ldsm_x4t(fb[g], bl_b + boff + 2 * (uint32_t)(g * 16));
#pragma unroll
            for (int mt = 0; mt < 4; mt++)
#pragma unroll
                for (int g = 0; g < 4; g++) {
                    mma_f16(acc[mt][2 * g],     ah[mt], &fb[g][0]);
                    mma_f16(acc[mt][2 * g + 1], ah[mt], &fb[g][2]);
                }
        }
        __syncthreads();
        buf ^= 1;
    }

    // epilogue: JumpReLU, write h / acts / acts-fp16
    float thr0[8], thr1[8];
#pragma unroll
    for (int nt = 0; nt < 8; nt++) {
        const int col = bn + wn * 64 + nt * 8 + 2 * c;
        thr0[nt] = expf(TH[l * FL + col]);
        thr1[nt] = expf(TH[l * FL + col + 1]);
    }
#pragma unroll
    for (int mt = 0; mt < 4; mt++) {
        const int row = bm + wm * 64 + mt * 16 + r;
#pragma unroll
        for (int nt = 0; nt < 8; nt++) {
            const int col = bn + wn * 64 + nt * 8 + 2 * c;
            const size_t b0 = (size_t)row * (NL * FL) + (size_t)l * FL + col;
            const size_t b1 = b0 + (size_t)8 * (NL * FL);
            const float h0 = acc[mt][nt][0], h1 = acc[mt][nt][1];
            const float h2 = acc[mt][nt][2], h3 = acc[mt][nt][3];
            if (H) {
                *(float2*)(H + b0) = make_float2(h0, h1);
                *(float2*)(H + b1) = make_float2(h2, h3);
            }
            const float a0 = (h0 > thr0[nt]) ? h0 : 0.0f;
            const float a1 = (h1 > thr1[nt]) ? h1 : 0.0f;
            const float a2 = (h2 > thr0[nt]) ? h2 : 0.0f;
            const float a3 = (h3 > thr1[nt]) ? h3 : 0.0f;
            *(float2*)(A + b0) = make_float2(a0, a1);
            *(float2*)(A + b1) = make_float2(a2, a3);
            *(__half2*)(AH16 + b0) = __floats2half2_rn(a0, a1);
            *(__half2*)(AH16 + b1) = __floats2half2_rn(a2, a3);
        }
    }
}

// ---------------- decode via mma.sync fp16 (single product) ----------------
__global__ __launch_bounds__(256, 1)
void decode_fp16(const __half* __restrict__ AH, const __half* __restrict__ WD,
                 float* __restrict__ XH) {
    extern __shared__ __half sm[];
    const uint32_t sb = smem_u32(sm);

    const int j  = (NL - 1) - blockIdx.z;
    const int bm = blockIdx.y * DBM;
    const int bn = blockIdx.x * DBN;
    const int KT = (j + 1) * (FL / DBK);

    const int tid  = threadIdx.x;
    const int lane = tid & 31, wid = tid >> 5;
    const int wm = wid & 3, wn = wid >> 2;
    const int r = lane >> 2, c = lane & 3;
    const int lr = lane & 15, lc = lane >> 4;

    const __half* gah = AH + (size_t)(bm + tid) * (NL * FL);
    const __half* wj  = WD + (size_t)j * FL * DM;
    const size_t wd_istride = (size_t)NL * FL * DM;

    const uint32_t a_row_off = (uint32_t)tid * ASTR;
    const int brow = tid >> 3, bq = (tid & 7) * 16;
    const uint32_t b_row_off = (uint32_t)brow * BSTR + bq;

    float acc[4][8][4];
#pragma unroll
    for (int mt = 0; mt < 4; mt++)
#pragma unroll
        for (int nt = 0; nt < 8; nt++)
#pragma unroll
            for (int q = 0; q < 4; q++) acc[mt][nt][q] = 0.0f;

    {
#pragma unroll
        for (int q = 0; q < 4; q++)
            cp16(sb + 2 * (A_OFF + a_row_off + q * 8), gah + q * 8);
        const __half* sbp = wj + (size_t)brow * DM + bn + bq;
        cp16(sb + 2 * (B_OFF + b_row_off),     sbp);
        cp16(sb + 2 * (B_OFF + b_row_off + 8), sbp + 8);
        asm volatile("cp.async.commit_group;");
    }

    int buf = 0;
    for (int kt = 0; kt < KT; kt++) {
        if (kt + 1 < KT) {
            const int kn = kt + 1;
            const int st = buf ^ 1;
            const uint32_t ao = a_row_off + (uint32_t)st * (DBM * ASTR);
#pragma unroll
            for (int q = 0; q < 4; q++)
                cp16(sb + 2 * (A_OFF + ao + q * 8), gah + kn * DBK + q * 8);
            const int ii = kn >> 6, f0 = (kn & 63) * DBK;
            const __half* sbp = wj + (size_t)ii * wd_istride +
                                (size_t)(f0 + brow) * DM + bn + bq;
            const uint32_t bo = B_OFF + b_row_off + (uint32_t)st * (DBK * BSTR);
            cp16(sb + 2 * bo, sbp);
            cp16(sb + 2 * (bo + 8), sbp + 8);
            asm volatile("cp.async.commit_group;");
            asm volatile("cp.async.wait_group 1;");
        } else {
            asm volatile("cp.async.wait_group 0;");
        }
        __syncthreads();

        const uint32_t a_b = sb + 2 * (A_OFF + (uint32_t)buf * (DBM * ASTR));
        const uint32_t b_b = sb + 2 * (B_OFF + (uint32_t)buf * (DBK * BSTR));

#pragma unroll
        for (int s = 0; s < 2; s++) {
            uint32_t a[4][4], bb[4][4];
#pragma unroll
            for (int mt = 0; mt < 4; mt++) {
                const uint32_t ao =
                    2 * ((uint32_t)(wm * 64 + mt * 16 + lr) * ASTR + s * 16 + 8 * lc);
                ldsm_x4(a[mt], a_b + ao);
            }
#pragma unroll
            for (int g = 0; g < 4; g++) {
                const uint32_t bo =
                    2 * ((uint32_t)(s * 16 + lr) * BSTR + wn * 64 + g * 16 + 8 * lc);
                ldsm_x4t(bb[g], b_b + bo);
            }
#pragma unroll
            for (int mt = 0; mt < 4; mt++)
#pragma unroll
                for (int g = 0; g < 4; g++) {
                    mma_f16(acc[mt][2 * g],     a[mt], &bb[g][0]);
                    mma_f16(acc[mt][2 * g + 1], a[mt], &bb[g][2]);
                }
        }
        __syncthreads();
        buf ^= 1;
    }

#pragma unroll
    for (int mt = 0; mt < 4; mt++) {
        const int row = bm + wm * 64 + mt * 16 + r;
#pragma unroll
        for (int nt = 0; nt < 8; nt++) {
            const int col = bn + wn * 64 + nt * 8 + 2 * c;
            float* p = XH + (size_t)row * (NL * DM) + (size_t)j * DM + col;
            *(float2*)p = make_float2(acc[mt][nt][0], acc[mt][nt][1]);
            *(float2*)(p + (size_t)8 * (NL * DM)) =
                make_float2(acc[mt][nt][2], acc[mt][nt][3]);
        }
    }
}

// ---------------- host ----------------
extern "C" void kernel_launch(void* const* d_in, const int* in_sizes, int n_in,
                              void* d_out, int out_size) {
    const float* x  = (const float*)d_in[0];
    const float* we = (const float*)d_in[1];
    const float* wd = (const float*)d_in[2];
    const float* th = (const float*)d_in[3];
    float* out = (float*)d_out;

    const long long HE = (long long)T_TOK * NL * FL;
    const long long XE = (long long)T_TOK * NL * DM;

    float *hp, *ap, *xp;
    if ((long long)out_size >= 2 * HE + XE) {
        hp = out; ap = out + HE; xp = out + 2 * HE;
    } else {
        hp = nullptr;
        float* sp = nullptr;
        cudaGetSymbolAddress((void**)&sp, g_acts_scratch);
        ap = sp; xp = out;
    }

    __half *wd16, *ah, *xh, *xl, *weh, *wel;
    cudaGetSymbolAddress((void**)&wd16, g_wd16);
    cudaGetSymbolAddress((void**)&ah, g_ah);
    cudaGetSymbolAddress((void**)&xh, g_xh);
    cudaGetSymbolAddress((void**)&xl, g_xl);
    cudaGetSymbolAddress((void**)&weh, g_weh);
    cudaGetSymbolAddress((void**)&wel, g_wel);

    static bool init_done = false;
    if (!init_done) {
        unsigned char ti[78], tj[78];
        int n = 0;
        for (int i = 0; i < NL; i++)
            for (int j = i; j < NL; j++) { ti[n] = (unsigned char)i; tj[n] = (unsigned char)j; n++; }
        cudaMemcpyToSymbol(c_tri_i, ti, 78);
        cudaMemcpyToSymbol(c_tri_j, tj, 78);
        cudaFuncSetAttribute(decode_fp16, cudaFuncAttributeMaxDynamicSharedMemorySize,
                             SMEM_DEC_BYTES);
        cudaFuncSetAttribute(encode_mma, cudaFuncAttributeMaxDynamicSharedMemorySize,
                             SMEM_ENC_BYTES);
        init_done = true;
    }
    cudaFuncSetAttribute(decode_fp16, cudaFuncAttributeMaxDynamicSharedMemorySize,
                         SMEM_DEC_BYTES);
    cudaFuncSetAttribute(encode_mma, cudaFuncAttributeMaxDynamicSharedMemorySize,
                         SMEM_ENC_BYTES);

    const int XN = T_TOK * NL * DM;   // 18,874,368
    const int WN = NL * DM * FL;      // 18,874,368

    split_f32<<<XN / 1024, 256>>>(x, xh, xl);
    split_f32<<<WN / 1024, 256>>>(we, weh, wel);
    round_wd16<<<dim3(FL * DM / 1024, 1, 78), 256>>>(wd, wd16);
    encode_mma<<<dim3(FL / DBN, T_TOK / DBM, NL), 256, SMEM_ENC_BYTES>>>(
        xh, xl, weh, wel, th, hp, ap, ah);
    decode_fp16<<<dim3(DM / DBN, T_TOK / DBM, NL), 256, SMEM_DEC_BYTES>>>(ah, wd16, xp);
}

// round 8
// speedup vs baseline: 3.8067x; 1.0349x over previous
#include <cuda_runtime.h>
#include <cuda_fp16.h>
#include <math.h>
#include <stdint.h>

#define T_TOK 2048
#define NL    12
#define DM    768
#define FL    2048

// tile geometry (both mma kernels): CTA 256x128x32, 8 warps (4m x 2n), warp 64x64
#define DBM 256
#define DBN 128
#define DBK 32
#define ASTR 40
#define BSTR 136
#define SA (DBM * ASTR)   // 10240 halves per A stage
#define SB (DBK * BSTR)   // 4352 halves per B stage

// decode smem (halves): A stages [0,3*SA), B stages [3*SA, 3*SA+3*SB)
#define DEC_B_BASE (3 * SA)
#define SMEM_DEC_BYTES ((3 * SA + 3 * SB) * 2)          // 87552

// encode smem (halves): XH, XL (3*SA each), WH, WL (3*SB each)
#define EXH_BASE 0
#define EXL_BASE (3 * SA)
#define EWH_BASE (6 * SA)
#define EWL_BASE (6 * SA + 3 * SB)
#define SMEM_ENC_BYTES ((6 * SA + 6 * SB) * 2)          // 175104

__device__ __half g_wd16[(size_t)NL * NL * FL * DM];
__device__ __half g_ah[(size_t)T_TOK * NL * FL];
__device__ __half g_xh[(size_t)T_TOK * NL * DM];
__device__ __half g_xl[(size_t)T_TOK * NL * DM];
__device__ __half g_weh[(size_t)NL * DM * FL];
__device__ __half g_wel[(size_t)NL * DM * FL];
__device__ float  g_acts_scratch[(size_t)T_TOK * NL * FL];

// ---------------- helpers ----------------
__device__ __forceinline__ uint32_t smem_u32(const void* p) {
    return (uint32_t)__cvta_generic_to_shared(p);
}
__device__ __forceinline__ void cp16(uint32_t d, const void* s) {
    asm volatile("cp.async.cg.shared.global [%0], [%1], 16;" :: "r"(d), "l"(s));
}
__device__ __forceinline__ void ldsm_x4(uint32_t* r, uint32_t a) {
    asm volatile("ldmatrix.sync.aligned.m8n8.x4.shared.b16 {%0,%1,%2,%3}, [%4];"
                 : "=r"(r[0]), "=r"(r[1]), "=r"(r[2]), "=r"(r[3]) : "r"(a));
}
__device__ __forceinline__ void ldsm_x4t(uint32_t* r, uint32_t a) {
    asm volatile("ldmatrix.sync.aligned.m8n8.x4.trans.shared.b16 {%0,%1,%2,%3}, [%4];"
                 : "=r"(r[0]), "=r"(r[1]), "=r"(r[2]), "=r"(r[3]) : "r"(a));
}
__device__ __forceinline__ void mma_f16(float* d, const uint32_t* a, const uint32_t* b) {
    asm volatile(
        "mma.sync.aligned.m16n8k16.row.col.f32.f16.f16.f32 "
        "{%0,%1,%2,%3}, {%4,%5,%6,%7}, {%8,%9}, {%0,%1,%2,%3};"
        : "+f"(d[0]), "+f"(d[1]), "+f"(d[2]), "+f"(d[3])
        : "r"(a[0]), "r"(a[1]), "r"(a[2]), "r"(a[3]), "r"(b[0]), "r"(b[1]));
}

// ---------------- fused prep: wd->fp16 (triangle), split x, split w_e ----------
#define NB_WD (78 * (FL * DM / 1024))    // 119808
#define NB_X  (T_TOK * NL * DM / 1024)   // 18432
#define NB_PREP (NB_WD + 2 * NB_X)

__global__ __launch_bounds__(256)
void prep_all(const float* __restrict__ x, const float* __restrict__ we,
              const float* __restrict__ wd,
              __half* __restrict__ xh, __half* __restrict__ xl,
              __half* __restrict__ weh, __half* __restrict__ wel,
              __half* __restrict__ wd16) {
    const int b = blockIdx.x;
    if (b < NB_WD) {
        const int p = b / (FL * DM / 1024), xb = b % (FL * DM / 1024);
        int i = 0, rem = p;
        while (rem >= NL - i) { rem -= NL - i; i++; }
        const int z = i * NL + (i + rem);
        const size_t idx = (size_t)z * FL * DM + ((size_t)xb * 256 + threadIdx.x) * 4;
        float4 v = *(const float4*)(wd + idx);
        __half h4[4] = {__float2half_rn(v.x), __float2half_rn(v.y),
                        __float2half_rn(v.z), __float2half_rn(v.w)};
        *(uint2*)(wd16 + idx) = *(uint2*)h4;
    } else {
        const int bb = b - NB_WD;
        const bool is_x = bb < NB_X;
        const float* src = is_x ? x : we;
        __half* hi = is_x ? xh : weh;
        __half* lo = is_x ? xl : wel;
        const size_t idx = ((size_t)(is_x ? bb : bb - NB_X) * 256 + threadIdx.x) * 4;
        float4 v = *(const float4*)(src + idx);
        __half h4[4] = {__float2half_rn(v.x), __float2half_rn(v.y),
                        __float2half_rn(v.z), __float2half_rn(v.w)};
        __half l4[4] = {__float2half_rn(v.x - __half2float(h4[0])),
                        __float2half_rn(v.y - __half2float(h4[1])),
                        __float2half_rn(v.z - __half2float(h4[2])),
                        __float2half_rn(v.w - __half2float(h4[3]))};
        *(uint2*)(hi + idx) = *(uint2*)h4;
        *(uint2*)(lo + idx) = *(uint2*)l4;
    }
}

// ---------------- encode via mma.sync fp16, 3-product split, 3-stage pipe ----
__global__ __launch_bounds__(256, 1)
void encode_mma(const __half* __restrict__ XHp, const __half* __restrict__ XLp,
                const __half* __restrict__ WHp, const __half* __restrict__ WLp,
                const float* __restrict__ TH, float* __restrict__ H,
                float* __restrict__ A, __half* __restrict__ AH16) {
    extern __shared__ __half sm[];
    const uint32_t sb = smem_u32(sm);

    const int l  = blockIdx.z;
    const int bm = blockIdx.y * DBM;
    const int bn = blockIdx.x * DBN;
    const int KT = DM / DBK;   // 24

    const int tid  = threadIdx.x;
    const int lane = tid & 31, wid = tid >> 5;
    const int wm = wid & 3, wn = wid >> 2;
    const int r = lane >> 2, c = lane & 3;
    const int lr = lane & 15, lc = lane >> 4;

    const __half* gxh = XHp + ((size_t)(bm + tid) * NL + l) * DM;
    const __half* gxl = XLp + ((size_t)(bm + tid) * NL + l) * DM;
    const __half* gwh = WHp + (size_t)l * DM * FL;
    const __half* gwl = WLp + (size_t)l * DM * FL;

    const uint32_t a_row_off = (uint32_t)tid * ASTR;
    const int brow = tid >> 3, bq = (tid & 7) * 16;
    const uint32_t b_row_off = (uint32_t)brow * BSTR + bq;

    float acc[4][8][4];
#pragma unroll
    for (int mt = 0; mt < 4; mt++)
#pragma unroll
        for (int nt = 0; nt < 8; nt++)
#pragma unroll
            for (int q = 0; q < 4; q++) acc[mt][nt][q] = 0.0f;

    // issue helper (macro to keep addressing in registers)
#define ENC_ISSUE(KN, ST)                                                        \
    do {                                                                         \
        const uint32_t ao = a_row_off + (uint32_t)(ST) * SA;                     \
        _Pragma("unroll")                                                        \
        for (int q = 0; q < 4; q++) {                                            \
            cp16(sb + 2 * (EXH_BASE + ao + q * 8), gxh + (KN) * DBK + q * 8);    \
            cp16(sb + 2 * (EXL_BASE + ao + q * 8), gxl + (KN) * DBK + q * 8);    \
        }                                                                        \
        const __half* wb = gwh + (size_t)((KN) * DBK + brow) * FL + bn + bq;     \
        const __half* wc = gwl + (size_t)((KN) * DBK + brow) * FL + bn + bq;     \
        const uint32_t bo = b_row_off + (uint32_t)(ST) * SB;                     \
        cp16(sb + 2 * (EWH_BASE + bo),     wb);                                  \
        cp16(sb + 2 * (EWH_BASE + bo + 8), wb + 8);                              \
        cp16(sb + 2 * (EWL_BASE + bo),     wc);                                  \
        cp16(sb + 2 * (EWL_BASE + bo + 8), wc + 8);                              \
        asm volatile("cp.async.commit_group;");                                  \
    } while (0)

    ENC_ISSUE(0, 0);
    ENC_ISSUE(1, 1);

    for (int kt = 0; kt < KT; kt++) {
        if (kt + 1 < KT) asm volatile("cp.async.wait_group 1;");
        else             asm volatile("cp.async.wait_group 0;");
        __syncthreads();
        if (kt + 2 < KT) {
            const int kn = kt + 2;
            ENC_ISSUE(kn, kn % 3);
        }
        const int st = kt % 3;
        const uint32_t ah_b = sb + 2 * (EXH_BASE + (uint32_t)st * SA);
        const uint32_t al_b = sb + 2 * (EXL_BASE + (uint32_t)st * SA);
        const uint32_t bh_b = sb + 2 * (EWH_BASE + (uint32_t)st * SB);
        const uint32_t bl_b = sb + 2 * (EWL_BASE + (uint32_t)st * SB);

#pragma unroll
        for (int s = 0; s < 2; s++) {
            uint32_t ah[4][4], fb[4][4];
            const uint32_t aoff = 2 * (uint32_t)((wm * 64 + lr) * ASTR + s * 16 + 8 * lc);
            const uint32_t boff = 2 * (uint32_t)((s * 16 + lr) * BSTR + wn * 64 + 8 * lc);
#pragma unroll
            for (int mt = 0; mt < 4; mt++)
                ldsm_x4(ah[mt], ah_b + aoff + 2 * (uint32_t)(mt * 16 * ASTR));
#pragma unroll
            for (int g = 0; g < 4; g++)
                ldsm_x4t(fb[g], bh_b + boff + 2 * (uint32_t)(g * 16));
#pragma unroll
            for (int mt = 0; mt < 4; mt++)
#pragma unroll
                for (int g = 0; g < 4; g++) {
                    mma_f16(acc[mt][2 * g],     ah[mt], &fb[g][0]);
                    mma_f16(acc[mt][2 * g + 1], ah[mt], &fb[g][2]);
                }
            {
                uint32_t al[4][4];
#pragma unroll
                for (int mt = 0; mt < 4; mt++)
                    ldsm_x4(al[mt], al_b + aoff + 2 * (uint32_t)(mt * 16 * ASTR));
#pragma unroll
                for (int mt = 0; mt < 4; mt++)
#pragma unroll
                    for (int g = 0; g < 4; g++) {
                        mma_f16(acc[mt][2 * g],     al[mt], &fb[g][0]);
                        mma_f16(acc[mt][2 * g + 1], al[mt], &fb[g][2]);
                    }
            }
#pragma unroll
            for (int g = 0; g < 4; g++)
                ldsm_x4t(fb[g], bl_b + boff + 2 * (uint32_t)(g * 16));
#pragma unroll
            for (int mt = 0; mt < 4; mt++)
#pragma unroll
                for (int g = 0; g < 4; g++) {
                    mma_f16(acc[mt][2 * g],     ah[mt], &fb[g][0]);
                    mma_f16(acc[mt][2 * g + 1], ah[mt], &fb[g][2]);
                }
        }
    }
#undef ENC_ISSUE

    float thr0[8], thr1[8];
#pragma unroll
    for (int nt = 0; nt < 8; nt++) {
        const int col = bn + wn * 64 + nt * 8 + 2 * c;
        thr0[nt] = expf(TH[l * FL + col]);
        thr1[nt] = expf(TH[l * FL + col + 1]);
    }
#pragma unroll
    for (int mt = 0; mt < 4; mt++) {
        const int row = bm + wm * 64 + mt * 16 + r;
#pragma unroll
        for (int nt = 0; nt < 8; nt++) {
            const int col = bn + wn * 64 + nt * 8 + 2 * c;
            const size_t b0 = (size_t)row * (NL * FL) + (size_t)l * FL + col;
            const size_t b1 = b0 + (size_t)8 * (NL * FL);
            const float h0 = acc[mt][nt][0], h1 = acc[mt][nt][1];
            const float h2 = acc[mt][nt][2], h3 = acc[mt][nt][3];
            if (H) {
                *(float2*)(H + b0) = make_float2(h0, h1);
                *(float2*)(H + b1) = make_float2(h2, h3);
            }
            const float a0 = (h0 > thr0[nt]) ? h0 : 0.0f;
            const float a1 = (h1 > thr1[nt]) ? h1 : 0.0f;
            const float a2 = (h2 > thr0[nt]) ? h2 : 0.0f;
            const float a3 = (h3 > thr1[nt]) ? h3 : 0.0f;
            *(float2*)(A + b0) = make_float2(a0, a1);
            *(float2*)(A + b1) = make_float2(a2, a3);
            *(__half2*)(AH16 + b0) = __floats2half2_rn(a0, a1);
            *(__half2*)(AH16 + b1) = __floats2half2_rn(a2, a3);
        }
    }
}

// ---------------- decode via mma.sync fp16, 3-stage pipe ----------------
__global__ __launch_bounds__(256, 1)
void decode_fp16(const __half* __restrict__ AH, const __half* __restrict__ WD,
                 float* __restrict__ XH) {
    extern __shared__ __half sm[];
    const uint32_t sb = smem_u32(sm);

    const int j  = (NL - 1) - blockIdx.z;
    const int bm = blockIdx.y * DBM;
    const int bn = blockIdx.x * DBN;
    const int KT = (j + 1) * (FL / DBK);

    const int tid  = threadIdx.x;
    const int lane = tid & 31, wid = tid >> 5;
    const int wm = wid & 3, wn = wid >> 2;
    const int r = lane >> 2, c = lane & 3;
    const int lr = lane & 15, lc = lane >> 4;

    const __half* gah = AH + (size_t)(bm + tid) * (NL * FL);
    const __half* wj  = WD + (size_t)j * FL * DM;
    const size_t wd_istride = (size_t)NL * FL * DM;

    const uint32_t a_row_off = (uint32_t)tid * ASTR;
    const int brow = tid >> 3, bq = (tid & 7) * 16;
    const uint32_t b_row_off = (uint32_t)brow * BSTR + bq;

    float acc[4][8][4];
#pragma unroll
    for (int mt = 0; mt < 4; mt++)
#pragma unroll
        for (int nt = 0; nt < 8; nt++)
#pragma unroll
            for (int q = 0; q < 4; q++) acc[mt][nt][q] = 0.0f;

#define DEC_ISSUE(KN, ST)                                                       \
    do {                                                                        \
        const uint32_t ao = a_row_off + (uint32_t)(ST) * SA;                    \
        _Pragma("unroll")                                                       \
        for (int q = 0; q < 4; q++)                                             \
            cp16(sb + 2 * (ao + q * 8), gah + (KN) * DBK + q * 8);              \
        const int ii = (KN) >> 6, f0 = ((KN) & 63) * DBK;                       \
        const __half* sbp = wj + (size_t)ii * wd_istride +                      \
                            (size_t)(f0 + brow) * DM + bn + bq;                 \
        const uint32_t bo = DEC_B_BASE + b_row_off + (uint32_t)(ST) * SB;       \
        cp16(sb + 2 * bo, sbp);                                                 \
        cp16(sb + 2 * (bo + 8), sbp + 8);                                       \
        asm volatile("cp.async.commit_group;");                                 \
    } while (0)

    DEC_ISSUE(0, 0);
    DEC_ISSUE(1, 1);

    for (int kt = 0; kt < KT; kt++) {
        if (kt + 1 < KT) asm volatile("cp.async.wait_group 1;");
        else             asm volatile("cp.async.wait_group 0;");
        __syncthreads();
        if (kt + 2 < KT) {
            const int kn = kt + 2;
            DEC_ISSUE(kn, kn % 3);
        }
        const int st = kt % 3;
        const uint32_t a_b = sb + 2 * ((uint32_t)st * SA);
        const uint32_t b_b = sb + 2 * (DEC_B_BASE + (uint32_t)st * SB);

#pragma unroll
        for (int s = 0; s < 2; s++) {
            uint32_t a[4][4], bb[4][4];
#pragma unroll
            for (int mt = 0; mt < 4; mt++) {
                const uint32_t ao =
                    2 * ((uint32_t)(wm * 64 + mt * 16 + lr) * ASTR + s * 16 + 8 * lc);
                ldsm_x4(a[mt], a_b + ao);
            }
#pragma unroll
            for (int g = 0; g < 4; g++) {
                const uint32_t bo =
                    2 * ((uint32_t)(s * 16 + lr) * BSTR + wn * 64 + g * 16 + 8 * lc);
                ldsm_x4t(bb[g], b_b + bo);
            }
#pragma unroll
            for (int mt = 0; mt < 4; mt++)
#pragma unroll
                for (int g = 0; g < 4; g++) {
                    mma_f16(acc[mt][2 * g],     a[mt], &bb[g][0]);
                    mma_f16(acc[mt][2 * g + 1], a[mt], &bb[g][2]);
                }
        }
    }
#undef DEC_ISSUE

#pragma unroll
    for (int mt = 0; mt < 4; mt++) {
        const int row = bm + wm * 64 + mt * 16 + r;
#pragma unroll
        for (int nt = 0; nt < 8; nt++) {
            const int col = bn + wn * 64 + nt * 8 + 2 * c;
            float* p = XH + (size_t)row * (NL * DM) + (size_t)j * DM + col;
            *(float2*)p = make_float2(acc[mt][nt][0], acc[mt][nt][1]);
            *(float2*)(p + (size_t)8 * (NL * DM)) =
                make_float2(acc[mt][nt][2], acc[mt][nt][3]);
        }
    }
}

// ---------------- host ----------------
extern "C" void kernel_launch(void* const* d_in, const int* in_sizes, int n_in,
                              void* d_out, int out_size) {
    const float* x  = (const float*)d_in[0];
    const float* we = (const float*)d_in[1];
    const float* wd = (const float*)d_in[2];
    const float* th = (const float*)d_in[3];
    float* out = (float*)d_out;

    const long long HE = (long long)T_TOK * NL * FL;
    const long long XE = (long long)T_TOK * NL * DM;

    float *hp, *ap, *xp;
    if ((long long)out_size >= 2 * HE + XE) {
        hp = out; ap = out + HE; xp = out + 2 * HE;
    } else {
        hp = nullptr;
        float* sp = nullptr;
        cudaGetSymbolAddress((void**)&sp, g_acts_scratch);
        ap = sp; xp = out;
    }

    __half *wd16, *ah, *xh, *xl, *weh, *wel;
    cudaGetSymbolAddress((void**)&wd16, g_wd16);
    cudaGetSymbolAddress((void**)&ah, g_ah);
    cudaGetSymbolAddress((void**)&xh, g_xh);
    cudaGetSymbolAddress((void**)&xl, g_xl);
    cudaGetSymbolAddress((void**)&weh, g_weh);
    cudaGetSymbolAddress((void**)&wel, g_wel);

    cudaFuncSetAttribute(decode_fp16, cudaFuncAttributeMaxDynamicSharedMemorySize,
                         SMEM_DEC_BYTES);
    cudaFuncSetAttribute(encode_mma, cudaFuncAttributeMaxDynamicSharedMemorySize,
                         SMEM_ENC_BYTES);

    prep_all<<<NB_PREP, 256>>>(x, we, wd, xh, xl, weh, wel, wd16);
    encode_mma<<<dim3(FL / DBN, T_TOK / DBM, NL), 256, SMEM_ENC_BYTES>>>(
        xh, xl, weh, wel, th, hp, ap, ah);
    decode_fp16<<<dim3(DM / DBN, T_TOK / DBM, NL), 256, SMEM_DEC_BYTES>>>(ah, wd16, xp);
}

// round 9
// speedup vs baseline: 3.8415x; 1.0092x over previous
#include <cuda_runtime.h>
#include <cuda_fp16.h>
#include <math.h>
#include <stdint.h>

#define T_TOK 2048
#define NL    12
#define DM    768
#define FL    2048

// tile geometry (both mma kernels): CTA 256x128x32, 8 warps (4m x 2n), warp 64x64
#define DBM 256
#define DBN 128
#define DBK 32
#define ASTR 40
#define BSTR 136
#define SA (DBM * ASTR)   // 10240 halves per A stage
#define SB (DBK * BSTR)   // 4352 halves per B stage

// decode smem (halves)
#define DEC_B_BASE (3 * SA)
#define SMEM_DEC_BYTES ((3 * SA + 3 * SB) * 2)          // 87552

// encode smem (halves)
#define EXH_BASE 0
#define EXL_BASE (3 * SA)
#define EWH_BASE (6 * SA)
#define EWL_BASE (6 * SA + 3 * SB)
#define SMEM_ENC_BYTES ((6 * SA + 6 * SB) * 2)          // 175104

#define NWD 78                 // triangle pairs, fused into encode launch
#define ENC_BLOCKS (16 * 8 * NL)   // 1536

__device__ __half g_wd16[(size_t)NL * NL * FL * DM];
__device__ __half g_ah[(size_t)T_TOK * NL * FL];
__device__ __half g_xh[(size_t)T_TOK * NL * DM];
__device__ __half g_xl[(size_t)T_TOK * NL * DM];
__device__ __half g_weh[(size_t)NL * DM * FL];
__device__ __half g_wel[(size_t)NL * DM * FL];
__device__ float  g_acts_scratch[(size_t)T_TOK * NL * FL];

// ---------------- helpers ----------------
__device__ __forceinline__ uint32_t smem_u32(const void* p) {
    return (uint32_t)__cvta_generic_to_shared(p);
}
__device__ __forceinline__ void cp16(uint32_t d, const void* s) {
    asm volatile("cp.async.cg.shared.global [%0], [%1], 16;" :: "r"(d), "l"(s));
}
__device__ __forceinline__ void ldsm_x4(uint32_t* r, uint32_t a) {
    asm volatile("ldmatrix.sync.aligned.m8n8.x4.shared.b16 {%0,%1,%2,%3}, [%4];"
                 : "=r"(r[0]), "=r"(r[1]), "=r"(r[2]), "=r"(r[3]) : "r"(a));
}
__device__ __forceinline__ void ldsm_x4t(uint32_t* r, uint32_t a) {
    asm volatile("ldmatrix.sync.aligned.m8n8.x4.trans.shared.b16 {%0,%1,%2,%3}, [%4];"
                 : "=r"(r[0]), "=r"(r[1]), "=r"(r[2]), "=r"(r[3]) : "r"(a));
}
__device__ __forceinline__ void mma_f16(float* d, const uint32_t* a, const uint32_t* b) {
    asm volatile(
        "mma.sync.aligned.m16n8k16.row.col.f32.f16.f16.f32 "
        "{%0,%1,%2,%3}, {%4,%5,%6,%7}, {%8,%9}, {%0,%1,%2,%3};"
        : "+f"(d[0]), "+f"(d[1]), "+f"(d[2]), "+f"(d[3])
        : "r"(a[0]), "r"(a[1]), "r"(a[2]), "r"(a[3]), "r"(b[0]), "r"(b[1]));
}
__device__ __forceinline__ void cvt4(__half* h4, float4 v) {
    h4[0] = __float2half_rn(v.x); h4[1] = __float2half_rn(v.y);
    h4[2] = __float2half_rn(v.z); h4[3] = __float2half_rn(v.w);
}

// ---------------- prep: split x and w_e into fp16 hi/lo ----------------
#define NB_X  (T_TOK * NL * DM / 1024)   // 18432

__global__ __launch_bounds__(256)
void prep_xwe(const float* __restrict__ x, const float* __restrict__ we,
              __half* __restrict__ xh, __half* __restrict__ xl,
              __half* __restrict__ weh, __half* __restrict__ wel) {
    const int b = blockIdx.x;
    const bool is_x = b < NB_X;
    const float* src = is_x ? x : we;
    __half* hi = is_x ? xh : weh;
    __half* lo = is_x ? xl : wel;
    const size_t idx = ((size_t)(is_x ? b : b - NB_X) * 256 + threadIdx.x) * 4;
    float4 v = *(const float4*)(src + idx);
    __half h4[4]; cvt4(h4, v);
    __half l4[4] = {__float2half_rn(v.x - __half2float(h4[0])),
                    __float2half_rn(v.y - __half2float(h4[1])),
                    __float2half_rn(v.z - __half2float(h4[2])),
                    __float2half_rn(v.w - __half2float(h4[3]))};
    *(uint2*)(hi + idx) = *(uint2*)h4;
    *(uint2*)(lo + idx) = *(uint2*)l4;
}

// ---------------- encode (3-product fp16 mma) + fused wd->fp16 convert -------
__global__ __launch_bounds__(256, 1)
void encode_fused(const __half* __restrict__ XHp, const __half* __restrict__ XLp,
                  const __half* __restrict__ WHp, const __half* __restrict__ WLp,
                  const float* __restrict__ TH, float* __restrict__ H,
                  float* __restrict__ A, __half* __restrict__ AH16,
                  const float* __restrict__ WDsrc, __half* __restrict__ WD16) {
    // ---- leading 78 CTAs: convert one wd[i][j] slab each ----
    if (blockIdx.x < NWD) {
        const int p = blockIdx.x;
        int i = 0, rem = p;
        while (rem >= NL - i) { rem -= NL - i; i++; }
        const size_t zoff = (size_t)(i * NL + i + rem) * FL * DM;
        const float4* src = (const float4*)(WDsrc + zoff);
        uint2* dst = (uint2*)(WD16 + zoff);
        const int N4 = FL * DM / 4;   // 393216; 384 iters of 1024
        for (int q = threadIdx.x; q < N4; q += 1024) {
            float4 v0 = src[q], v1 = src[q + 256], v2 = src[q + 512], v3 = src[q + 768];
            __half h0[4], h1[4], h2[4], h3[4];
            cvt4(h0, v0); cvt4(h1, v1); cvt4(h2, v2); cvt4(h3, v3);
            dst[q]       = *(uint2*)h0;
            dst[q + 256] = *(uint2*)h1;
            dst[q + 512] = *(uint2*)h2;
            dst[q + 768] = *(uint2*)h3;
        }
        return;
    }

    // ---- encode CTAs ----
    extern __shared__ __half sm[];
    const uint32_t sb = smem_u32(sm);

    const int bid = blockIdx.x - NWD;
    const int l  = bid >> 7;                 // /128
    const int bm = ((bid >> 4) & 7) * DBM;
    const int bn = (bid & 15) * DBN;
    const int KT = DM / DBK;   // 24

    const int tid  = threadIdx.x;
    const int lane = tid & 31, wid = tid >> 5;
    const int wm = wid & 3, wn = wid >> 2;
    const int r = lane >> 2, c = lane & 3;
    const int lr = lane & 15, lc = lane >> 4;

    const __half* gxh = XHp + ((size_t)(bm + tid) * NL + l) * DM;
    const __half* gxl = XLp + ((size_t)(bm + tid) * NL + l) * DM;
    const __half* gwh = WHp + (size_t)l * DM * FL;
    const __half* gwl = WLp + (size_t)l * DM * FL;

    const uint32_t a_row_off = (uint32_t)tid * ASTR;
    const int brow = tid >> 3, bq = (tid & 7) * 16;
    const uint32_t b_row_off = (uint32_t)brow * BSTR + bq;

    float acc[4][8][4];
#pragma unroll
    for (int mt = 0; mt < 4; mt++)
#pragma unroll
        for (int nt = 0; nt < 8; nt++)
#pragma unroll
            for (int q = 0; q < 4; q++) acc[mt][nt][q] = 0.0f;

#define ENC_ISSUE(KN, ST)                                                        \
    do {                                                                         \
        const uint32_t ao = a_row_off + (uint32_t)(ST) * SA;                     \
        _Pragma("unroll")                                                        \
        for (int q = 0; q < 4; q++) {                                            \
            cp16(sb + 2 * (EXH_BASE + ao + q * 8), gxh + (KN) * DBK + q * 8);    \
            cp16(sb + 2 * (EXL_BASE + ao + q * 8), gxl + (KN) * DBK + q * 8);    \
        }                                                                        \
        const __half* wb = gwh + (size_t)((KN) * DBK + brow) * FL + bn + bq;     \
        const __half* wc = gwl + (size_t)((KN) * DBK + brow) * FL + bn + bq;     \
        const uint32_t bo = b_row_off + (uint32_t)(ST) * SB;                     \
        cp16(sb + 2 * (EWH_BASE + bo),     wb);                                  \
        cp16(sb + 2 * (EWH_BASE + bo + 8), wb + 8);                              \
        cp16(sb + 2 * (EWL_BASE + bo),     wc);                                  \
        cp16(sb + 2 * (EWL_BASE + bo + 8), wc + 8);                              \
        asm volatile("cp.async.commit_group;");                                  \
    } while (0)

    ENC_ISSUE(0, 0);
    ENC_ISSUE(1, 1);

    for (int kt = 0; kt < KT; kt++) {
        if (kt + 1 < KT) asm volatile("cp.async.wait_group 1;");
        else             asm volatile("cp.async.wait_group 0;");
        __syncthreads();
        if (kt + 2 < KT) {
            const int kn = kt + 2;
            ENC_ISSUE(kn, kn % 3);
        }
        const int st = kt % 3;
        const uint32_t ah_b = sb + 2 * (EXH_BASE + (uint32_t)st * SA);
        const uint32_t al_b = sb + 2 * (EXL_BASE + (uint32_t)st * SA);
        const uint32_t bh_b = sb + 2 * (EWH_BASE + (uint32_t)st * SB);
        const uint32_t bl_b = sb + 2 * (EWL_BASE + (uint32_t)st * SB);

#pragma unroll
        for (int s = 0; s < 2; s++) {
            uint32_t ah[4][4], fb[4][4];
            const uint32_t aoff = 2 * (uint32_t)((wm * 64 + lr) * ASTR + s * 16 + 8 * lc);
            const uint32_t boff = 2 * (uint32_t)((s * 16 + lr) * BSTR + wn * 64 + 8 * lc);
#pragma unroll
            for (int mt = 0; mt < 4; mt++)
                ldsm_x4(ah[mt], ah_b + aoff + 2 * (uint32_t)(mt * 16 * ASTR));
#pragma unroll
            for (int g = 0; g < 4; g++)
                ldsm_x4t(fb[g], bh_b + boff + 2 * (uint32_t)(g * 16));
#pragma unroll
            for (int mt = 0; mt < 4; mt++)
#pragma unroll
                for (int g = 0; g < 4; g++) {
                    mma_f16(acc[mt][2 * g],     ah[mt], &fb[g][0]);
                    mma_f16(acc[mt][2 * g + 1], ah[mt], &fb[g][2]);
                }
            {
                uint32_t al[4][4];
#pragma unroll
                for (int mt = 0; mt < 4; mt++)
                    ldsm_x4(al[mt], al_b + aoff + 2 * (uint32_t)(mt * 16 * ASTR));
#pragma unroll
                for (int mt = 0; mt < 4; mt++)
#pragma unroll
                    for (int g = 0; g < 4; g++) {
                        mma_f16(acc[mt][2 * g],     al[mt], &fb[g][0]);
                        mma_f16(acc[mt][2 * g + 1], al[mt], &fb[g][2]);
                    }
            }
#pragma unroll
            for (int g = 0; g < 4; g++)
                ldsm_x4t(fb[g], bl_b + boff + 2 * (uint32_t)(g * 16));
#pragma unroll
            for (int mt = 0; mt < 4; mt++)
#pragma unroll
                for (int g = 0; g < 4; g++) {
                    mma_f16(acc[mt][2 * g],     ah[mt], &fb[g][0]);
                    mma_f16(acc[mt][2 * g + 1], ah[mt], &fb[g][2]);
                }
        }
    }
#undef ENC_ISSUE

    float thr0[8], thr1[8];
#pragma unroll
    for (int nt = 0; nt < 8; nt++) {
        const int col = bn + wn * 64 + nt * 8 + 2 * c;
        thr0[nt] = expf(TH[l * FL + col]);
        thr1[nt] = expf(TH[l * FL + col + 1]);
    }
#pragma unroll
    for (int mt = 0; mt < 4; mt++) {
        const int row = bm + wm * 64 + mt * 16 + r;
#pragma unroll
        for (int nt = 0; nt < 8; nt++) {
            const int col = bn + wn * 64 + nt * 8 + 2 * c;
            const size_t b0 = (size_t)row * (NL * FL) + (size_t)l * FL + col;
            const size_t b1 = b0 + (size_t)8 * (NL * FL);
            const float h0 = acc[mt][nt][0], h1 = acc[mt][nt][1];
            const float h2 = acc[mt][nt][2], h3 = acc[mt][nt][3];
            if (H) {
                *(float2*)(H + b0) = make_float2(h0, h1);
                *(float2*)(H + b1) = make_float2(h2, h3);
            }
            const float a0 = (h0 > thr0[nt]) ? h0 : 0.0f;
            const float a1 = (h1 > thr1[nt]) ? h1 : 0.0f;
            const float a2 = (h2 > thr0[nt]) ? h2 : 0.0f;
            const float a3 = (h3 > thr1[nt]) ? h3 : 0.0f;
            *(float2*)(A + b0) = make_float2(a0, a1);
            *(float2*)(A + b1) = make_float2(a2, a3);
            *(__half2*)(AH16 + b0) = __floats2half2_rn(a0, a1);
            *(__half2*)(AH16 + b1) = __floats2half2_rn(a2, a3);
        }
    }
}

// ---------------- decode via mma.sync fp16, 3-stage pipe ----------------
__global__ __launch_bounds__(256, 1)
void decode_fp16(const __half* __restrict__ AH, const __half* __restrict__ WD,
                 float* __restrict__ XH) {
    extern __shared__ __half sm[];
    const uint32_t sb = smem_u32(sm);

    const int j  = (NL - 1) - blockIdx.z;
    const int bm = blockIdx.y * DBM;
    const int bn = blockIdx.x * DBN;
    const int KT = (j + 1) * (FL / DBK);

    const int tid  = threadIdx.x;
    const int lane = tid & 31, wid = tid >> 5;
    const int wm = wid & 3, wn = wid >> 2;
    const int r = lane >> 2, c = lane & 3;
    const int lr = lane & 15, lc = lane >> 4;

    const __half* gah = AH + (size_t)(bm + tid) * (NL * FL);
    const __half* wj  = WD + (size_t)j * FL * DM;
    const size_t wd_istride = (size_t)NL * FL * DM;

    const uint32_t a_row_off = (uint32_t)tid * ASTR;
    const int brow = tid >> 3, bq = (tid & 7) * 16;
    const uint32_t b_row_off = (uint32_t)brow * BSTR + bq;

    float acc[4][8][4];
#pragma unroll
    for (int mt = 0; mt < 4; mt++)
#pragma unroll
        for (int nt = 0; nt < 8; nt++)
#pragma unroll
            for (int q = 0; q < 4; q++) acc[mt][nt][q] = 0.0f;

#define DEC_ISSUE(KN, ST)                                                       \
    do {                                                                        \
        const uint32_t ao = a_row_off + (uint32_t)(ST) * SA;                    \
        _Pragma("unroll")                                                       \
        for (int q = 0; q < 4; q++)                                             \
            cp16(sb + 2 * (ao + q * 8), gah + (KN) * DBK + q * 8);              \
        const int ii = (KN) >> 6, f0 = ((KN) & 63) * DBK;                       \
        const __half* sbp = wj + (size_t)ii * wd_istride +                      \
                            (size_t)(f0 + brow) * DM + bn + bq;                 \
        const uint32_t bo = DEC_B_BASE + b_row_off + (uint32_t)(ST) * SB;       \
        cp16(sb + 2 * bo, sbp);                                                 \
        cp16(sb + 2 * (bo + 8), sbp + 8);                                       \
        asm volatile("cp.async.commit_group;");                                 \
    } while (0)

    DEC_ISSUE(0, 0);
    DEC_ISSUE(1, 1);

    for (int kt = 0; kt < KT; kt++) {
        if (kt + 1 < KT) asm volatile("cp.async.wait_group 1;");
        else             asm volatile("cp.async.wait_group 0;");
        __syncthreads();
        if (kt + 2 < KT) {
            const int kn = kt + 2;
            DEC_ISSUE(kn, kn % 3);
        }
        const int st = kt % 3;
        const uint32_t a_b = sb + 2 * ((uint32_t)st * SA);
        const uint32_t b_b = sb + 2 * (DEC_B_BASE + (uint32_t)st * SB);

#pragma unroll
        for (int s = 0; s < 2; s++) {
            uint32_t a[4][4], bb[4][4];
#pragma unroll
            for (int mt = 0; mt < 4; mt++) {
                const uint32_t ao =
                    2 * ((uint32_t)(wm * 64 + mt * 16 + lr) * ASTR + s * 16 + 8 * lc);
                ldsm_x4(a[mt], a_b + ao);
            }
#pragma unroll
            for (int g = 0; g < 4; g++) {
                const uint32_t bo =
                    2 * ((uint32_t)(s * 16 + lr) * BSTR + wn * 64 + g * 16 + 8 * lc);
                ldsm_x4t(bb[g], b_b + bo);
            }
#pragma unroll
            for (int mt = 0; mt < 4; mt++)
#pragma unroll
                for (int g = 0; g < 4; g++) {
                    mma_f16(acc[mt][2 * g],     a[mt], &bb[g][0]);
                    mma_f16(acc[mt][2 * g + 1], a[mt], &bb[g][2]);
                }
        }
    }
#undef DEC_ISSUE

#pragma unroll
    for (int mt = 0; mt < 4; mt++) {
        const int row = bm + wm * 64 + mt * 16 + r;
#pragma unroll
        for (int nt = 0; nt < 8; nt++) {
            const int col = bn + wn * 64 + nt * 8 + 2 * c;
            float* p = XH + (size_t)row * (NL * DM) + (size_t)j * DM + col;
            *(float2*)p = make_float2(acc[mt][nt][0], acc[mt][nt][1]);
            *(float2*)(p + (size_t)8 * (NL * DM)) =
                make_float2(acc[mt][nt][2], acc[mt][nt][3]);
        }
    }
}

// ---------------- host ----------------
extern "C" void kernel_launch(void* const* d_in, const int* in_sizes, int n_in,
                              void* d_out, int out_size) {
    const float* x  = (const float*)d_in[0];
    const float* we = (const float*)d_in[1];
    const float* wd = (const float*)d_in[2];
    const float* th = (const float*)d_in[3];
    float* out = (float*)d_out;

    const long long HE = (long long)T_TOK * NL * FL;
    const long long XE = (long long)T_TOK * NL * DM;

    float *hp, *ap, *xp;
    if ((long long)out_size >= 2 * HE + XE) {
        hp = out; ap = out + HE; xp = out + 2 * HE;
    } else {
        hp = nullptr;
        float* sp = nullptr;
        cudaGetSymbolAddress((void**)&sp, g_acts_scratch);
        ap = sp; xp = out;
    }

    __half *wd16, *ah, *xh, *xl, *weh, *wel;
    cudaGetSymbolAddress((void**)&wd16, g_wd16);
    cudaGetSymbolAddress((void**)&ah, g_ah);
    cudaGetSymbolAddress((void**)&xh, g_xh);
    cudaGetSymbolAddress((void**)&xl, g_xl);
    cudaGetSymbolAddress((void**)&weh, g_weh);
    cudaGetSymbolAddress((void**)&wel, g_wel);

    cudaFuncSetAttribute(decode_fp16, cudaFuncAttributeMaxDynamicSharedMemorySize,
                         SMEM_DEC_BYTES);
    cudaFuncSetAttribute(encode_fused, cudaFuncAttributeMaxDynamicSharedMemorySize,
                         SMEM_ENC_BYTES);

    prep_xwe<<<2 * NB_X, 256>>>(x, we, xh, xl, weh, wel);
    encode_fused<<<NWD + ENC_BLOCKS, 256, SMEM_ENC_BYTES>>>(
        xh, xl, weh, wel, th, hp, ap, ah, wd, wd16);
    decode_fp16<<<dim3(DM / DBN, T_TOK / DBM, NL), 256, SMEM_DEC_BYTES>>>(ah, wd16, xp);
}

// round 11
// speedup vs baseline: 4.5967x; 1.1966x over previous
#include <cuda_runtime.h>
#include <cuda_fp16.h>
#include <math.h>
#include <stdint.h>

#define T_TOK 2048
#define NL    12
#define DM    768
#define FL    2048

// encode tile: CTA 256x128x32, 8 warps (4m x 2n), warp 64x64
#define DBM 256
#define DBN 128
#define DBK 32
#define ASTR 40
#define BSTR 136
#define SA (DBM * ASTR)   // 10240 halves per A stage (encode)
#define SB (DBK * BSTR)   // 4352 halves per B stage

// decode tile: CTA 128x128x32, 8 warps (4m x 2n), warp 32x64 -> 2 CTAs/SM
#define DM2 128
#define SA2 (DM2 * ASTR)  // 5120 halves per A stage (decode)
#define DEC_B_BASE (3 * SA2)
#define SMEM_DEC_BYTES ((3 * SA2 + 3 * SB) * 2)         // 56832

// encode smem (halves)
#define EXH_BASE 0
#define EXL_BASE (3 * SA)
#define EWH_BASE (6 * SA)
#define EWL_BASE (6 * SA + 3 * SB)
#define SMEM_ENC_BYTES ((6 * SA + 6 * SB) * 2)          // 175104

#define NWD 78
#define ENC_BLOCKS (16 * 8 * NL)   // 1536

__device__ __half g_wd16[(size_t)NL * NL * FL * DM];
__device__ __half g_ah[(size_t)T_TOK * NL * FL];
__device__ __half g_xh[(size_t)T_TOK * NL * DM];
__device__ __half g_xl[(size_t)T_TOK * NL * DM];
__device__ __half g_weh[(size_t)NL * DM * FL];
__device__ __half g_wel[(size_t)NL * DM * FL];
__device__ float  g_acts_scratch[(size_t)T_TOK * NL * FL];

// ---------------- helpers ----------------
__device__ __forceinline__ uint32_t smem_u32(const void* p) {
    return (uint32_t)__cvta_generic_to_shared(p);
}
__device__ __forceinline__ void cp16(uint32_t d, const void* s) {
    asm volatile("cp.async.cg.shared.global [%0], [%1], 16;" :: "r"(d), "l"(s));
}
__device__ __forceinline__ void ldsm_x4(uint32_t* r, uint32_t a) {
    asm volatile("ldmatrix.sync.aligned.m8n8.x4.shared.b16 {%0,%1,%2,%3}, [%4];"
                 : "=r"(r[0]), "=r"(r[1]), "=r"(r[2]), "=r"(r[3]) : "r"(a));
}
__device__ __forceinline__ void ldsm_x4t(uint32_t* r, uint32_t a) {
    asm volatile("ldmatrix.sync.aligned.m8n8.x4.trans.shared.b16 {%0,%1,%2,%3}, [%4];"
                 : "=r"(r[0]), "=r"(r[1]), "=r"(r[2]), "=r"(r[3]) : "r"(a));
}
__device__ __forceinline__ void mma_f16(float* d, const uint32_t* a, const uint32_t* b) {
    asm volatile(
        "mma.sync.aligned.m16n8k16.row.col.f32.f16.f16.f32 "
        "{%0,%1,%2,%3}, {%4,%5,%6,%7}, {%8,%9}, {%0,%1,%2,%3};"
        : "+f"(d[0]), "+f"(d[1]), "+f"(d[2]), "+f"(d[3])
        : "r"(a[0]), "r"(a[1]), "r"(a[2]), "r"(a[3]), "r"(b[0]), "r"(b[1]));
}
__device__ __forceinline__ void cvt4(__half* h4, float4 v) {
    h4[0] = __float2half_rn(v.x); h4[1] = __float2half_rn(v.y);
    h4[2] = __float2half_rn(v.z); h4[3] = __float2half_rn(v.w);
}

// ---------------- prep: split x and w_e into fp16 hi/lo ----------------
#define NB_X  (T_TOK * NL * DM / 1024)   // 18432

__global__ __launch_bounds__(256)
void prep_xwe(const float* __restrict__ x, const float* __restrict__ we,
              __half* __restrict__ xh, __half* __restrict__ xl,
              __half* __restrict__ weh, __half* __restrict__ wel) {
    const int b = blockIdx.x;
    const bool is_x = b < NB_X;
    const float* src = is_x ? x : we;
    __half* hi = is_x ? xh : weh;
    __half* lo = is_x ? xl : wel;
    const size_t idx = ((size_t)(is_x ? b : b - NB_X) * 256 + threadIdx.x) * 4;
    float4 v = *(const float4*)(src + idx);
    __half h4[4]; cvt4(h4, v);
    __half l4[4] = {__float2half_rn(v.x - __half2float(h4[0])),
                    __float2half_rn(v.y - __half2float(h4[1])),
                    __float2half_rn(v.z - __half2float(h4[2])),
                    __float2half_rn(v.w - __half2float(h4[3]))};
    *(uint2*)(hi + idx) = *(uint2*)h4;
    *(uint2*)(lo + idx) = *(uint2*)l4;
}

// ---------------- encode (3-product fp16 mma) + fused wd->fp16 convert -------
__global__ __launch_bounds__(256, 1)
void encode_fused(const __half* __restrict__ XHp, const __half* __restrict__ XLp,
                  const __half* __restrict__ WHp, const __half* __restrict__ WLp,
                  const float* __restrict__ TH, float* __restrict__ H,
                  float* __restrict__ A, __half* __restrict__ AH16,
                  const float* __restrict__ WDsrc, __half* __restrict__ WD16) {
    if (blockIdx.x < NWD) {
        const int p = blockIdx.x;
        int i = 0, rem = p;
        while (rem >= NL - i) { rem -= NL - i; i++; }
        const size_t zoff = (size_t)(i * NL + i + rem) * FL * DM;
        const float4* src = (const float4*)(WDsrc + zoff);
        uint2* dst = (uint2*)(WD16 + zoff);
        const int N4 = FL * DM / 4;
        for (int q = threadIdx.x; q < N4; q += 1024) {
            float4 v0 = src[q], v1 = src[q + 256], v2 = src[q + 512], v3 = src[q + 768];
            __half h0[4], h1[4], h2[4], h3[4];
            cvt4(h0, v0); cvt4(h1, v1); cvt4(h2, v2); cvt4(h3, v3);
            dst[q]       = *(uint2*)h0;
            dst[q + 256] = *(uint2*)h1;
            dst[q + 512] = *(uint2*)h2;
            dst[q + 768] = *(uint2*)h3;
        }
        return;
    }

    extern __shared__ __half sm[];
    const uint32_t sb = smem_u32(sm);

    const int bid = blockIdx.x - NWD;
    const int l  = bid >> 7;
    const int bm = ((bid >> 4) & 7) * DBM;
    const int bn = (bid & 15) * DBN;
    const int KT = DM / DBK;   // 24

    const int tid  = threadIdx.x;
    const int lane = tid & 31, wid = tid >> 5;
    const int wm = wid & 3, wn = wid >> 2;
    const int r = lane >> 2, c = lane & 3;
    const int lr = lane & 15, lc = lane >> 4;

    const __half* gxh = XHp + ((size_t)(bm + tid) * NL + l) * DM;
    const __half* gxl = XLp + ((size_t)(bm + tid) * NL + l) * DM;
    const __half* gwh = WHp + (size_t)l * DM * FL;
    const __half* gwl = WLp + (size_t)l * DM * FL;

    const uint32_t a_row_off = (uint32_t)tid * ASTR;
    const int brow = tid >> 3, bq = (tid & 7) * 16;
    const uint32_t b_row_off = (uint32_t)brow * BSTR + bq;

    float acc[4][8][4];
#pragma unroll
    for (int mt = 0; mt < 4; mt++)
#pragma unroll
        for (int nt = 0; nt < 8; nt++)
#pragma unroll
            for (int q = 0; q < 4; q++) acc[mt][nt][q] = 0.0f;

#define ENC_ISSUE(KN, ST)                                                        \
    do {                                                                         \
        const uint32_t ao = a_row_off + (uint32_t)(ST) * SA;                     \
        _Pragma("unroll")                                                        \
        for (int q = 0; q < 4; q++) {                                            \
            cp16(sb + 2 * (EXH_BASE + ao + q * 8), gxh + (KN) * DBK + q * 8);    \
            cp16(sb + 2 * (EXL_BASE + ao + q * 8), gxl + (KN) * DBK + q * 8);    \
        }                                                                        \
        const __half* wb = gwh + (size_t)((KN) * DBK + brow) * FL + bn + bq;     \
        const __half* wc = gwl + (size_t)((KN) * DBK + brow) * FL + bn + bq;     \
        const uint32_t bo = b_row_off + (uint32_t)(ST) * SB;                     \
        cp16(sb + 2 * (EWH_BASE + bo),     wb);                                  \
        cp16(sb + 2 * (EWH_BASE + bo + 8), wb + 8);                              \
        cp16(sb + 2 * (EWL_BASE + bo),     wc);                                  \
        cp16(sb + 2 * (EWL_BASE + bo + 8), wc + 8);                              \
        asm volatile("cp.async.commit_group;");                                  \
    } while (0)

    ENC_ISSUE(0, 0);
    ENC_ISSUE(1, 1);

    for (int kt = 0; kt < KT; kt++) {
        if (kt + 1 < KT) asm volatile("cp.async.wait_group 1;");
        else             asm volatile("cp.async.wait_group 0;");
        __syncthreads();
        if (kt + 2 < KT) {
            const int kn = kt + 2;
            ENC_ISSUE(kn, kn % 3);
        }
        const int st = kt % 3;
        const uint32_t ah_b = sb + 2 * (EXH_BASE + (uint32_t)st * SA);
        const uint32_t al_b = sb + 2 * (EXL_BASE + (uint32_t)st * SA);
        const uint32_t bh_b = sb + 2 * (EWH_BASE + (uint32_t)st * SB);
        const uint32_t bl_b = sb + 2 * (EWL_BASE + (uint32_t)st * SB);

#pragma unroll
        for (int s = 0; s < 2; s++) {
            uint32_t ah[4][4], fb[4][4];
            const uint32_t aoff = 2 * (uint32_t)((wm * 64 + lr) * ASTR + s * 16 + 8 * lc);
            const uint32_t boff = 2 * (uint32_t)((s * 16 + lr) * BSTR + wn * 64 + 8 * lc);
#pragma unroll
            for (int mt = 0; mt < 4; mt++)
                ldsm_x4(ah[mt], ah_b + aoff + 2 * (uint32_t)(mt * 16 * ASTR));
#pragma unroll
            for (int g = 0; g < 4; g++)
                ldsm_x4t(fb[g], bh_b + boff + 2 * (uint32_t)(g * 16));
#pragma unroll
            for (int mt = 0; mt < 4; mt++)
#pragma unroll
                for (int g = 0; g < 4; g++) {
                    mma_f16(acc[mt][2 * g],     ah[mt], &fb[g][0]);
                    mma_f16(acc[mt][2 * g + 1], ah[mt], &fb[g][2]);
                }
            {
                uint32_t al[4][4];
#pragma unroll
                for (int mt = 0; mt < 4; mt++)
                    ldsm_x4(al[mt], al_b + aoff + 2 * (uint32_t)(mt * 16 * ASTR));
#pragma unroll
                for (int mt = 0; mt < 4; mt++)
#pragma unroll
                    for (int g = 0; g < 4; g++) {
                        mma_f16(acc[mt][2 * g],     al[mt], &fb[g][0]);
                        mma_f16(acc[mt][2 * g + 1], al[mt], &fb[g][2]);
                    }
            }
#pragma unroll
            for (int g = 0; g < 4; g++)
                ldsm_x4t(fb[g], bl_b + boff + 2 * (uint32_t)(g * 16));
#pragma unroll
            for (int mt = 0; mt < 4; mt++)
#pragma unroll
                for (int g = 0; g < 4; g++) {
                    mma_f16(acc[mt][2 * g],     ah[mt], &fb[g][0]);
                    mma_f16(acc[mt][2 * g + 1], ah[mt], &fb[g][2]);
                }
        }
    }
#undef ENC_ISSUE

    float thr0[8], thr1[8];
#pragma unroll
    for (int nt = 0; nt < 8; nt++) {
        const int col = bn + wn * 64 + nt * 8 + 2 * c;
        thr0[nt] = expf(TH[l * FL + col]);
        thr1[nt] = expf(TH[l * FL + col + 1]);
    }
#pragma unroll
    for (int mt = 0; mt < 4; mt++) {
        const int row = bm + wm * 64 + mt * 16 + r;
#pragma unroll
        for (int nt = 0; nt < 8; nt++) {
            const int col = bn + wn * 64 + nt * 8 + 2 * c;
            const size_t b0 = (size_t)row * (NL * FL) + (size_t)l * FL + col;
            const size_t b1 = b0 + (size_t)8 * (NL * FL);
            const float h0 = acc[mt][nt][0], h1 = acc[mt][nt][1];
            const float h2 = acc[mt][nt][2], h3 = acc[mt][nt][3];
            if (H) {
                *(float2*)(H + b0) = make_float2(h0, h1);
                *(float2*)(H + b1) = make_float2(h2, h3);
            }
            const float a0 = (h0 > thr0[nt]) ? h0 : 0.0f;
            const float a1 = (h1 > thr1[nt]) ? h1 : 0.0f;
            const float a2 = (h2 > thr0[nt]) ? h2 : 0.0f;
            const float a3 = (h3 > thr1[nt]) ? h3 : 0.0f;
            *(float2*)(A + b0) = make_float2(a0, a1);
            *(float2*)(A + b1) = make_float2(a2, a3);
            *(__half2*)(AH16 + b0) = __floats2half2_rn(a0, a1);
            *(__half2*)(AH16 + b1) = __floats2half2_rn(a2, a3);
        }
    }
}

// ---------------- decode: CTA 128x128x32, 2 CTAs/SM ----------------
__global__ __launch_bounds__(256, 2)
void decode_fp16(const __half* __restrict__ AH, const __half* __restrict__ WD,
                 float* __restrict__ XH) {
    extern __shared__ __half sm[];
    const uint32_t sb = smem_u32(sm);

    const int j  = (NL - 1) - blockIdx.z;
    const int bm = blockIdx.y * DM2;
    const int bn = blockIdx.x * DBN;
    const int KT = (j + 1) * (FL / DBK);

    const int tid  = threadIdx.x;
    const int lane = tid & 31, wid = tid >> 5;
    const int wm = wid & 3, wn = wid >> 2;   // warp tile 32x64
    const int r = lane >> 2, c = lane & 3;
    const int lr = lane & 15, lc = lane >> 4;

    // A: 128 rows x 32 halves/ktile = 512 cp16; 256 threads -> 2 cp16 each
    // thread covers row tid>>1, halves [(tid&1)*16, (tid&1)*16+16)
    const __half* gah = AH + (size_t)(bm + (tid >> 1)) * (NL * FL) + (tid & 1) * 16;
    const uint32_t a_off_t = (uint32_t)(tid >> 1) * ASTR + (uint32_t)(tid & 1) * 16;

    const __half* wj  = WD + (size_t)j * FL * DM;
    const size_t wd_istride = (size_t)NL * FL * DM;
    const int brow = tid >> 3, bq = (tid & 7) * 16;
    const uint32_t b_row_off = (uint32_t)brow * BSTR + bq;

    float acc[2][8][4];
#pragma unroll
    for (int mt = 0; mt < 2; mt++)
#pragma unroll
        for (int nt = 0; nt < 8; nt++)
#pragma unroll
            for (int q = 0; q < 4; q++) acc[mt][nt][q] = 0.0f;

#define DEC_ISSUE(KN, ST)                                                       \
    do {                                                                        \
        const uint32_t ao = a_off_t + (uint32_t)(ST) * SA2;                     \
        cp16(sb + 2 * ao,       gah + (KN) * DBK);                              \
        cp16(sb + 2 * (ao + 8), gah + (KN) * DBK + 8);                          \
        const int ii = (KN) >> 6, f0 = ((KN) & 63) * DBK;                       \
        const __half* sbp = wj + (size_t)ii * wd_istride +                      \
                            (size_t)(f0 + brow) * DM + bn + bq;                 \
        const uint32_t bo = DEC_B_BASE + b_row_off + (uint32_t)(ST) * SB;       \
        cp16(sb + 2 * bo, sbp);                                                 \
        cp16(sb + 2 * (bo + 8), sbp + 8);                                       \
        asm volatile("cp.async.commit_group;");                                 \
    } while (0)

    DEC_ISSUE(0, 0);
    DEC_ISSUE(1, 1);

    for (int kt = 0; kt < KT; kt++) {
        if (kt + 1 < KT) asm volatile("cp.async.wait_group 1;");
        else             asm volatile("cp.async.wait_group 0;");
        __syncthreads();
        if (kt + 2 < KT) {
            const int kn = kt + 2;
            DEC_ISSUE(kn, kn % 3);
        }
        const int st = kt % 3;
        const uint32_t a_b = sb + 2 * ((uint32_t)st * SA2);
        const uint32_t b_b = sb + 2 * (DEC_B_BASE + (uint32_t)st * SB);

#pragma unroll
        for (int s = 0; s < 2; s++) {
            uint32_t a[2][4], bb[4][4];
#pragma unroll
            for (int mt = 0; mt < 2; mt++) {
                const uint32_t ao =
                    2 * ((uint32_t)(wm * 32 + mt * 16 + lr) * ASTR + s * 16 + 8 * lc);
                ldsm_x4(a[mt], a_b + ao);
            }
#pragma unroll
            for (int g = 0; g < 4; g++) {
                const uint32_t bo =
                    2 * ((uint32_t)(s * 16 + lr) * BSTR + wn * 64 + g * 16 + 8 * lc);
                ldsm_x4t(bb[g], b_b + bo);
            }
#pragma unroll
            for (int mt = 0; mt < 2; mt++)
#pragma unroll
                for (int g = 0; g < 4; g++) {
                    mma_f16(acc[mt][2 * g],     a[mt], &bb[g][0]);
                    mma_f16(acc[mt][2 * g + 1], a[mt], &bb[g][2]);
                }
        }
    }
#undef DEC_ISSUE

#pragma unroll
    for (int mt = 0; mt < 2; mt++) {
        const int row = bm + wm * 32 + mt * 16 + r;
#pragma unroll
        for (int nt = 0; nt < 8; nt++) {
            const int col = bn + wn * 64 + nt * 8 + 2 * c;
            float* p = XH + (size_t)row * (NL * DM) + (size_t)j * DM + col;
            *(float2*)p = make_float2(acc[mt][nt][0], acc[mt][nt][1]);
            *(float2*)(p + (size_t)8 * (NL * DM)) =
                make_float2(acc[mt][nt][2], acc[mt][nt][3]);
        }
    }
}

// ---------------- host ----------------
extern "C" void kernel_launch(void* const* d_in, const int* in_sizes, int n_in,
                              void* d_out, int out_size) {
    const float* x  = (const float*)d_in[0];
    const float* we = (const float*)d_in[1];
    const float* wd = (const float*)d_in[2];
    const float* th = (const float*)d_in[3];
    float* out = (float*)d_out;

    const long long HE = (long long)T_TOK * NL * FL;
    const long long XE = (long long)T_TOK * NL * DM;

    float *hp, *ap, *xp;
    if ((long long)out_size >= 2 * HE + XE) {
        hp = out; ap = out + HE; xp = out + 2 * HE;
    } else {
        hp = nullptr;
        float* sp = nullptr;
        cudaGetSymbolAddress((void**)&sp, g_acts_scratch);
        ap = sp; xp = out;
    }

    __half *wd16, *ah, *xh, *xl, *weh, *wel;
    cudaGetSymbolAddress((void**)&wd16, g_wd16);
    cudaGetSymbolAddress((void**)&ah, g_ah);
    cudaGetSymbolAddress((void**)&xh, g_xh);
    cudaGetSymbolAddress((void**)&xl, g_xl);
    cudaGetSymbolAddress((void**)&weh, g_weh);
    cudaGetSymbolAddress((void**)&wel, g_wel);

    cudaFuncSetAttribute(decode_fp16, cudaFuncAttributeMaxDynamicSharedMemorySize,
                         SMEM_DEC_BYTES);
    cudaFuncSetAttribute(encode_fused, cudaFuncAttributeMaxDynamicSharedMemorySize,
                         SMEM_ENC_BYTES);

    prep_xwe<<<2 * NB_X, 256>>>(x, we, xh, xl, weh, wel);
    encode_fused<<<NWD + ENC_BLOCKS, 256, SMEM_ENC_BYTES>>>(
        xh, xl, weh, wel, th, hp, ap, ah, wd, wd16);
    decode_fp16<<<dim3(DM / DBN, T_TOK / DM2, NL), 256, SMEM_DEC_BYTES>>>(ah, wd16, xp);
}

// round 12
// speedup vs baseline: 4.9510x; 1.0771x over previous
#include <cuda_runtime.h>
#include <cuda_fp16.h>
#include <math.h>
#include <stdint.h>

#define T_TOK 2048
#define NL    12
#define DM    768
#define FL    2048

#define DBN 128
#define DBK 32
#define ASTR 40
#define BSTR 136
#define SB (DBK * BSTR)   // 4352 halves per B stage

// both mma kernels: CTA 128x128x32, 8 warps (4m x 2n), warp 32x64, 2 CTAs/SM
#define DM2 128
#define SA2 (DM2 * ASTR)  // 5120 halves per A stage

// decode smem (halves)
#define DEC_B_BASE (3 * SA2)
#define SMEM_DEC_BYTES ((3 * SA2 + 3 * SB) * 2)         // 56832

// encode smem (halves)
#define EXH_BASE 0
#define EXL_BASE (3 * SA2)
#define EWH_BASE (6 * SA2)
#define EWL_BASE (6 * SA2 + 3 * SB)
#define SMEM_ENC_BYTES ((6 * SA2 + 6 * SB) * 2)         // 113664

#define NWD 78
#define ENC_BLOCKS (16 * 16 * NL)   // 3072

__device__ __half g_wd16[(size_t)NL * NL * FL * DM];
__device__ __half g_ah[(size_t)T_TOK * NL * FL];
__device__ __half g_xh[(size_t)T_TOK * NL * DM];
__device__ __half g_xl[(size_t)T_TOK * NL * DM];
__device__ __half g_weh[(size_t)NL * DM * FL];
__device__ __half g_wel[(size_t)NL * DM * FL];
__device__ float  g_acts_scratch[(size_t)T_TOK * NL * FL];

// ---------------- helpers ----------------
__device__ __forceinline__ uint32_t smem_u32(const void* p) {
    return (uint32_t)__cvta_generic_to_shared(p);
}
__device__ __forceinline__ void cp16(uint32_t d, const void* s) {
    asm volatile("cp.async.cg.shared.global [%0], [%1], 16;" :: "r"(d), "l"(s));
}
__device__ __forceinline__ void ldsm_x4(uint32_t* r, uint32_t a) {
    asm volatile("ldmatrix.sync.aligned.m8n8.x4.shared.b16 {%0,%1,%2,%3}, [%4];"
                 : "=r"(r[0]), "=r"(r[1]), "=r"(r[2]), "=r"(r[3]) : "r"(a));
}
__device__ __forceinline__ void ldsm_x4t(uint32_t* r, uint32_t a) {
    asm volatile("ldmatrix.sync.aligned.m8n8.x4.trans.shared.b16 {%0,%1,%2,%3}, [%4];"
                 : "=r"(r[0]), "=r"(r[1]), "=r"(r[2]), "=r"(r[3]) : "r"(a));
}
__device__ __forceinline__ void mma_f16(float* d, const uint32_t* a, const uint32_t* b) {
    asm volatile(
        "mma.sync.aligned.m16n8k16.row.col.f32.f16.f16.f32 "
        "{%0,%1,%2,%3}, {%4,%5,%6,%7}, {%8,%9}, {%0,%1,%2,%3};"
        : "+f"(d[0]), "+f"(d[1]), "+f"(d[2]), "+f"(d[3])
        : "r"(a[0]), "r"(a[1]), "r"(a[2]), "r"(a[3]), "r"(b[0]), "r"(b[1]));
}
__device__ __forceinline__ void cvt4(__half* h4, float4 v) {
    h4[0] = __float2half_rn(v.x); h4[1] = __float2half_rn(v.y);
    h4[2] = __float2half_rn(v.z); h4[3] = __float2half_rn(v.w);
}

// ---------------- prep: split x and w_e into fp16 hi/lo ----------------
#define NB_X  (T_TOK * NL * DM / 1024)   // 18432

__global__ __launch_bounds__(256)
void prep_xwe(const float* __restrict__ x, const float* __restrict__ we,
              __half* __restrict__ xh, __half* __restrict__ xl,
              __half* __restrict__ weh, __half* __restrict__ wel) {
    const int b = blockIdx.x;
    const bool is_x = b < NB_X;
    const float* src = is_x ? x : we;
    __half* hi = is_x ? xh : weh;
    __half* lo = is_x ? xl : wel;
    const size_t idx = ((size_t)(is_x ? b : b - NB_X) * 256 + threadIdx.x) * 4;
    float4 v = *(const float4*)(src + idx);
    __half h4[4]; cvt4(h4, v);
    __half l4[4] = {__float2half_rn(v.x - __half2float(h4[0])),
                    __float2half_rn(v.y - __half2float(h4[1])),
                    __float2half_rn(v.z - __half2float(h4[2])),
                    __float2half_rn(v.w - __half2float(h4[3]))};
    *(uint2*)(hi + idx) = *(uint2*)h4;
    *(uint2*)(lo + idx) = *(uint2*)l4;
}

// ---------------- encode (3-product fp16 mma, 128-row tile, 2 CTA/SM) --------
__global__ __launch_bounds__(256, 2)
void encode_fused(const __half* __restrict__ XHp, const __half* __restrict__ XLp,
                  const __half* __restrict__ WHp, const __half* __restrict__ WLp,
                  const float* __restrict__ TH, float* __restrict__ H,
                  float* __restrict__ A, __half* __restrict__ AH16,
                  const float* __restrict__ WDsrc, __half* __restrict__ WD16) {
    if (blockIdx.x < NWD) {
        const int p = blockIdx.x;
        int i = 0, rem = p;
        while (rem >= NL - i) { rem -= NL - i; i++; }
        const size_t zoff = (size_t)(i * NL + i + rem) * FL * DM;
        const float4* src = (const float4*)(WDsrc + zoff);
        uint2* dst = (uint2*)(WD16 + zoff);
        const int N4 = FL * DM / 4;
        for (int q = threadIdx.x; q < N4; q += 1024) {
            float4 v0 = src[q], v1 = src[q + 256], v2 = src[q + 512], v3 = src[q + 768];
            __half h0[4], h1[4], h2[4], h3[4];
            cvt4(h0, v0); cvt4(h1, v1); cvt4(h2, v2); cvt4(h3, v3);
            dst[q]       = *(uint2*)h0;
            dst[q + 256] = *(uint2*)h1;
            dst[q + 512] = *(uint2*)h2;
            dst[q + 768] = *(uint2*)h3;
        }
        return;
    }

    extern __shared__ __half sm[];
    const uint32_t sb = smem_u32(sm);

    const int bid = blockIdx.x - NWD;
    const int l  = bid >> 8;                  // 256 blocks per layer
    const int bm = ((bid >> 4) & 15) * DM2;
    const int bn = (bid & 15) * DBN;
    const int KT = DM / DBK;   // 24

    const int tid  = threadIdx.x;
    const int lane = tid & 31, wid = tid >> 5;
    const int wm = wid & 3, wn = wid >> 2;   // warp tile 32x64
    const int r = lane >> 2, c = lane & 3;
    const int lr = lane & 15, lc = lane >> 4;

    // A: 128 rows x 32 halves/ktile; thread -> row tid>>1, chunk (tid&1)*16
    const __half* gxh = XHp + ((size_t)(bm + (tid >> 1)) * NL + l) * DM + (tid & 1) * 16;
    const __half* gxl = XLp + ((size_t)(bm + (tid >> 1)) * NL + l) * DM + (tid & 1) * 16;
    const uint32_t a_off_t = (uint32_t)(tid >> 1) * ASTR + (uint32_t)(tid & 1) * 16;

    const __half* gwh = WHp + (size_t)l * DM * FL;
    const __half* gwl = WLp + (size_t)l * DM * FL;
    const int brow = tid >> 3, bq = (tid & 7) * 16;
    const uint32_t b_row_off = (uint32_t)brow * BSTR + bq;

    float acc[2][8][4];
#pragma unroll
    for (int mt = 0; mt < 2; mt++)
#pragma unroll
        for (int nt = 0; nt < 8; nt++)
#pragma unroll
            for (int q = 0; q < 4; q++) acc[mt][nt][q] = 0.0f;

#define ENC_ISSUE(KN, ST)                                                        \
    do {                                                                         \
        const uint32_t ao = a_off_t + (uint32_t)(ST) * SA2;                      \
        cp16(sb + 2 * (EXH_BASE + ao),     gxh + (KN) * DBK);                    \
        cp16(sb + 2 * (EXH_BASE + ao + 8), gxh + (KN) * DBK + 8);                \
        cp16(sb + 2 * (EXL_BASE + ao),     gxl + (KN) * DBK);                    \
        cp16(sb + 2 * (EXL_BASE + ao + 8), gxl + (KN) * DBK + 8);                \
        const __half* wb = gwh + (size_t)((KN) * DBK + brow) * FL + bn + bq;     \
        const __half* wc = gwl + (size_t)((KN) * DBK + brow) * FL + bn + bq;     \
        const uint32_t bo = b_row_off + (uint32_t)(ST) * SB;                     \
        cp16(sb + 2 * (EWH_BASE + bo),     wb);                                  \
        cp16(sb + 2 * (EWH_BASE + bo + 8), wb + 8);                              \
        cp16(sb + 2 * (EWL_BASE + bo),     wc);                                  \
        cp16(sb + 2 * (EWL_BASE + bo + 8), wc + 8);                              \
        asm volatile("cp.async.commit_group;");                                  \
    } while (0)

    ENC_ISSUE(0, 0);
    ENC_ISSUE(1, 1);

    for (int kt = 0; kt < KT; kt++) {
        if (kt + 1 < KT) asm volatile("cp.async.wait_group 1;");
        else             asm volatile("cp.async.wait_group 0;");
        __syncthreads();
        if (kt + 2 < KT) {
            const int kn = kt + 2;
            ENC_ISSUE(kn, kn % 3);
        }
        const int st = kt % 3;
        const uint32_t ah_b = sb + 2 * (EXH_BASE + (uint32_t)st * SA2);
        const uint32_t al_b = sb + 2 * (EXL_BASE + (uint32_t)st * SA2);
        const uint32_t bh_b = sb + 2 * (EWH_BASE + (uint32_t)st * SB);
        const uint32_t bl_b = sb + 2 * (EWL_BASE + (uint32_t)st * SB);

#pragma unroll
        for (int s = 0; s < 2; s++) {
            uint32_t ah[2][4], fb[4][4];
            const uint32_t aoff = 2 * (uint32_t)((wm * 32 + lr) * ASTR + s * 16 + 8 * lc);
            const uint32_t boff = 2 * (uint32_t)((s * 16 + lr) * BSTR + wn * 64 + 8 * lc);
#pragma unroll
            for (int mt = 0; mt < 2; mt++)
                ldsm_x4(ah[mt], ah_b + aoff + 2 * (uint32_t)(mt * 16 * ASTR));
#pragma unroll
            for (int g = 0; g < 4; g++)
                ldsm_x4t(fb[g], bh_b + boff + 2 * (uint32_t)(g * 16));
#pragma unroll
            for (int mt = 0; mt < 2; mt++)
#pragma unroll
                for (int g = 0; g < 4; g++) {
                    mma_f16(acc[mt][2 * g],     ah[mt], &fb[g][0]);
                    mma_f16(acc[mt][2 * g + 1], ah[mt], &fb[g][2]);
                }
            {
                uint32_t al[2][4];
#pragma unroll
                for (int mt = 0; mt < 2; mt++)
                    ldsm_x4(al[mt], al_b + aoff + 2 * (uint32_t)(mt * 16 * ASTR));
#pragma unroll
                for (int mt = 0; mt < 2; mt++)
#pragma unroll
                    for (int g = 0; g < 4; g++) {
                        mma_f16(acc[mt][2 * g],     al[mt], &fb[g][0]);
                        mma_f16(acc[mt][2 * g + 1], al[mt], &fb[g][2]);
                    }
            }
#pragma unroll
            for (int g = 0; g < 4; g++)
                ldsm_x4t(fb[g], bl_b + boff + 2 * (uint32_t)(g * 16));
#pragma unroll
            for (int mt = 0; mt < 2; mt++)
#pragma unroll
                for (int g = 0; g < 4; g++) {
                    mma_f16(acc[mt][2 * g],     ah[mt], &fb[g][0]);
                    mma_f16(acc[mt][2 * g + 1], ah[mt], &fb[g][2]);
                }
        }
    }
#undef ENC_ISSUE

    float thr0[8], thr1[8];
#pragma unroll
    for (int nt = 0; nt < 8; nt++) {
        const int col = bn + wn * 64 + nt * 8 + 2 * c;
        thr0[nt] = expf(TH[l * FL + col]);
        thr1[nt] = expf(TH[l * FL + col + 1]);
    }
#pragma unroll
    for (int mt = 0; mt < 2; mt++) {
        const int row = bm + wm * 32 + mt * 16 + r;
#pragma unroll
        for (int nt = 0; nt < 8; nt++) {
            const int col = bn + wn * 64 + nt * 8 + 2 * c;
            const size_t b0 = (size_t)row * (NL * FL) + (size_t)l * FL + col;
            const size_t b1 = b0 + (size_t)8 * (NL * FL);
            const float h0 = acc[mt][nt][0], h1 = acc[mt][nt][1];
            const float h2 = acc[mt][nt][2], h3 = acc[mt][nt][3];
            if (H) {
                *(float2*)(H + b0) = make_float2(h0, h1);
                *(float2*)(H + b1) = make_float2(h2, h3);
            }
            const float a0 = (h0 > thr0[nt]) ? h0 : 0.0f;
            const float a1 = (h1 > thr1[nt]) ? h1 : 0.0f;
            const float a2 = (h2 > thr0[nt]) ? h2 : 0.0f;
            const float a3 = (h3 > thr1[nt]) ? h3 : 0.0f;
            *(float2*)(A + b0) = make_float2(a0, a1);
            *(float2*)(A + b1) = make_float2(a2, a3);
            *(__half2*)(AH16 + b0) = __floats2half2_rn(a0, a1);
            *(__half2*)(AH16 + b1) = __floats2half2_rn(a2, a3);
        }
    }
}

// ---------------- decode: CTA 128x128x32, 2 CTAs/SM (unchanged) ----------------
__global__ __launch_bounds__(256, 2)
void decode_fp16(const __half* __restrict__ AH, const __half* __restrict__ WD,
                 float* __restrict__ XH) {
    extern __shared__ __half sm[];
    const uint32_t sb = smem_u32(sm);

    const int j  = (NL - 1) - blockIdx.z;
    const int bm = blockIdx.y * DM2;
    const int bn = blockIdx.x * DBN;
    const int KT = (j + 1) * (FL / DBK);

    const int tid  = threadIdx.x;
    const int lane = tid & 31, wid = tid >> 5;
    const int wm = wid & 3, wn = wid >> 2;
    const int r = lane >> 2, c = lane & 3;
    const int lr = lane & 15, lc = lane >> 4;

    const __half* gah = AH + (size_t)(bm + (tid >> 1)) * (NL * FL) + (tid & 1) * 16;
    const uint32_t a_off_t = (uint32_t)(tid >> 1) * ASTR + (uint32_t)(tid & 1) * 16;

    const __half* wj  = WD + (size_t)j * FL * DM;
    const size_t wd_istride = (size_t)NL * FL * DM;
    const int brow = tid >> 3, bq = (tid & 7) * 16;
    const uint32_t b_row_off = (uint32_t)brow * BSTR + bq;

    float acc[2][8][4];
#pragma unroll
    for (int mt = 0; mt < 2; mt++)
#pragma unroll
        for (int nt = 0; nt < 8; nt++)
#pragma unroll
            for (int q = 0; q < 4; q++) acc[mt][nt][q] = 0.0f;

#define DEC_ISSUE(KN, ST)                                                       \
    do {                                                                        \
        const uint32_t ao = a_off_t + (uint32_t)(ST) * SA2;                     \
        cp16(sb + 2 * ao,       gah + (KN) * DBK);                              \
        cp16(sb + 2 * (ao + 8), gah + (KN) * DBK + 8);                          \
        const int ii = (KN) >> 6, f0 = ((KN) & 63) * DBK;                       \
        const __half* sbp = wj + (size_t)ii * wd_istride +                      \
                            (size_t)(f0 + brow) * DM + bn + bq;                 \
        const uint32_t bo = DEC_B_BASE + b_row_off + (uint32_t)(ST) * SB;       \
        cp16(sb + 2 * bo, sbp);                                                 \
        cp16(sb + 2 * (bo + 8), sbp + 8);                                      \
        asm volatile("cp.async.commit_group;");                                 \
    } while (0)

    DEC_ISSUE(0, 0);
    DEC_ISSUE(1, 1);

    for (int kt = 0; kt < KT; kt++) {
        if (kt + 1 < KT) asm volatile("cp.async.wait_group 1;");
        else             asm volatile("cp.async.wait_group 0;");
        __syncthreads();
        if (kt + 2 < KT) {
            const int kn = kt + 2;
            DEC_ISSUE(kn, kn % 3);
        }
        const int st = kt % 3;
        const uint32_t a_b = sb + 2 * ((uint32_t)st * SA2);
        const uint32_t b_b = sb + 2 * (DEC_B_BASE + (uint32_t)st * SB);

#pragma unroll
        for (int s = 0; s < 2; s++) {
            uint32_t a[2][4], bb[4][4];
#pragma unroll
            for (int mt = 0; mt < 2; mt++) {
                const uint32_t ao =
                    2 * ((uint32_t)(wm * 32 + mt * 16 + lr) * ASTR + s * 16 + 8 * lc);
                ldsm_x4(a[mt], a_b + ao);
            }
#pragma unroll
            for (int g = 0; g < 4; g++) {
                const uint32_t bo =
                    2 * ((uint32_t)(s * 16 + lr) * BSTR + wn * 64 + g * 16 + 8 * lc);
                ldsm_x4t(bb[g], b_b + bo);
            }
#pragma unroll
            for (int mt = 0; mt < 2; mt++)
#pragma unroll
                for (int g = 0; g < 4; g++) {
                    mma_f16(acc[mt][2 * g],     a[mt], &bb[g][0]);
                    mma_f16(acc[mt][2 * g + 1], a[mt], &bb[g][2]);
                }
        }
    }
#undef DEC_ISSUE

#pragma unroll
    for (int mt = 0; mt < 2; mt++) {
        const int row = bm + wm * 32 + mt * 16 + r;
#pragma unroll
        for (int nt = 0; nt < 8; nt++) {
            const int col = bn + wn * 64 + nt * 8 + 2 * c;
            float* p = XH + (size_t)row * (NL * DM) + (size_t)j * DM + col;
            *(float2*)p = make_float2(acc[mt][nt][0], acc[mt][nt][1]);
            *(float2*)(p + (size_t)8 * (NL * DM)) =
                make_float2(acc[mt][nt][2], acc[mt][nt][3]);
        }
    }
}

// ---------------- host ----------------
extern "C" void kernel_launch(void* const* d_in, const int* in_sizes, int n_in,
                              void* d_out, int out_size) {
    const float* x  = (const float*)d_in[0];
    const float* we = (const float*)d_in[1];
    const float* wd = (const float*)d_in[2];
    const float* th = (const float*)d_in[3];
    float* out = (float*)d_out;

    const long long HE = (long long)T_TOK * NL * FL;
    const long long XE = (long long)T_TOK * NL * DM;

    float *hp, *ap, *xp;
    if ((long long)out_size >= 2 * HE + XE) {
        hp = out; ap = out + HE; xp = out + 2 * HE;
    } else {
        hp = nullptr;
        float* sp = nullptr;
        cudaGetSymbolAddress((void**)&sp, g_acts_scratch);
        ap = sp; xp = out;
    }

    __half *wd16, *ah, *xh, *xl, *weh, *wel;
    cudaGetSymbolAddress((void**)&wd16, g_wd16);
    cudaGetSymbolAddress((void**)&ah, g_ah);
    cudaGetSymbolAddress((void**)&xh, g_xh);
    cudaGetSymbolAddress((void**)&xl, g_xl);
    cudaGetSymbolAddress((void**)&weh, g_weh);
    cudaGetSymbolAddress((void**)&wel, g_wel);

    cudaFuncSetAttribute(decode_fp16, cudaFuncAttributeMaxDynamicSharedMemorySize,
                         SMEM_DEC_BYTES);
    cudaFuncSetAttribute(encode_fused, cudaFuncAttributeMaxDynamicSharedMemorySize,
                         SMEM_ENC_BYTES);

    prep_xwe<<<2 * NB_X, 256>>>(x, we, xh, xl, weh, wel);
    encode_fused<<<NWD + ENC_BLOCKS, 256, SMEM_ENC_BYTES>>>(
        xh, xl, weh, wel, th, hp, ap, ah, wd, wd16);
    decode_fp16<<<dim3(DM / DBN, T_TOK / DM2, NL), 256, SMEM_DEC_BYTES>>>(ah, wd16, xp);
}

// round 13
// speedup vs baseline: 5.2350x; 1.0574x over previous
#include <cuda_runtime.h>
#include <cuda_fp16.h>
#include <math.h>
#include <stdint.h>

#define T_TOK 2048
#define NL    12
#define DM    768
#define FL    2048

#define DBN 128
#define DBK 32
#define ASTR 40
#define BSTR 136
#define SB (DBK * BSTR)   // 4352 halves per B stage

// both mma kernels: CTA 128x128x32, 8 warps (4m x 2n), warp 32x64, 2 CTAs/SM
#define DM2 128
#define SA2 (DM2 * ASTR)  // 5120 halves per A stage

// decode smem (halves)
#define DEC_B_BASE (3 * SA2)
#define SMEM_DEC_BYTES ((3 * SA2 + 3 * SB) * 2)         // 56832

// encode smem (halves): XH, XL (3 stages each), WH (3 stages)
#define EXH_BASE 0
#define EXL_BASE (3 * SA2)
#define EWH_BASE (6 * SA2)
#define SMEM_ENC_BYTES ((6 * SA2 + 3 * SB) * 2)         // 87552

#define NWD 78
#define ENC_BLOCKS (16 * 16 * NL)   // 3072

#define FIX_CAP (1 << 22)
#define DELTA 8e-4f

__device__ __half g_wd16[(size_t)NL * NL * FL * DM];
__device__ __half g_ah[(size_t)T_TOK * NL * FL];
__device__ __half g_xh[(size_t)T_TOK * NL * DM];
__device__ __half g_xl[(size_t)T_TOK * NL * DM];
__device__ __half g_weh[(size_t)NL * DM * FL];
__device__ float  g_weT[(size_t)NL * FL * DM];          // we transposed [l][f][d]
__device__ float  g_acts_scratch[(size_t)T_TOK * NL * FL];
__device__ int    g_fix_count;
__device__ int    g_fix_list[FIX_CAP];

// ---------------- helpers ----------------
__device__ __forceinline__ uint32_t smem_u32(const void* p) {
    return (uint32_t)__cvta_generic_to_shared(p);
}
__device__ __forceinline__ void cp16(uint32_t d, const void* s) {
    asm volatile("cp.async.cg.shared.global [%0], [%1], 16;" :: "r"(d), "l"(s));
}
__device__ __forceinline__ void ldsm_x4(uint32_t* r, uint32_t a) {
    asm volatile("ldmatrix.sync.aligned.m8n8.x4.shared.b16 {%0,%1,%2,%3}, [%4];"
                 : "=r"(r[0]), "=r"(r[1]), "=r"(r[2]), "=r"(r[3]) : "r"(a));
}
__device__ __forceinline__ void ldsm_x4t(uint32_t* r, uint32_t a) {
    asm volatile("ldmatrix.sync.aligned.m8n8.x4.trans.shared.b16 {%0,%1,%2,%3}, [%4];"
                 : "=r"(r[0]), "=r"(r[1]), "=r"(r[2]), "=r"(r[3]) : "r"(a));
}
__device__ __forceinline__ void mma_f16(float* d, const uint32_t* a, const uint32_t* b) {
    asm volatile(
        "mma.sync.aligned.m16n8k16.row.col.f32.f16.f16.f32 "
        "{%0,%1,%2,%3}, {%4,%5,%6,%7}, {%8,%9}, {%0,%1,%2,%3};"
        : "+f"(d[0]), "+f"(d[1]), "+f"(d[2]), "+f"(d[3])
        : "r"(a[0]), "r"(a[1]), "r"(a[2]), "r"(a[3]), "r"(b[0]), "r"(b[1]));
}
__device__ __forceinline__ void cvt4(__half* h4, float4 v) {
    h4[0] = __float2half_rn(v.x); h4[1] = __float2half_rn(v.y);
    h4[2] = __float2half_rn(v.z); h4[3] = __float2half_rn(v.w);
}

// ---------------- prep: split x (hi/lo), we (hi), transpose we, zero ctr ----
#define NB_X  (T_TOK * NL * DM / 1024)   // 18432
#define NB_TR (NL * (DM / 32) * (FL / 32))   // 18432
#define NB_PREP (2 * NB_X + NB_TR)

__global__ __launch_bounds__(256)
void prep_xwe(const float* __restrict__ x, const float* __restrict__ we,
              __half* __restrict__ xh, __half* __restrict__ xl,
              __half* __restrict__ weh, float* __restrict__ weT) {
    const int b = blockIdx.x;
    if (b == 0 && threadIdx.x == 0) g_fix_count = 0;

    if (b < NB_X) {   // split x
        const size_t idx = ((size_t)b * 256 + threadIdx.x) * 4;
        float4 v = *(const float4*)(x + idx);
        __half h4[4]; cvt4(h4, v);
        __half l4[4] = {__float2half_rn(v.x - __half2float(h4[0])),
                        __float2half_rn(v.y - __half2float(h4[1])),
                        __float2half_rn(v.z - __half2float(h4[2])),
                        __float2half_rn(v.w - __half2float(h4[3]))};
        *(uint2*)(xh + idx) = *(uint2*)h4;
        *(uint2*)(xl + idx) = *(uint2*)l4;
    } else if (b < 2 * NB_X) {   // we -> fp16 hi only
        const size_t idx = ((size_t)(b - NB_X) * 256 + threadIdx.x) * 4;
        float4 v = *(const float4*)(we + idx);
        __half h4[4]; cvt4(h4, v);
        *(uint2*)(weh + idx) = *(uint2*)h4;
    } else {   // transpose we [l][d][f] -> weT [l][f][d], 32x32 tiles
        __shared__ float t[32][33];
        const int bt = b - 2 * NB_X;
        const int l  = bt / ((DM / 32) * (FL / 32));
        const int rm = bt % ((DM / 32) * (FL / 32));
        const int d0 = (rm / (FL / 32)) * 32;
        const int f0 = (rm % (FL / 32)) * 32;
        const int tx = threadIdx.x & 31, ty = threadIdx.x >> 5;
        const float* src = we + (size_t)l * DM * FL;
        float* dst = weT + (size_t)l * FL * DM;
#pragma unroll
        for (int r = 0; r < 32; r += 8)
            t[ty + r][tx] = src[(size_t)(d0 + ty + r) * FL + f0 + tx];
        __syncthreads();
#pragma unroll
        for (int r = 0; r < 32; r += 8)
            dst[(size_t)(f0 + ty + r) * DM + d0 + tx] = t[tx][ty + r];
    }
}

// ---------------- encode (2-product fp16 mma) + fused wd->fp16 convert -------
__global__ __launch_bounds__(256, 2)
void encode_fused(const __half* __restrict__ XHp, const __half* __restrict__ XLp,
                  const __half* __restrict__ WHp,
                  const float* __restrict__ TH, float* __restrict__ H,
                  float* __restrict__ A, __half* __restrict__ AH16,
                  const float* __restrict__ WDsrc, __half* __restrict__ WD16) {
    if (blockIdx.x < NWD) {
        const int p = blockIdx.x;
        int i = 0, rem = p;
        while (rem >= NL - i) { rem -= NL - i; i++; }
        const size_t zoff = (size_t)(i * NL + i + rem) * FL * DM;
        const float4* src = (const float4*)(WDsrc + zoff);
        uint2* dst = (uint2*)(WD16 + zoff);
        const int N4 = FL * DM / 4;
        for (int q = threadIdx.x; q < N4; q += 1024) {
            float4 v0 = src[q], v1 = src[q + 256], v2 = src[q + 512], v3 = src[q + 768];
            __half h0[4], h1[4], h2[4], h3[4];
            cvt4(h0, v0); cvt4(h1, v1); cvt4(h2, v2); cvt4(h3, v3);
            dst[q]       = *(uint2*)h0;
            dst[q + 256] = *(uint2*)h1;
            dst[q + 512] = *(uint2*)h2;
            dst[q + 768] = *(uint2*)h3;
        }
        return;
    }

    extern __shared__ __half sm[];
    const uint32_t sb = smem_u32(sm);

    const int bid = blockIdx.x - NWD;
    const int l  = bid >> 8;
    const int bm = ((bid >> 4) & 15) * DM2;
    const int bn = (bid & 15) * DBN;
    const int KT = DM / DBK;   // 24

    const int tid  = threadIdx.x;
    const int lane = tid & 31, wid = tid >> 5;
    const int wm = wid & 3, wn = wid >> 2;
    const int r = lane >> 2, c = lane & 3;
    const int lr = lane & 15, lc = lane >> 4;

    const __half* gxh = XHp + ((size_t)(bm + (tid >> 1)) * NL + l) * DM + (tid & 1) * 16;
    const __half* gxl = XLp + ((size_t)(bm + (tid >> 1)) * NL + l) * DM + (tid & 1) * 16;
    const uint32_t a_off_t = (uint32_t)(tid >> 1) * ASTR + (uint32_t)(tid & 1) * 16;

    const __half* gwh = WHp + (size_t)l * DM * FL;
    const int brow = tid >> 3, bq = (tid & 7) * 16;
    const uint32_t b_row_off = (uint32_t)brow * BSTR + bq;

    float acc[2][8][4];
#pragma unroll
    for (int mt = 0; mt < 2; mt++)
#pragma unroll
        for (int nt = 0; nt < 8; nt++)
#pragma unroll
            for (int q = 0; q < 4; q++) acc[mt][nt][q] = 0.0f;

#define ENC_ISSUE(KN, ST)                                                        \
    do {                                                                         \
        const uint32_t ao = a_off_t + (uint32_t)(ST) * SA2;                      \
        cp16(sb + 2 * (EXH_BASE + ao),     gxh + (KN) * DBK);                    \
        cp16(sb + 2 * (EXH_BASE + ao + 8), gxh + (KN) * DBK + 8);                \
        cp16(sb + 2 * (EXL_BASE + ao),     gxl + (KN) * DBK);                    \
        cp16(sb + 2 * (EXL_BASE + ao + 8), gxl + (KN) * DBK + 8);                \
        const __half* wb = gwh + (size_t)((KN) * DBK + brow) * FL + bn + bq;     \
        const uint32_t bo = b_row_off + (uint32_t)(ST) * SB;                     \
        cp16(sb + 2 * (EWH_BASE + bo),     wb);                                  \
        cp16(sb + 2 * (EWH_BASE + bo + 8), wb + 8);                              \
        asm volatile("cp.async.commit_group;");                                  \
    } while (0)

    ENC_ISSUE(0, 0);
    ENC_ISSUE(1, 1);

    for (int kt = 0; kt < KT; kt++) {
        if (kt + 1 < KT) asm volatile("cp.async.wait_group 1;");
        else             asm volatile("cp.async.wait_group 0;");
        __syncthreads();
        if (kt + 2 < KT) {
            const int kn = kt + 2;
            ENC_ISSUE(kn, kn % 3);
        }
        const int st = kt % 3;
        const uint32_t ah_b = sb + 2 * (EXH_BASE + (uint32_t)st * SA2);
        const uint32_t al_b = sb + 2 * (EXL_BASE + (uint32_t)st * SA2);
        const uint32_t bh_b = sb + 2 * (EWH_BASE + (uint32_t)st * SB);

#pragma unroll
        for (int s = 0; s < 2; s++) {
            uint32_t ah[2][4], al[2][4], fb[4][4];
            const uint32_t aoff = 2 * (uint32_t)((wm * 32 + lr) * ASTR + s * 16 + 8 * lc);
            const uint32_t boff = 2 * (uint32_t)((s * 16 + lr) * BSTR + wn * 64 + 8 * lc);
#pragma unroll
            for (int mt = 0; mt < 2; mt++) {
                ldsm_x4(ah[mt], ah_b + aoff + 2 * (uint32_t)(mt * 16 * ASTR));
                ldsm_x4(al[mt], al_b + aoff + 2 * (uint32_t)(mt * 16 * ASTR));
            }
#pragma unroll
            for (int g = 0; g < 4; g++)
                ldsm_x4t(fb[g], bh_b + boff + 2 * (uint32_t)(g * 16));
#pragma unroll
            for (int mt = 0; mt < 2; mt++)
#pragma unroll
                for (int g = 0; g < 4; g++) {
                    mma_f16(acc[mt][2 * g],     ah[mt], &fb[g][0]);
                    mma_f16(acc[mt][2 * g + 1], ah[mt], &fb[g][2]);
                    mma_f16(acc[mt][2 * g],     al[mt], &fb[g][0]);
                    mma_f16(acc[mt][2 * g + 1], al[mt], &fb[g][2]);
                }
        }
    }
#undef ENC_ISSUE

    float thr0[8], thr1[8];
#pragma unroll
    for (int nt = 0; nt < 8; nt++) {
        const int col = bn + wn * 64 + nt * 8 + 2 * c;
        thr0[nt] = expf(TH[l * FL + col]);
        thr1[nt] = expf(TH[l * FL + col + 1]);
    }
#pragma unroll
    for (int mt = 0; mt < 2; mt++) {
        const int row = bm + wm * 32 + mt * 16 + r;
#pragma unroll
        for (int nt = 0; nt < 8; nt++) {
            const int col = bn + wn * 64 + nt * 8 + 2 * c;
            const size_t b0 = (size_t)row * (NL * FL) + (size_t)l * FL + col;
            const size_t b1 = b0 + (size_t)8 * (NL * FL);
            const float h0 = acc[mt][nt][0], h1 = acc[mt][nt][1];
            const float h2 = acc[mt][nt][2], h3 = acc[mt][nt][3];
            if (H) {
                *(float2*)(H + b0) = make_float2(h0, h1);
                *(float2*)(H + b1) = make_float2(h2, h3);
            }
            const float a0 = (h0 > thr0[nt]) ? h0 : 0.0f;
            const float a1 = (h1 > thr1[nt]) ? h1 : 0.0f;
            const float a2 = (h2 > thr0[nt]) ? h2 : 0.0f;
            const float a3 = (h3 > thr1[nt]) ? h3 : 0.0f;
            *(float2*)(A + b0) = make_float2(a0, a1);
            *(float2*)(A + b1) = make_float2(a2, a3);
            *(__half2*)(AH16 + b0) = __floats2half2_rn(a0, a1);
            *(__half2*)(AH16 + b1) = __floats2half2_rn(a2, a3);
            // flag flip-risk elements for exact fp32 recompute
            if (fabsf(h0 - thr0[nt]) < DELTA) {
                int s0 = atomicAdd(&g_fix_count, 1);
                if (s0 < FIX_CAP) g_fix_list[s0] = (int)b0;
            }
            if (fabsf(h1 - thr1[nt]) < DELTA) {
                int s1 = atomicAdd(&g_fix_count, 1);
                if (s1 < FIX_CAP) g_fix_list[s1] = (int)(b0 + 1);
            }
            if (fabsf(h2 - thr0[nt]) < DELTA) {
                int s2 = atomicAdd(&g_fix_count, 1);
                if (s2 < FIX_CAP) g_fix_list[s2] = (int)b1;
            }
            if (fabsf(h3 - thr1[nt]) < DELTA) {
                int s3 = atomicAdd(&g_fix_count, 1);
                if (s3 < FIX_CAP) g_fix_list[s3] = (int)(b1 + 1);
            }
        }
    }
}

// ---------------- fixup: exact fp32 recompute of flagged elements ----------
__global__ __launch_bounds__(256)
void fixup(const float* __restrict__ x, const float* __restrict__ weT,
           const float* __restrict__ TH, float* __restrict__ A,
           __half* __restrict__ AH16) {
    const int nwarps = gridDim.x * (blockDim.x >> 5);
    const int gw = blockIdx.x * (blockDim.x >> 5) + (threadIdx.x >> 5);
    const int lane = threadIdx.x & 31;
    const int n = min(g_fix_count, FIX_CAP);
    for (int e = gw; e < n; e += nwarps) {
        const int idx = g_fix_list[e];
        const int t = idx / (NL * FL);
        const int rm = idx % (NL * FL);
        const int l = rm / FL, f = rm % FL;
        const float* xr = x + ((size_t)t * NL + l) * DM;
        const float* wr = weT + ((size_t)l * FL + f) * DM;
        float s = 0.0f;
#pragma unroll 4
        for (int d = lane; d < DM; d += 32) s = fmaf(xr[d], wr[d], s);
#pragma unroll
        for (int o = 16; o; o >>= 1) s += __shfl_xor_sync(0xFFFFFFFFu, s, o);
        if (lane == 0) {
            const float thr = expf(TH[l * FL + f]);
            const float a = (s > thr) ? s : 0.0f;
            A[idx] = a;
            AH16[idx] = __float2half_rn(a);
        }
    }
}

// ---------------- decode: CTA 128x128x32, 2 CTAs/SM (unchanged) -------------
__global__ __launch_bounds__(256, 2)
void decode_fp16(const __half* __restrict__ AH, const __half* __restrict__ WD,
                 float* __restrict__ XH) {
    extern __shared__ __half sm[];
    const uint32_t sb = smem_u32(sm);

    const int j  = (NL - 1) - blockIdx.z;
    const int bm = blockIdx.y * DM2;
    const int bn = blockIdx.x * DBN;
    const int KT = (j + 1) * (FL / DBK);

    const int tid  = threadIdx.x;
    const int lane = tid & 31, wid = tid >> 5;
    const int wm = wid & 3, wn = wid >> 2;
    const int r = lane >> 2, c = lane & 3;
    const int lr = lane & 15, lc = lane >> 4;

    const __half* gah = AH + (size_t)(bm + (tid >> 1)) * (NL * FL) + (tid & 1) * 16;
    const uint32_t a_off_t = (uint32_t)(tid >> 1) * ASTR + (uint32_t)(tid & 1) * 16;

    const __half* wj  = WD + (size_t)j * FL * DM;
    const size_t wd_istride = (size_t)NL * FL * DM;
    const int brow = tid >> 3, bq = (tid & 7) * 16;
    const uint32_t b_row_off = (uint32_t)brow * BSTR + bq;

    float acc[2][8][4];
#pragma unroll
    for (int mt = 0; mt < 2; mt++)
#pragma unroll
        for (int nt = 0; nt < 8; nt++)
#pragma unroll
            for (int q = 0; q < 4; q++) acc[mt][nt][q] = 0.0f;

#define DEC_ISSUE(KN, ST)                                                       \
    do {                                                                        \
        const uint32_t ao = a_off_t + (uint32_t)(ST) * SA2;                     \
        cp16(sb + 2 * ao,       gah + (KN) * DBK);                              \
        cp16(sb + 2 * (ao + 8), gah + (KN) * DBK + 8);                          \
        const int ii = (KN) >> 6, f0 = ((KN) & 63) * DBK;                       \
        const __half* sbp = wj + (size_t)ii * wd_istride +                      \
                            (size_t)(f0 + brow) * DM + bn + bq;                 \
        const uint32_t bo = DEC_B_BASE + b_row_off + (uint32_t)(ST) * SB;       \
        cp16(sb + 2 * bo, sbp);                                                 \
        cp16(sb + 2 * (bo + 8), sbp + 8);                                       \
        asm volatile("cp.async.commit_group;");                                 \
    } while (0)

    DEC_ISSUE(0, 0);
    DEC_ISSUE(1, 1);

    for (int kt = 0; kt < KT; kt++) {
        if (kt + 1 < KT) asm volatile("cp.async.wait_group 1;");
        else             asm volatile("cp.async.wait_group 0;");
        __syncthreads();
        if (kt + 2 < KT) {
            const int kn = kt + 2;
            DEC_ISSUE(kn, kn % 3);
        }
        const int st = kt % 3;
        const uint32_t a_b = sb + 2 * ((uint32_t)st * SA2);
        const uint32_t b_b = sb + 2 * (DEC_B_BASE + (uint32_t)st * SB);

#pragma unroll
        for (int s = 0; s < 2; s++) {
            uint32_t a[2][4], bb[4][4];
#pragma unroll
            for (int mt = 0; mt < 2; mt++) {
                const uint32_t ao =
                    2 * ((uint32_t)(wm * 32 + mt * 16 + lr) * ASTR + s * 16 + 8 * lc);
                ldsm_x4(a[mt], a_b + ao);
            }
#pragma unroll
            for (int g = 0; g < 4; g++) {
                const uint32_t bo =
                    2 * ((uint32_t)(s * 16 + lr) * BSTR + wn * 64 + g * 16 + 8 * lc);
                ldsm_x4t(bb[g], b_b + bo);
            }
#pragma unroll
            for (int mt = 0; mt < 2; mt++)
#pragma unroll
                for (int g = 0; g < 4; g++) {
                    mma_f16(acc[mt][2 * g],     a[mt], &bb[g][0]);
                    mma_f16(acc[mt][2 * g + 1], a[mt], &bb[g][2]);
                }
        }
    }
#undef DEC_ISSUE

#pragma unroll
    for (int mt = 0; mt < 2; mt++) {
        const int row = bm + wm * 32 + mt * 16 + r;
#pragma unroll
        for (int nt = 0; nt < 8; nt++) {
            const int col = bn + wn * 64 + nt * 8 + 2 * c;
            float* p = XH + (size_t)row * (NL * DM) + (size_t)j * DM + col;
            *(float2*)p = make_float2(acc[mt][nt][0], acc[mt][nt][1]);
            *(float2*)(p + (size_t)8 * (NL * DM)) =
                make_float2(acc[mt][nt][2], acc[mt][nt][3]);
        }
    }
}

// ---------------- host ----------------
extern "C" void kernel_launch(void* const* d_in, const int* in_sizes, int n_in,
                              void* d_out, int out_size) {
    const float* x  = (const float*)d_in[0];
    const float* we = (const float*)d_in[1];
    const float* wd = (const float*)d_in[2];
    const float* th = (const float*)d_in[3];
    float* out = (float*)d_out;

    const long long HE = (long long)T_TOK * NL * FL;
    const long long XE = (long long)T_TOK * NL * DM;

    float *hp, *ap, *xp;
    if ((long long)out_size >= 2 * HE + XE) {
        hp = out; ap = out + HE; xp = out + 2 * HE;
    } else {
        hp = nullptr;
        float* sp = nullptr;
        cudaGetSymbolAddress((void**)&sp, g_acts_scratch);
        ap = sp; xp = out;
    }

    __half *wd16, *ah, *xh, *xl, *weh;
    float* weT;
    cudaGetSymbolAddress((void**)&wd16, g_wd16);
    cudaGetSymbolAddress((void**)&ah, g_ah);
    cudaGetSymbolAddress((void**)&xh, g_xh);
    cudaGetSymbolAddress((void**)&xl, g_xl);
    cudaGetSymbolAddress((void**)&weh, g_weh);
    cudaGetSymbolAddress((void**)&weT, g_weT);

    cudaFuncSetAttribute(decode_fp16, cudaFuncAttributeMaxDynamicSharedMemorySize,
                         SMEM_DEC_BYTES);
    cudaFuncSetAttribute(encode_fused, cudaFuncAttributeMaxDynamicSharedMemorySize,
                         SMEM_ENC_BYTES);

    prep_xwe<<<NB_PREP, 256>>>(x, we, xh, xl, weh, weT);
    encode_fused<<<NWD + ENC_BLOCKS, 256, SMEM_ENC_BYTES>>>(
        xh, xl, weh, th, hp, ap, ah, wd, wd16);
    fixup<<<296, 256>>>(x, weT, th, ap, ah);
    decode_fp16<<<dim3(DM / DBN, T_TOK / DM2, NL), 256, SMEM_DEC_BYTES>>>(ah, wd16, xp);
}

// round 14
// speedup vs baseline: 5.5893x; 1.0677x over previous
#include <cuda_runtime.h>
#include <cuda_fp16.h>
#include <math.h>
#include <stdint.h>

#define T_TOK 2048
#define NL    12
#define DM    768
#define FL    2048

#define DBN 128
#define DBK 32
#define ASTR 40
#define BSTR 136
#define SB (DBK * BSTR)   // 4352 halves per B stage

#define DM2 128
#define SA2 (DM2 * ASTR)  // 5120 halves per A stage

// decode smem (halves)
#define DEC_B_BASE (3 * SA2)
#define SMEM_DEC_BYTES ((3 * SA2 + 3 * SB) * 2)         // 56832

// encode smem (halves): XH, XL (3 stages each), WH (3 stages)
#define EXH_BASE 0
#define EXL_BASE (3 * SA2)
#define EWH_BASE (6 * SA2)
#define SMEM_ENC_BYTES ((6 * SA2 + 3 * SB) * 2)         // 87552

#define NWD 78
#define ENC_BLOCKS (16 * 16 * NL)   // 3072

#define FIX_CAP (1 << 22)
#define DELTA 8e-4f

__device__ __half g_wd16[(size_t)NL * NL * FL * DM];
__device__ __half g_ah[(size_t)T_TOK * NL * FL];
__device__ __half g_xh[(size_t)T_TOK * NL * DM];
__device__ __half g_xl[(size_t)T_TOK * NL * DM];
__device__ __half g_weh[(size_t)NL * DM * FL];
__device__ float  g_weT[(size_t)NL * FL * DM];
__device__ float  g_acts_scratch[(size_t)T_TOK * NL * FL];
__device__ int    g_fix_count;
__device__ int    g_fix_list[FIX_CAP];

// ---------------- helpers ----------------
__device__ __forceinline__ uint32_t smem_u32(const void* p) {
    return (uint32_t)__cvta_generic_to_shared(p);
}
__device__ __forceinline__ void cp16(uint32_t d, const void* s) {
    asm volatile("cp.async.cg.shared.global [%0], [%1], 16;" :: "r"(d), "l"(s));
}
__device__ __forceinline__ void ldsm_x4(uint32_t* r, uint32_t a) {
    asm volatile("ldmatrix.sync.aligned.m8n8.x4.shared.b16 {%0,%1,%2,%3}, [%4];"
                 : "=r"(r[0]), "=r"(r[1]), "=r"(r[2]), "=r"(r[3]) : "r"(a));
}
__device__ __forceinline__ void ldsm_x4t(uint32_t* r, uint32_t a) {
    asm volatile("ldmatrix.sync.aligned.m8n8.x4.trans.shared.b16 {%0,%1,%2,%3}, [%4];"
                 : "=r"(r[0]), "=r"(r[1]), "=r"(r[2]), "=r"(r[3]) : "r"(a));
}
__device__ __forceinline__ void mma_f16(float* d, const uint32_t* a, const uint32_t* b) {
    asm volatile(
        "mma.sync.aligned.m16n8k16.row.col.f32.f16.f16.f32 "
        "{%0,%1,%2,%3}, {%4,%5,%6,%7}, {%8,%9}, {%0,%1,%2,%3};"
        : "+f"(d[0]), "+f"(d[1]), "+f"(d[2]), "+f"(d[3])
        : "r"(a[0]), "r"(a[1]), "r"(a[2]), "r"(a[3]), "r"(b[0]), "r"(b[1]));
}
__device__ __forceinline__ void cvt4(__half* h4, float4 v) {
    h4[0] = __float2half_rn(v.x); h4[1] = __float2half_rn(v.y);
    h4[2] = __float2half_rn(v.z); h4[3] = __float2half_rn(v.w);
}

// ---------------- prep ----------------
#define NB_X  (T_TOK * NL * DM / 1024)
#define NB_TR (NL * (DM / 32) * (FL / 32))
#define NB_PREP (2 * NB_X + NB_TR)

__global__ __launch_bounds__(256)
void prep_xwe(const float* __restrict__ x, const float* __restrict__ we,
              __half* __restrict__ xh, __half* __restrict__ xl,
              __half* __restrict__ weh, float* __restrict__ weT) {
    const int b = blockIdx.x;
    if (b == 0 && threadIdx.x == 0) g_fix_count = 0;

    if (b < NB_X) {
        const size_t idx = ((size_t)b * 256 + threadIdx.x) * 4;
        float4 v = *(const float4*)(x + idx);
        __half h4[4]; cvt4(h4, v);
        __half l4[4] = {__float2half_rn(v.x - __half2float(h4[0])),
                        __float2half_rn(v.y - __half2float(h4[1])),
                        __float2half_rn(v.z - __half2float(h4[2])),
                        __float2half_rn(v.w - __half2float(h4[3]))};
        *(uint2*)(xh + idx) = *(uint2*)h4;
        *(uint2*)(xl + idx) = *(uint2*)l4;
    } else if (b < 2 * NB_X) {
        const size_t idx = ((size_t)(b - NB_X) * 256 + threadIdx.x) * 4;
        float4 v = *(const float4*)(we + idx);
        __half h4[4]; cvt4(h4, v);
        *(uint2*)(weh + idx) = *(uint2*)h4;
    } else {
        __shared__ float t[32][33];
        const int bt = b - 2 * NB_X;
        const int l  = bt / ((DM / 32) * (FL / 32));
        const int rm = bt % ((DM / 32) * (FL / 32));
        const int d0 = (rm / (FL / 32)) * 32;
        const int f0 = (rm % (FL / 32)) * 32;
        const int tx = threadIdx.x & 31, ty = threadIdx.x >> 5;
        const float* src = we + (size_t)l * DM * FL;
        float* dst = weT + (size_t)l * FL * DM;
#pragma unroll
        for (int r = 0; r < 32; r += 8)
            t[ty + r][tx] = src[(size_t)(d0 + ty + r) * FL + f0 + tx];
        __syncthreads();
#pragma unroll
        for (int r = 0; r < 32; r += 8)
            dst[(size_t)(f0 + ty + r) * DM + d0 + tx] = t[tx][ty + r];
    }
}

// ---------------- encode (2-product fp16 mma) + fused wd convert -------------
__global__ __launch_bounds__(256, 2)
void encode_fused(const __half* __restrict__ XHp, const __half* __restrict__ XLp,
                  const __half* __restrict__ WHp,
                  const float* __restrict__ TH, float* __restrict__ H,
                  float* __restrict__ A, __half* __restrict__ AH16,
                  const float* __restrict__ WDsrc, __half* __restrict__ WD16) {
    if (blockIdx.x < NWD) {
        const int p = blockIdx.x;
        int i = 0, rem = p;
        while (rem >= NL - i) { rem -= NL - i; i++; }
        const size_t zoff = (size_t)(i * NL + i + rem) * FL * DM;
        const float4* src = (const float4*)(WDsrc + zoff);
        uint2* dst = (uint2*)(WD16 + zoff);
        const int N4 = FL * DM / 4;
        for (int q = threadIdx.x; q < N4; q += 1024) {
            float4 v0 = src[q], v1 = src[q + 256], v2 = src[q + 512], v3 = src[q + 768];
            __half h0[4], h1[4], h2[4], h3[4];
            cvt4(h0, v0); cvt4(h1, v1); cvt4(h2, v2); cvt4(h3, v3);
            dst[q]       = *(uint2*)h0;
            dst[q + 256] = *(uint2*)h1;
            dst[q + 512] = *(uint2*)h2;
            dst[q + 768] = *(uint2*)h3;
        }
        return;
    }

    extern __shared__ __half sm[];
    const uint32_t sb = smem_u32(sm);

    const int bid = blockIdx.x - NWD;
    const int l  = bid >> 8;
    const int bm = ((bid >> 4) & 15) * DM2;
    const int bn = (bid & 15) * DBN;
    const int KT = DM / DBK;

    const int tid  = threadIdx.x;
    const int lane = tid & 31, wid = tid >> 5;
    const int wm = wid & 3, wn = wid >> 2;
    const int r = lane >> 2, c = lane & 3;
    const int lr = lane & 15, lc = lane >> 4;

    const __half* gxh = XHp + ((size_t)(bm + (tid >> 1)) * NL + l) * DM + (tid & 1) * 16;
    const __half* gxl = XLp + ((size_t)(bm + (tid >> 1)) * NL + l) * DM + (tid & 1) * 16;
    const uint32_t a_off_t = (uint32_t)(tid >> 1) * ASTR + (uint32_t)(tid & 1) * 16;

    const __half* gwh = WHp + (size_t)l * DM * FL;
    const int brow = tid >> 3, bq = (tid & 7) * 16;
    const uint32_t b_row_off = (uint32_t)brow * BSTR + bq;

    float acc[2][8][4];
#pragma unroll
    for (int mt = 0; mt < 2; mt++)
#pragma unroll
        for (int nt = 0; nt < 8; nt++)
#pragma unroll
            for (int q = 0; q < 4; q++) acc[mt][nt][q] = 0.0f;

#define ENC_ISSUE(KN, ST)                                                        \
    do {                                                                         \
        const uint32_t ao = a_off_t + (uint32_t)(ST) * SA2;                      \
        cp16(sb + 2 * (EXH_BASE + ao),     gxh + (KN) * DBK);                    \
        cp16(sb + 2 * (EXH_BASE + ao + 8), gxh + (KN) * DBK + 8);                \
        cp16(sb + 2 * (EXL_BASE + ao),     gxl + (KN) * DBK);                    \
        cp16(sb + 2 * (EXL_BASE + ao + 8), gxl + (KN) * DBK + 8);                \
        const __half* wb = gwh + (size_t)((KN) * DBK + brow) * FL + bn + bq;     \
        const uint32_t bo = b_row_off + (uint32_t)(ST) * SB;                     \
        cp16(sb + 2 * (EWH_BASE + bo),     wb);                                  \
        cp16(sb + 2 * (EWH_BASE + bo + 8), wb + 8);                              \
        asm volatile("cp.async.commit_group;");                                  \
    } while (0)

    ENC_ISSUE(0, 0);
    ENC_ISSUE(1, 1);

    for (int kt = 0; kt < KT; kt++) {
        if (kt + 1 < KT) asm volatile("cp.async.wait_group 1;");
        else             asm volatile("cp.async.wait_group 0;");
        __syncthreads();
        if (kt + 2 < KT) {
            const int kn = kt + 2;
            ENC_ISSUE(kn, kn % 3);
        }
        const int st = kt % 3;
        const uint32_t ah_b = sb + 2 * (EXH_BASE + (uint32_t)st * SA2);
        const uint32_t al_b = sb + 2 * (EXL_BASE + (uint32_t)st * SA2);
        const uint32_t bh_b = sb + 2 * (EWH_BASE + (uint32_t)st * SB);

#pragma unroll
        for (int s = 0; s < 2; s++) {
            uint32_t ah[2][4], al[2][4], fb[4][4];
            const uint32_t aoff = 2 * (uint32_t)((wm * 32 + lr) * ASTR + s * 16 + 8 * lc);
            const uint32_t boff = 2 * (uint32_t)((s * 16 + lr) * BSTR + wn * 64 + 8 * lc);
#pragma unroll
            for (int mt = 0; mt < 2; mt++) {
                ldsm_x4(ah[mt], ah_b + aoff + 2 * (uint32_t)(mt * 16 * ASTR));
                ldsm_x4(al[mt], al_b + aoff + 2 * (uint32_t)(mt * 16 * ASTR));
            }
#pragma unroll
            for (int g = 0; g < 4; g++)
                ldsm_x4t(fb[g], bh_b + boff + 2 * (uint32_t)(g * 16));
#pragma unroll
            for (int mt = 0; mt < 2; mt++)
#pragma unroll
                for (int g = 0; g < 4; g++) {
                    mma_f16(acc[mt][2 * g],     ah[mt], &fb[g][0]);
                    mma_f16(acc[mt][2 * g + 1], ah[mt], &fb[g][2]);
                    mma_f16(acc[mt][2 * g],     al[mt], &fb[g][0]);
                    mma_f16(acc[mt][2 * g + 1], al[mt], &fb[g][2]);
                }
        }
    }
#undef ENC_ISSUE

    float thr0[8], thr1[8];
#pragma unroll
    for (int nt = 0; nt < 8; nt++) {
        const int col = bn + wn * 64 + nt * 8 + 2 * c;
        thr0[nt] = expf(TH[l * FL + col]);
        thr1[nt] = expf(TH[l * FL + col + 1]);
    }
#pragma unroll
    for (int mt = 0; mt < 2; mt++) {
        const int row = bm + wm * 32 + mt * 16 + r;
#pragma unroll
        for (int nt = 0; nt < 8; nt++) {
            const int col = bn + wn * 64 + nt * 8 + 2 * c;
            const size_t b0 = (size_t)row * (NL * FL) + (size_t)l * FL + col;
            const size_t b1 = b0 + (size_t)8 * (NL * FL);
            const float h0 = acc[mt][nt][0], h1 = acc[mt][nt][1];
            const float h2 = acc[mt][nt][2], h3 = acc[mt][nt][3];
            if (H) {
                *(float2*)(H + b0) = make_float2(h0, h1);
                *(float2*)(H + b1) = make_float2(h2, h3);
            }
            const float a0 = (h0 > thr0[nt]) ? h0 : 0.0f;
            const float a1 = (h1 > thr1[nt]) ? h1 : 0.0f;
            const float a2 = (h2 > thr0[nt]) ? h2 : 0.0f;
            const float a3 = (h3 > thr1[nt]) ? h3 : 0.0f;
            *(float2*)(A + b0) = make_float2(a0, a1);
            *(float2*)(A + b1) = make_float2(a2, a3);
            *(__half2*)(AH16 + b0) = __floats2half2_rn(a0, a1);
            *(__half2*)(AH16 + b1) = __floats2half2_rn(a2, a3);
            if (fabsf(h0 - thr0[nt]) < DELTA) {
                int s0 = atomicAdd(&g_fix_count, 1);
                if (s0 < FIX_CAP) g_fix_list[s0] = (int)b0;
            }
            if (fabsf(h1 - thr1[nt]) < DELTA) {
                int s1 = atomicAdd(&g_fix_count, 1);
                if (s1 < FIX_CAP) g_fix_list[s1] = (int)(b0 + 1);
            }
            if (fabsf(h2 - thr0[nt]) < DELTA) {
                int s2 = atomicAdd(&g_fix_count, 1);
                if (s2 < FIX_CAP) g_fix_list[s2] = (int)b1;
            }
            if (fabsf(h3 - thr1[nt]) < DELTA) {
                int s3 = atomicAdd(&g_fix_count, 1);
                if (s3 < FIX_CAP) g_fix_list[s3] = (int)(b1 + 1);
            }
        }
    }
}

// ---------------- fixup ----------------
__global__ __launch_bounds__(256)
void fixup(const float* __restrict__ x, const float* __restrict__ weT,
           const float* __restrict__ TH, float* __restrict__ A,
           __half* __restrict__ AH16) {
    const int nwarps = gridDim.x * (blockDim.x >> 5);
    const int gw = blockIdx.x * (blockDim.x >> 5) + (threadIdx.x >> 5);
    const int lane = threadIdx.x & 31;
    const int n = min(g_fix_count, FIX_CAP);
    for (int e = gw; e < n; e += nwarps) {
        const int idx = g_fix_list[e];
        const int t = idx / (NL * FL);
        const int rm = idx % (NL * FL);
        const int l = rm / FL, f = rm % FL;
        const float* xr = x + ((size_t)t * NL + l) * DM;
        const float* wr = weT + ((size_t)l * FL + f) * DM;
        float s = 0.0f;
#pragma unroll 4
        for (int d = lane; d < DM; d += 32) s = fmaf(xr[d], wr[d], s);
#pragma unroll
        for (int o = 16; o; o >>= 1) s += __shfl_xor_sync(0xFFFFFFFFu, s, o);
        if (lane == 0) {
            const float thr = expf(TH[l * FL + f]);
            const float a = (s > thr) ? s : 0.0f;
            A[idx] = a;
            AH16[idx] = __float2half_rn(a);
        }
    }
}

// ---------------- decode: CTA 128x128x32, 512 thr (16 warps 4m x 4n), 2/SM --
__global__ __launch_bounds__(512, 2)
void decode_fp16(const __half* __restrict__ AH, const __half* __restrict__ WD,
                 float* __restrict__ XH) {
    extern __shared__ __half sm[];
    const uint32_t sb = smem_u32(sm);

    const int j  = (NL - 1) - blockIdx.z;
    const int bm = blockIdx.y * DM2;
    const int bn = blockIdx.x * DBN;
    const int KT = (j + 1) * (FL / DBK);

    const int tid  = threadIdx.x;
    const int lane = tid & 31, wid = tid >> 5;
    const int wm = wid & 3, wn = wid >> 2;   // 4m x 4n, warp tile 32x32
    const int r = lane >> 2, c = lane & 3;
    const int lr = lane & 15, lc = lane >> 4;

    // A: 128 rows x 32 halves = 512 cp16; thread -> row tid>>2, chunk (tid&3)*8
    const __half* gah = AH + (size_t)(bm + (tid >> 2)) * (NL * FL) + (tid & 3) * 8;
    const uint32_t a_off_t = (uint32_t)(tid >> 2) * ASTR + (uint32_t)(tid & 3) * 8;

    // B: 32 rows x 128 halves = 512 cp16; thread -> row tid>>4, chunk (tid&15)*8
    const __half* wj  = WD + (size_t)j * FL * DM;
    const size_t wd_istride = (size_t)NL * FL * DM;
    const int brow = tid >> 4, bq = (tid & 15) * 8;
    const uint32_t b_row_off = (uint32_t)brow * BSTR + bq;

    float acc[2][4][4];
#pragma unroll
    for (int mt = 0; mt < 2; mt++)
#pragma unroll
        for (int nt = 0; nt < 4; nt++)
#pragma unroll
            for (int q = 0; q < 4; q++) acc[mt][nt][q] = 0.0f;

#define DEC_ISSUE(KN, ST)                                                       \
    do {                                                                        \
        cp16(sb + 2 * (a_off_t + (uint32_t)(ST) * SA2), gah + (KN) * DBK);      \
        const int ii = (KN) >> 6, f0 = ((KN) & 63) * DBK;                       \
        const __half* sbp = wj + (size_t)ii * wd_istride +                      \
                            (size_t)(f0 + brow) * DM + bn + bq;                 \
        cp16(sb + 2 * (DEC_B_BASE + b_row_off + (uint32_t)(ST) * SB), sbp);     \
        asm volatile("cp.async.commit_group;");                                 \
    } while (0)

    DEC_ISSUE(0, 0);
    DEC_ISSUE(1, 1);

    for (int kt = 0; kt < KT; kt++) {
        if (kt + 1 < KT) asm volatile("cp.async.wait_group 1;");
        else             asm volatile("cp.async.wait_group 0;");
        __syncthreads();
        if (kt + 2 < KT) {
            const int kn = kt + 2;
            DEC_ISSUE(kn, kn % 3);
        }
        const int st = kt % 3;
        const uint32_t a_b = sb + 2 * ((uint32_t)st * SA2);
        const uint32_t b_b = sb + 2 * (DEC_B_BASE + (uint32_t)st * SB);

#pragma unroll
        for (int s = 0; s < 2; s++) {
            uint32_t a[2][4], bb[2][4];
#pragma unroll
            for (int mt = 0; mt < 2; mt++) {
                const uint32_t ao =
                    2 * ((uint32_t)(wm * 32 + mt * 16 + lr) * ASTR + s * 16 + 8 * lc);
                ldsm_x4(a[mt], a_b + ao);
            }
#pragma unroll
            for (int g = 0; g < 2; g++) {
                const uint32_t bo =
                    2 * ((uint32_t)(s * 16 + lr) * BSTR + wn * 32 + g * 16 + 8 * lc);
                ldsm_x4t(bb[g], b_b + bo);
            }
#pragma unroll
            for (int mt = 0; mt < 2; mt++)
#pragma unroll
                for (int g = 0; g < 2; g++) {
                    mma_f16(acc[mt][2 * g],     a[mt], &bb[g][0]);
                    mma_f16(acc[mt][2 * g + 1], a[mt], &bb[g][2]);
                }
        }
    }
#undef DEC_ISSUE

#pragma unroll
    for (int mt = 0; mt < 2; mt++) {
        const int row = bm + wm * 32 + mt * 16 + r;
#pragma unroll
        for (int nt = 0; nt < 4; nt++) {
            const int col = bn + wn * 32 + nt * 8 + 2 * c;
            float* p = XH + (size_t)row * (NL * DM) + (size_t)j * DM + col;
            *(float2*)p = make_float2(acc[mt][nt][0], acc[mt][nt][1]);
            *(float2*)(p + (size_t)8 * (NL * DM)) =
                make_float2(acc[mt][nt][2], acc[mt][nt][3]);
        }
    }
}

// ---------------- host ----------------
extern "C" void kernel_launch(void* const* d_in, const int* in_sizes, int n_in,
                              void* d_out, int out_size) {
    const float* x  = (const float*)d_in[0];
    const float* we = (const float*)d_in[1];
    const float* wd = (const float*)d_in[2];
    const float* th = (const float*)d_in[3];
    float* out = (float*)d_out;

    const long long HE = (long long)T_TOK * NL * FL;
    const long long XE = (long long)T_TOK * NL * DM;

    float *hp, *ap, *xp;
    if ((long long)out_size >= 2 * HE + XE) {
        hp = out; ap = out + HE; xp = out + 2 * HE;
    } else {
        hp = nullptr;
        float* sp = nullptr;
        cudaGetSymbolAddress((void**)&sp, g_acts_scratch);
        ap = sp; xp = out;
    }

    __half *wd16, *ah, *xh, *xl, *weh;
    float* weT;
    cudaGetSymbolAddress((void**)&wd16, g_wd16);
    cudaGetSymbolAddress((void**)&ah, g_ah);
    cudaGetSymbolAddress((void**)&xh, g_xh);
    cudaGetSymbolAddress((void**)&xl, g_xl);
    cudaGetSymbolAddress((void**)&weh, g_weh);
    cudaGetSymbolAddress((void**)&weT, g_weT);

    cudaFuncSetAttribute(decode_fp16, cudaFuncAttributeMaxDynamicSharedMemorySize,
                         SMEM_DEC_BYTES);
    cudaFuncSetAttribute(encode_fused, cudaFuncAttributeMaxDynamicSharedMemorySize,
                         SMEM_ENC_BYTES);

    prep_xwe<<<NB_PREP, 256>>>(x, we, xh, xl, weh, weT);
    encode_fused<<<NWD + ENC_BLOCKS, 256, SMEM_ENC_BYTES>>>(
        xh, xl, weh, th, hp, ap, ah, wd, wd16);
    fixup<<<296, 256>>>(x, weT, th, ap, ah);
    decode_fp16<<<dim3(DM / DBN, T_TOK / DM2, NL), 512, SMEM_DEC_BYTES>>>(ah, wd16, xp);
}

// round 15
// speedup vs baseline: 5.5914x; 1.0004x over previous
#include <cuda_runtime.h>
#include <cuda_fp16.h>
#include <math.h>
#include <stdint.h>

#define T_TOK 2048
#define NL    12
#define DM    768
#define FL    2048

#define DBN 128
#define DBK 32
#define ASTR 40
#define BSTR 136
#define SB (DBK * BSTR)   // 4352 halves per B stage

#define DM2 128
#define SA2 (DM2 * ASTR)  // 5120 halves per A stage

// decode smem (halves)
#define DEC_B_BASE (3 * SA2)
#define SMEM_DEC_BYTES ((3 * SA2 + 3 * SB) * 2)         // 56832

// encode smem (halves): XH, XL (3 stages each), WH (3 stages)
#define EXH_BASE 0
#define EXL_BASE (3 * SA2)
#define EWH_BASE (6 * SA2)
#define SMEM_ENC_BYTES ((6 * SA2 + 3 * SB) * 2)         // 87552

#define NWD 78
#define ENC_BLOCKS (16 * 16 * NL)   // 3072

#define FIX_CAP (1 << 22)
#define DELTA 8e-4f

__device__ __half g_wd16[(size_t)NL * NL * FL * DM];
__device__ __half g_ah[(size_t)T_TOK * NL * FL];
__device__ __half g_xh[(size_t)T_TOK * NL * DM];
__device__ __half g_xl[(size_t)T_TOK * NL * DM];
__device__ __half g_weh[(size_t)NL * DM * FL];
__device__ float  g_weT[(size_t)NL * FL * DM];
__device__ float  g_acts_scratch[(size_t)T_TOK * NL * FL];
__device__ int    g_fix_count;
__device__ int    g_fix_list[FIX_CAP];

// ---------------- helpers ----------------
__device__ __forceinline__ uint32_t smem_u32(const void* p) {
    return (uint32_t)__cvta_generic_to_shared(p);
}
__device__ __forceinline__ void cp16(uint32_t d, const void* s) {
    asm volatile("cp.async.cg.shared.global [%0], [%1], 16;" :: "r"(d), "l"(s));
}
__device__ __forceinline__ void ldsm_x4(uint32_t* r, uint32_t a) {
    asm volatile("ldmatrix.sync.aligned.m8n8.x4.shared.b16 {%0,%1,%2,%3}, [%4];"
                 : "=r"(r[0]), "=r"(r[1]), "=r"(r[2]), "=r"(r[3]) : "r"(a));
}
__device__ __forceinline__ void ldsm_x4t(uint32_t* r, uint32_t a) {
    asm volatile("ldmatrix.sync.aligned.m8n8.x4.trans.shared.b16 {%0,%1,%2,%3}, [%4];"
                 : "=r"(r[0]), "=r"(r[1]), "=r"(r[2]), "=r"(r[3]) : "r"(a));
}
__device__ __forceinline__ void mma_f16(float* d, const uint32_t* a, const uint32_t* b) {
    asm volatile(
        "mma.sync.aligned.m16n8k16.row.col.f32.f16.f16.f32 "
        "{%0,%1,%2,%3}, {%4,%5,%6,%7}, {%8,%9}, {%0,%1,%2,%3};"
        : "+f"(d[0]), "+f"(d[1]), "+f"(d[2]), "+f"(d[3])
        : "r"(a[0]), "r"(a[1]), "r"(a[2]), "r"(a[3]), "r"(b[0]), "r"(b[1]));
}
__device__ __forceinline__ void cvt4(__half* h4, float4 v) {
    h4[0] = __float2half_rn(v.x); h4[1] = __float2half_rn(v.y);
    h4[2] = __float2half_rn(v.z); h4[3] = __float2half_rn(v.w);
}

// ---------------- prep ----------------
#define NB_X  (T_TOK * NL * DM / 1024)
#define NB_TR (NL * (DM / 32) * (FL / 32))
#define NB_PREP (2 * NB_X + NB_TR)

__global__ __launch_bounds__(256)
void prep_xwe(const float* __restrict__ x, const float* __restrict__ we,
              __half* __restrict__ xh, __half* __restrict__ xl,
              __half* __restrict__ weh, float* __restrict__ weT) {
    const int b = blockIdx.x;
    if (b == 0 && threadIdx.x == 0) g_fix_count = 0;

    if (b < NB_X) {
        const size_t idx = ((size_t)b * 256 + threadIdx.x) * 4;
        float4 v = *(const float4*)(x + idx);
        __half h4[4]; cvt4(h4, v);
        __half l4[4] = {__float2half_rn(v.x - __half2float(h4[0])),
                        __float2half_rn(v.y - __half2float(h4[1])),
                        __float2half_rn(v.z - __half2float(h4[2])),
                        __float2half_rn(v.w - __half2float(h4[3]))};
        *(uint2*)(xh + idx) = *(uint2*)h4;
        *(uint2*)(xl + idx) = *(uint2*)l4;
    } else if (b < 2 * NB_X) {
        const size_t idx = ((size_t)(b - NB_X) * 256 + threadIdx.x) * 4;
        float4 v = *(const float4*)(we + idx);
        __half h4[4]; cvt4(h4, v);
        *(uint2*)(weh + idx) = *(uint2*)h4;
    } else {
        __shared__ float t[32][33];
        const int bt = b - 2 * NB_X;
        const int l  = bt / ((DM / 32) * (FL / 32));
        const int rm = bt % ((DM / 32) * (FL / 32));
        const int d0 = (rm / (FL / 32)) * 32;
        const int f0 = (rm % (FL / 32)) * 32;
        const int tx = threadIdx.x & 31, ty = threadIdx.x >> 5;
        const float* src = we + (size_t)l * DM * FL;
        float* dst = weT + (size_t)l * FL * DM;
#pragma unroll
        for (int r = 0; r < 32; r += 8)
            t[ty + r][tx] = src[(size_t)(d0 + ty + r) * FL + f0 + tx];
        __syncthreads();
#pragma unroll
        for (int r = 0; r < 32; r += 8)
            dst[(size_t)(f0 + ty + r) * DM + d0 + tx] = t[tx][ty + r];
    }
}

// ---------------- encode: 512 thr, 16 warps (4m x 4n), warp 32x32, 2 CTA/SM --
__global__ __launch_bounds__(512, 2)
void encode_fused(const __half* __restrict__ XHp, const __half* __restrict__ XLp,
                  const __half* __restrict__ WHp,
                  const float* __restrict__ TH, float* __restrict__ H,
                  float* __restrict__ A, __half* __restrict__ AH16,
                  const float* __restrict__ WDsrc, __half* __restrict__ WD16) {
    if (blockIdx.x < NWD) {
        const int p = blockIdx.x;
        int i = 0, rem = p;
        while (rem >= NL - i) { rem -= NL - i; i++; }
        const size_t zoff = (size_t)(i * NL + i + rem) * FL * DM;
        const float4* src = (const float4*)(WDsrc + zoff);
        uint2* dst = (uint2*)(WD16 + zoff);
        const int N4 = FL * DM / 4;   // 393216
        for (int q = threadIdx.x; q < N4; q += 1024) {
            float4 v0 = src[q], v1 = src[q + 512];
            __half h0[4], h1[4];
            cvt4(h0, v0); cvt4(h1, v1);
            dst[q]       = *(uint2*)h0;
            dst[q + 512] = *(uint2*)h1;
        }
        return;
    }

    extern __shared__ __half sm[];
    const uint32_t sb = smem_u32(sm);

    const int bid = blockIdx.x - NWD;
    const int l  = bid >> 8;
    const int bm = ((bid >> 4) & 15) * DM2;
    const int bn = (bid & 15) * DBN;
    const int KT = DM / DBK;   // 24

    const int tid  = threadIdx.x;
    const int lane = tid & 31, wid = tid >> 5;
    const int wm = wid & 3, wn = wid >> 2;   // warp tile 32x32
    const int r = lane >> 2, c = lane & 3;
    const int lr = lane & 15, lc = lane >> 4;

    // A loads: XH,XL each 128 rows x 32 halves = 512 cp16 -> 1 per thread each
    const __half* gxh = XHp + ((size_t)(bm + (tid >> 2)) * NL + l) * DM + (tid & 3) * 8;
    const __half* gxl = XLp + ((size_t)(bm + (tid >> 2)) * NL + l) * DM + (tid & 3) * 8;
    const uint32_t a_off_t = (uint32_t)(tid >> 2) * ASTR + (uint32_t)(tid & 3) * 8;

    // B: 32 rows x 128 halves = 512 cp16 -> 1 per thread
    const __half* gwh = WHp + (size_t)l * DM * FL;
    const int brow = tid >> 4, bq = (tid & 15) * 8;
    const uint32_t b_row_off = (uint32_t)brow * BSTR + bq;

    float acc[2][4][4];
#pragma unroll
    for (int mt = 0; mt < 2; mt++)
#pragma unroll
        for (int nt = 0; nt < 4; nt++)
#pragma unroll
            for (int q = 0; q < 4; q++) acc[mt][nt][q] = 0.0f;

#define ENC_ISSUE(KN, ST)                                                        \
    do {                                                                         \
        const uint32_t ao = a_off_t + (uint32_t)(ST) * SA2;                      \
        cp16(sb + 2 * (EXH_BASE + ao), gxh + (KN) * DBK);                        \
        cp16(sb + 2 * (EXL_BASE + ao), gxl + (KN) * DBK);                        \
        const __half* wb = gwh + (size_t)((KN) * DBK + brow) * FL + bn + bq;     \
        cp16(sb + 2 * (EWH_BASE + b_row_off + (uint32_t)(ST) * SB), wb);         \
        asm volatile("cp.async.commit_group;");                                  \
    } while (0)

    ENC_ISSUE(0, 0);
    ENC_ISSUE(1, 1);

    for (int kt = 0; kt < KT; kt++) {
        if (kt + 1 < KT) asm volatile("cp.async.wait_group 1;");
        else             asm volatile("cp.async.wait_group 0;");
        __syncthreads();
        if (kt + 2 < KT) {
            const int kn = kt + 2;
            ENC_ISSUE(kn, kn % 3);
        }
        const int st = kt % 3;
        const uint32_t ah_b = sb + 2 * (EXH_BASE + (uint32_t)st * SA2);
        const uint32_t al_b = sb + 2 * (EXL_BASE + (uint32_t)st * SA2);
        const uint32_t bh_b = sb + 2 * (EWH_BASE + (uint32_t)st * SB);

#pragma unroll
        for (int s = 0; s < 2; s++) {
            uint32_t ah[2][4], bb[2][4];
            const uint32_t aoff = 2 * (uint32_t)((wm * 32 + lr) * ASTR + s * 16 + 8 * lc);
            const uint32_t boff = 2 * (uint32_t)((s * 16 + lr) * BSTR + wn * 32 + 8 * lc);
#pragma unroll
            for (int mt = 0; mt < 2; mt++)
                ldsm_x4(ah[mt], ah_b + aoff + 2 * (uint32_t)(mt * 16 * ASTR));
#pragma unroll
            for (int g = 0; g < 2; g++)
                ldsm_x4t(bb[g], bh_b + boff + 2 * (uint32_t)(g * 16));
#pragma unroll
            for (int mt = 0; mt < 2; mt++)
#pragma unroll
                for (int g = 0; g < 2; g++) {
                    mma_f16(acc[mt][2 * g],     ah[mt], &bb[g][0]);
                    mma_f16(acc[mt][2 * g + 1], ah[mt], &bb[g][2]);
                }
            // low half of x against same B fragments
            {
                uint32_t al[2][4];
#pragma unroll
                for (int mt = 0; mt < 2; mt++)
                    ldsm_x4(al[mt], al_b + aoff + 2 * (uint32_t)(mt * 16 * ASTR));
#pragma unroll
                for (int mt = 0; mt < 2; mt++)
#pragma unroll
                    for (int g = 0; g < 2; g++) {
                        mma_f16(acc[mt][2 * g],     al[mt], &bb[g][0]);
                        mma_f16(acc[mt][2 * g + 1], al[mt], &bb[g][2]);
                    }
            }
        }
    }
#undef ENC_ISSUE

    float thr0[4], thr1[4];
#pragma unroll
    for (int nt = 0; nt < 4; nt++) {
        const int col = bn + wn * 32 + nt * 8 + 2 * c;
        thr0[nt] = expf(TH[l * FL + col]);
        thr1[nt] = expf(TH[l * FL + col + 1]);
    }
#pragma unroll
    for (int mt = 0; mt < 2; mt++) {
        const int row = bm + wm * 32 + mt * 16 + r;
#pragma unroll
        for (int nt = 0; nt < 4; nt++) {
            const int col = bn + wn * 32 + nt * 8 + 2 * c;
            const size_t b0 = (size_t)row * (NL * FL) + (size_t)l * FL + col;
            const size_t b1 = b0 + (size_t)8 * (NL * FL);
            const float h0 = acc[mt][nt][0], h1 = acc[mt][nt][1];
            const float h2 = acc[mt][nt][2], h3 = acc[mt][nt][3];
            if (H) {
                *(float2*)(H + b0) = make_float2(h0, h1);
                *(float2*)(H + b1) = make_float2(h2, h3);
            }
            const float a0 = (h0 > thr0[nt]) ? h0 : 0.0f;
            const float a1 = (h1 > thr1[nt]) ? h1 : 0.0f;
            const float a2 = (h2 > thr0[nt]) ? h2 : 0.0f;
            const float a3 = (h3 > thr1[nt]) ? h3 : 0.0f;
            *(float2*)(A + b0) = make_float2(a0, a1);
            *(float2*)(A + b1) = make_float2(a2, a3);
            *(__half2*)(AH16 + b0) = __floats2half2_rn(a0, a1);
            *(__half2*)(AH16 + b1) = __floats2half2_rn(a2, a3);
            if (fabsf(h0 - thr0[nt]) < DELTA) {
                int s0 = atomicAdd(&g_fix_count, 1);
                if (s0 < FIX_CAP) g_fix_list[s0] = (int)b0;
            }
            if (fabsf(h1 - thr1[nt]) < DELTA) {
                int s1 = atomicAdd(&g_fix_count, 1);
                if (s1 < FIX_CAP) g_fix_list[s1] = (int)(b0 + 1);
            }
            if (fabsf(h2 - thr0[nt]) < DELTA) {
                int s2 = atomicAdd(&g_fix_count, 1);
                if (s2 < FIX_CAP) g_fix_list[s2] = (int)b1;
            }
            if (fabsf(h3 - thr1[nt]) < DELTA) {
                int s3 = atomicAdd(&g_fix_count, 1);
                if (s3 < FIX_CAP) g_fix_list[s3] = (int)(b1 + 1);
            }
        }
    }
}

// ---------------- fixup ----------------
__global__ __launch_bounds__(256)
void fixup(const float* __restrict__ x, const float* __restrict__ weT,
           const float* __restrict__ TH, float* __restrict__ A,
           __half* __restrict__ AH16) {
    const int nwarps = gridDim.x * (blockDim.x >> 5);
    const int gw = blockIdx.x * (blockDim.x >> 5) + (threadIdx.x >> 5);
    const int lane = threadIdx.x & 31;
    const int n = min(g_fix_count, FIX_CAP);
    for (int e = gw; e < n; e += nwarps) {
        const int idx = g_fix_list[e];
        const int t = idx / (NL * FL);
        const int rm = idx % (NL * FL);
        const int l = rm / FL, f = rm % FL;
        const float* xr = x + ((size_t)t * NL + l) * DM;
        const float* wr = weT + ((size_t)l * FL + f) * DM;
        float s = 0.0f;
#pragma unroll 4
        for (int d = lane; d < DM; d += 32) s = fmaf(xr[d], wr[d], s);
#pragma unroll
        for (int o = 16; o; o >>= 1) s += __shfl_xor_sync(0xFFFFFFFFu, s, o);
        if (lane == 0) {
            const float thr = expf(TH[l * FL + f]);
            const float a = (s > thr) ? s : 0.0f;
            A[idx] = a;
            AH16[idx] = __float2half_rn(a);
        }
    }
}

// ---------------- decode: CTA 128x128x32, 512 thr, 2/SM (unchanged) ---------
__global__ __launch_bounds__(512, 2)
void decode_fp16(const __half* __restrict__ AH, const __half* __restrict__ WD,
                 float* __restrict__ XH) {
    extern __shared__ __half sm[];
    const uint32_t sb = smem_u32(sm);

    const int j  = (NL - 1) - blockIdx.z;
    const int bm = blockIdx.y * DM2;
    const int bn = blockIdx.x * DBN;
    const int KT = (j + 1) * (FL / DBK);

    const int tid  = threadIdx.x;
    const int lane = tid & 31, wid = tid >> 5;
    const int wm = wid & 3, wn = wid >> 2;
    const int r = lane >> 2, c = lane & 3;
    const int lr = lane & 15, lc = lane >> 4;

    const __half* gah = AH + (size_t)(bm + (tid >> 2)) * (NL * FL) + (tid & 3) * 8;
    const uint32_t a_off_t = (uint32_t)(tid >> 2) * ASTR + (uint32_t)(tid & 3) * 8;

    const __half* wj  = WD + (size_t)j * FL * DM;
    const size_t wd_istride = (size_t)NL * FL * DM;
    const int brow = tid >> 4, bq = (tid & 15) * 8;
    const uint32_t b_row_off = (uint32_t)brow * BSTR + bq;

    float acc[2][4][4];
#pragma unroll
    for (int mt = 0; mt < 2; mt++)
#pragma unroll
        for (int nt = 0; nt < 4; nt++)
#pragma unroll
            for (int q = 0; q < 4; q++) acc[mt][nt][q] = 0.0f;

#define DEC_ISSUE(KN, ST)                                                       \
    do {                                                                        \
        cp16(sb + 2 * (a_off_t + (uint32_t)(ST) * SA2), gah + (KN) * DBK);      \
        const int ii = (KN) >> 6, f0 = ((KN) & 63) * DBK;                       \
        const __half* sbp = wj + (size_t)ii * wd_istride +                      \
                            (size_t)(f0 + brow) * DM + bn + bq;                 \
        cp16(sb + 2 * (DEC_B_BASE + b_row_off + (uint32_t)(ST) * SB), sbp);     \
        asm volatile("cp.async.commit_group;");                                 \
    } while (0)

    DEC_ISSUE(0, 0);
    DEC_ISSUE(1, 1);

    for (int kt = 0; kt < KT; kt++) {
        if (kt + 1 < KT) asm volatile("cp.async.wait_group 1;");
        else             asm volatile("cp.async.wait_group 0;");
        __syncthreads();
        if (kt + 2 < KT) {
            const int kn = kt + 2;
            DEC_ISSUE(kn, kn % 3);
        }
        const int st = kt % 3;
        const uint32_t a_b = sb + 2 * ((uint32_t)st * SA2);
        const uint32_t b_b = sb + 2 * (DEC_B_BASE + (uint32_t)st * SB);

#pragma unroll
        for (int s = 0; s < 2; s++) {
            uint32_t a[2][4], bb[2][4];
#pragma unroll
            for (int mt = 0; mt < 2; mt++) {
                const uint32_t ao =
                    2 * ((uint32_t)(wm * 32 + mt * 16 + lr) * ASTR + s * 16 + 8 * lc);
                ldsm_x4(a[mt], a_b + ao);
            }
#pragma unroll
            for (int g = 0; g < 2; g++) {
                const uint32_t bo =
                    2 * ((uint32_t)(s * 16 + lr) * BSTR + wn * 32 + g * 16 + 8 * lc);
                ldsm_x4t(bb[g], b_b + bo);
            }
#pragma unroll
            for (int mt = 0; mt < 2; mt++)
#pragma unroll
                for (int g = 0; g < 2; g++) {
                    mma_f16(acc[mt][2 * g],     a[mt], &bb[g][0]);
                    mma_f16(acc[mt][2 * g + 1], a[mt], &bb[g][2]);
                }
        }
    }
#undef DEC_ISSUE

#pragma unroll
    for (int mt = 0; mt < 2; mt++) {
        const int row = bm + wm * 32 + mt * 16 + r;
#pragma unroll
        for (int nt = 0; nt < 4; nt++) {
            const int col = bn + wn * 32 + nt * 8 + 2 * c;
            float* p = XH + (size_t)row * (NL * DM) + (size_t)j * DM + col;
            *(float2*)p = make_float2(acc[mt][nt][0], acc[mt][nt][1]);
            *(float2*)(p + (size_t)8 * (NL * DM)) =
                make_float2(acc[mt][nt][2], acc[mt][nt][3]);
        }
    }
}

// ---------------- host ----------------
extern "C" void kernel_launch(void* const* d_in, const int* in_sizes, int n_in,
                              void* d_out, int out_size) {
    const float* x  = (const float*)d_in[0];
    const float* we = (const float*)d_in[1];
    const float* wd = (const float*)d_in[2];
    const float* th = (const float*)d_in[3];
    float* out = (float*)d_out;

    const long long HE = (long long)T_TOK * NL * FL;
    const long long XE = (long long)T_TOK * NL * DM;

    float *hp, *ap, *xp;
    if ((long long)out_size >= 2 * HE + XE) {
        hp = out; ap = out + HE; xp = out + 2 * HE;
    } else {
        hp = nullptr;
        float* sp = nullptr;
        cudaGetSymbolAddress((void**)&sp, g_acts_scratch);
        ap = sp; xp = out;
    }

    __half *wd16, *ah, *xh, *xl, *weh;
    float* weT;
    cudaGetSymbolAddress((void**)&wd16, g_wd16);
    cudaGetSymbolAddress((void**)&ah, g_ah);
    cudaGetSymbolAddress((void**)&xh, g_xh);
    cudaGetSymbolAddress((void**)&xl, g_xl);
    cudaGetSymbolAddress((void**)&weh, g_weh);
    cudaGetSymbolAddress((void**)&weT, g_weT);

    cudaFuncSetAttribute(decode_fp16, cudaFuncAttributeMaxDynamicSharedMemorySize,
                         SMEM_DEC_BYTES);
    cudaFuncSetAttribute(encode_fused, cudaFuncAttributeMaxDynamicSharedMemorySize,
                         SMEM_ENC_BYTES);

    prep_xwe<<<NB_PREP, 256>>>(x, we, xh, xl, weh, weT);
    encode_fused<<<NWD + ENC_BLOCKS, 512, SMEM_ENC_BYTES>>>(
        xh, xl, weh, th, hp, ap, ah, wd, wd16);
    fixup<<<296, 256>>>(x, weT, th, ap, ah);
    decode_fp16<<<dim3(DM / DBN, T_TOK / DM2, NL), 512, SMEM_DEC_BYTES>>>(ah, wd16, xp);
}